// round 12
// baseline (speedup 1.0000x reference)
#include <cuda_runtime.h>
#include <cuda_fp16.h>
#include <cuda_bf16.h>
#include <mma.h>

#define NB   8
#define RR   256
#define IND  64
#define OUTD 64
#define MD   32
#define KXN  64

typedef unsigned long long ull;
using namespace nvcuda;

// ---------------- scratch (device globals; no allocations allowed) ----------
__device__ __half g_XwRh[NB*MD*RR*IND];   // [n][ky][h][i]  forward w-DFT (fp16)
__device__ __half g_XwIh[NB*MD*RR*IND];
__device__ float g_XmR[NB*MD*KXN*IND];    // [ky][kx][n][i] forward modes
__device__ float g_XmI[NB*MD*KXN*IND];
__device__ float g_OmR[NB*MD*KXN*OUTD];   // [n][ky][kx][o] mixed modes
__device__ float g_OmI[NB*MD*KXN*OUTD];
__device__ __half g_Y1Rh[NB*RR*MD*OUTD];  // [n][h][ky][o]  inverse h-DFT (fp16)
__device__ __half g_Y1Ih[NB*RR*MD*OUTD];
__device__ float4 g_tw4p[256];            // (c, c,  s,  s)
__device__ float4 g_tw4n[256];            // (c, c, -s, -s)

// ---------------- packed f32x2 helpers --------------------------------------
__device__ __forceinline__ void fma2(ull &d, ull a, ull b) {
    asm("fma.rn.f32x2 %0, %1, %2, %0;" : "+l"(d) : "l"(a), "l"(b));
}
__device__ __forceinline__ ull splat2(float x) {
    ull r; asm("mov.b64 %0, {%1, %1};" : "=l"(r) : "f"(x)); return r;
}
__device__ __forceinline__ ull pack2(float x, float y) {
    ull r; asm("mov.b64 %0, {%1, %2};" : "=l"(r) : "f"(x), "f"(y)); return r;
}
__device__ __forceinline__ ull mul2(ull a, ull b) {
    ull r; asm("mul.rn.f32x2 %0, %1, %2;" : "=l"(r) : "l"(a), "l"(b)); return r;
}
__device__ __forceinline__ ull add2(ull a, ull b) {
    ull r; asm("add.rn.f32x2 %0, %1, %2;" : "=l"(r) : "l"(a), "l"(b)); return r;
}
__device__ __forceinline__ ull sub2(ull a, ull b, ull negone) {   // a - b
    ull r; asm("fma.rn.f32x2 %0, %1, %2, %3;" : "=l"(r) : "l"(b), "l"(negone), "l"(a)); return r;
}
__device__ __forceinline__ float2 unpk(ull v) {
    float2 r; asm("mov.b64 {%0, %1}, %2;" : "=f"(r.x), "=f"(r.y) : "l"(v)); return r;
}
// ---------------- fp16 pack/unpack helpers ----------------------------------
__device__ __forceinline__ unsigned f22h(float a, float b) {
    __half2 h = __floats2half2_rn(a, b);
    return *reinterpret_cast<unsigned*>(&h);
}
__device__ __forceinline__ ulonglong2 h4f(uint2 u) {            // 4 halves -> 2 packed f32x2
    __half2 ha = *reinterpret_cast<__half2*>(&u.x);
    __half2 hb = *reinterpret_cast<__half2*>(&u.y);
    float2 fa = __half22float2(ha), fb = __half22float2(hb);
    return make_ulonglong2(pack2(fa.x, fa.y), pack2(fb.x, fb.y));
}
__device__ __forceinline__ void h8store(float* dst, uint4 u) {  // 8 halves -> smem f32
    __half2* hp = reinterpret_cast<__half2*>(&u);
    float2 f0 = __half22float2(hp[0]), f1 = __half22float2(hp[1]);
    float2 f2 = __half22float2(hp[2]), f3 = __half22float2(hp[3]);
    *reinterpret_cast<float4*>(dst)     = make_float4(f0.x, f0.y, f1.x, f1.y);
    *reinterpret_cast<float4*>(dst + 4) = make_float4(f2.x, f2.y, f3.x, f3.y);
}
// split-bf16 pack: 4 floats -> 4 hi bf16 + 4 lo bf16 (uint2 each)
__device__ __forceinline__ void bfsplit4(float4 v, uint2 &hi, uint2 &lo) {
    __nv_bfloat16 h0 = __float2bfloat16_rn(v.x), h1 = __float2bfloat16_rn(v.y);
    __nv_bfloat16 h2 = __float2bfloat16_rn(v.z), h3 = __float2bfloat16_rn(v.w);
    __nv_bfloat162 p01 = __nv_bfloat162(h0, h1), p23 = __nv_bfloat162(h2, h3);
    hi = make_uint2(*reinterpret_cast<unsigned*>(&p01), *reinterpret_cast<unsigned*>(&p23));
    __nv_bfloat16 l0 = __float2bfloat16_rn(v.x - __bfloat162float(h0));
    __nv_bfloat16 l1 = __float2bfloat16_rn(v.y - __bfloat162float(h1));
    __nv_bfloat16 l2 = __float2bfloat16_rn(v.z - __bfloat162float(h2));
    __nv_bfloat16 l3 = __float2bfloat16_rn(v.w - __bfloat162float(h3));
    __nv_bfloat162 q01 = __nv_bfloat162(l0, l1), q23 = __nv_bfloat162(l2, l3);
    lo = make_uint2(*reinterpret_cast<unsigned*>(&q01), *reinterpret_cast<unsigned*>(&q23));
}

__global__ void k_init_tw() {
    int k = threadIdx.x;
    double a = 6.283185307179586476925286766559 * (double)k / 256.0;
    float c = (float)cos(a), s = (float)sin(a);
    g_tw4p[k] = make_float4(c, c,  s,  s);
    g_tw4n[k] = make_float4(c, c, -s, -s);
}

// ---------------- K1: forward DFT along w (radix-4, 256 thr, 2 ky/thread) ---
__global__ __launch_bounds__(256) void k1_fwd_w(const float* __restrict__ x) {
    extern __shared__ __align__(16) float us[];   // u0|u2|d02|d13, each [64][64]
    __shared__ __align__(16) float4 twp[256], twn[256];
    const int t = threadIdx.x;
    twp[t] = g_tw4p[t]; twn[t] = g_tw4n[t];
    const int b = blockIdx.x, n = b >> 8, h = b & 255;
    const float* xb = x + (size_t)(n*RR + h)*RR*IND;
    float* u0s = us; float* u2s = us + 4096; float* d2s = us + 8192; float* d3s = us + 12288;
#pragma unroll
    for (int it = 0; it < 16; it++) {
        int idx = t + 256*it;                    // idx = w0*64 + i
        float a0 = xb[idx], a1 = xb[idx + 4096], a2 = xb[idx + 8192], a3 = xb[idx + 12288];
        float s02 = a0 + a2, d02 = a0 - a2, s13 = a1 + a3, d13 = a1 - a3;
        u0s[idx] = s02 + s13; u2s[idx] = s02 - s13; d2s[idx] = d02; d3s[idx] = d13;
    }
    __syncthreads();

    const int i0 = (t & 15) * 4;
    const int slot = (t >> 4) & 7;
    const bool oddky = (t >= 128);               // warp-uniform
    const int ky_a = 2*slot + (oddky ? 1 : 0);
    const int ky_b = ky_a + 16;
    ull aR[2][2] = {{0,0},{0,0}}, aI[2][2] = {{0,0},{0,0}};
    int pa = 0, pb = 0;
    const float sc = 1.f/256.f;
    float iscl = sc;

    if (!oddky) {
        const float* Up = (slot & 1) ? u2s : u0s;
        for (int w0 = 0; w0 < 64; w0++) {
            ulonglong2 U = *reinterpret_cast<const ulonglong2*>(&Up[w0*64 + i0]);
            ulonglong2 ta = *reinterpret_cast<const ulonglong2*>(&twn[pa]);
            fma2(aR[0][0], ta.x, U.x); fma2(aR[0][1], ta.x, U.y);
            fma2(aI[0][0], ta.y, U.x); fma2(aI[0][1], ta.y, U.y);
            ulonglong2 tb = *reinterpret_cast<const ulonglong2*>(&twn[pb]);
            fma2(aR[1][0], tb.x, U.x); fma2(aR[1][1], tb.x, U.y);
            fma2(aI[1][0], tb.y, U.x); fma2(aI[1][1], tb.y, U.y);
            pa = (pa + ky_a) & 255; pb = (pb + ky_b) & 255;
        }
    } else {
        const bool c1 = ((slot & 1) == 0);
        const ull S = splat2(c1 ? 1.f : -1.f);
        iscl = c1 ? -sc : sc;
        for (int w0 = 0; w0 < 64; w0++) {
            ulonglong2 D2 = *reinterpret_cast<const ulonglong2*>(&d2s[w0*64 + i0]);
            ulonglong2 D3 = *reinterpret_cast<const ulonglong2*>(&d3s[w0*64 + i0]);
            ull D3r0 = mul2(D3.x, S), D3r1 = mul2(D3.y, S);
            ull D2i0 = mul2(D2.x, S), D2i1 = mul2(D2.y, S);
            ulonglong2 tpa = *reinterpret_cast<const ulonglong2*>(&twp[pa]);
            ulonglong2 tna = *reinterpret_cast<const ulonglong2*>(&twn[pa]);
            fma2(aR[0][0], tpa.x, D2.x); fma2(aR[0][1], tpa.x, D2.y);
            fma2(aR[0][0], tna.y, D3r0); fma2(aR[0][1], tna.y, D3r1);
            fma2(aI[0][0], tpa.x, D3.x); fma2(aI[0][1], tpa.x, D3.y);
            fma2(aI[0][0], tpa.y, D2i0); fma2(aI[0][1], tpa.y, D2i1);
            ulonglong2 tpb = *reinterpret_cast<const ulonglong2*>(&twp[pb]);
            ulonglong2 tnb = *reinterpret_cast<const ulonglong2*>(&twn[pb]);
            fma2(aR[1][0], tpb.x, D2.x); fma2(aR[1][1], tpb.x, D2.y);
            fma2(aR[1][0], tnb.y, D3r0); fma2(aR[1][1], tnb.y, D3r1);
            fma2(aI[1][0], tpb.x, D3.x); fma2(aI[1][1], tpb.x, D3.y);
            fma2(aI[1][0], tpb.y, D2i0); fma2(aI[1][1], tpb.y, D2i1);
            pa = (pa + ky_a) & 255; pb = (pb + ky_b) & 255;
        }
    }
#pragma unroll
    for (int j = 0; j < 2; j++) {
        const int ky = j ? ky_b : ky_a;
        size_t o = (size_t)((n*MD + ky)*RR + h)*IND + i0;
        float2 a0 = unpk(aR[j][0]), a1 = unpk(aR[j][1]);
        *reinterpret_cast<uint2*>(&g_XwRh[o]) =
            make_uint2(f22h(a0.x*sc, a0.y*sc), f22h(a1.x*sc, a1.y*sc));
        a0 = unpk(aI[j][0]); a1 = unpk(aI[j][1]);
        *reinterpret_cast<uint2*>(&g_XwIh[o]) =
            make_uint2(f22h(a0.x*iscl, a0.y*iscl), f22h(a1.x*iscl, a1.y*iscl));
    }
}

// ---------------- K2: forward h-DFT, radix-4, register-prefetch pipeline ----
__global__ __launch_bounds__(256, 3) void k2_fwd_h() {
    __shared__ __align__(16) float Vs[8*16*64];       // 8 planes x [16 h0][64 i] = 32KB
    __shared__ __align__(16) float4 twp[256], twn[256];
    const int t = threadIdx.x;
    twp[t] = g_tw4p[t]; twn[t] = g_tw4n[t];
    const int b = blockIdx.x, half = b & 1, ky = (b >> 1) & 31, n = b >> 6;
    const __half* baseR = g_XwRh + (size_t)(n*MD + ky)*RR*IND;
    const __half* baseI = g_XwIh + (size_t)(n*MD + ky)*RR*IND;
    const int i0 = (t & 15) * 4;
    const int g = t >> 4, c = g & 3, mseg = g >> 2;
    const int kxl0 = 8*mseg + c;                       // slots of class c
    const int kap0 = half ? (224 + kxl0) : kxl0;
    const int kap1 = kap0 + 4;
    const int h0ld = t >> 4, iq = (t & 15) * 4;        // loader role (1 per thread)
    const ull NEG1 = splat2(-1.f);
    ull aR[2][2] = {{0,0},{0,0}}, aI[2][2] = {{0,0},{0,0}};
    int p0 = 0, p1 = 0;

    uint2 R0u, R1u, R2u, R3u, I0u, I1u, I2u, I3u;
    {
        const __half* pR = baseR + h0ld*IND + iq;
        const __half* pI = baseI + h0ld*IND + iq;
        R0u = *reinterpret_cast<const uint2*>(pR);
        R1u = *reinterpret_cast<const uint2*>(pR + 64*IND);
        R2u = *reinterpret_cast<const uint2*>(pR + 128*IND);
        R3u = *reinterpret_cast<const uint2*>(pR + 192*IND);
        I0u = *reinterpret_cast<const uint2*>(pI);
        I1u = *reinterpret_cast<const uint2*>(pI + 64*IND);
        I2u = *reinterpret_cast<const uint2*>(pI + 128*IND);
        I3u = *reinterpret_cast<const uint2*>(pI + 192*IND);
    }

    for (int hc = 0; hc < 64; hc += 16) {
        __syncthreads();
        {   // convert + butterfly registers -> Vs
            ulonglong2 R0 = h4f(R0u), R1 = h4f(R1u), R2 = h4f(R2u), R3 = h4f(R3u);
            ulonglong2 I0 = h4f(I0u), I1 = h4f(I1u), I2 = h4f(I2u), I3 = h4f(I3u);
            ull sRx = add2(R0.x, R2.x), sRy = add2(R0.y, R2.y);
            ull dRx = sub2(R0.x, R2.x, NEG1), dRy = sub2(R0.y, R2.y, NEG1);
            ull uRx = add2(R1.x, R3.x), uRy = add2(R1.y, R3.y);
            ull eRx = sub2(R1.x, R3.x, NEG1), eRy = sub2(R1.y, R3.y, NEG1);
            ull sIx = add2(I0.x, I2.x), sIy = add2(I0.y, I2.y);
            ull dIx = sub2(I0.x, I2.x, NEG1), dIy = sub2(I0.y, I2.y, NEG1);
            ull uIx = add2(I1.x, I3.x), uIy = add2(I1.y, I3.y);
            ull eIx = sub2(I1.x, I3.x, NEG1), eIy = sub2(I1.y, I3.y, NEG1);
            const int rb = h0ld*64 + iq;
            ulonglong2* vp;
            vp = reinterpret_cast<ulonglong2*>(&Vs[0*1024 + rb]);
            *vp = make_ulonglong2(add2(sRx, uRx), add2(sRy, uRy));
            vp = reinterpret_cast<ulonglong2*>(&Vs[1*1024 + rb]);
            *vp = make_ulonglong2(add2(sIx, uIx), add2(sIy, uIy));
            vp = reinterpret_cast<ulonglong2*>(&Vs[2*1024 + rb]);
            *vp = make_ulonglong2(add2(dRx, eIx), add2(dRy, eIy));
            vp = reinterpret_cast<ulonglong2*>(&Vs[3*1024 + rb]);
            *vp = make_ulonglong2(sub2(dIx, eRx, NEG1), sub2(dIy, eRy, NEG1));
            vp = reinterpret_cast<ulonglong2*>(&Vs[4*1024 + rb]);
            *vp = make_ulonglong2(sub2(sRx, uRx, NEG1), sub2(sRy, uRy, NEG1));
            vp = reinterpret_cast<ulonglong2*>(&Vs[5*1024 + rb]);
            *vp = make_ulonglong2(sub2(sIx, uIx, NEG1), sub2(sIy, uIy, NEG1));
            vp = reinterpret_cast<ulonglong2*>(&Vs[6*1024 + rb]);
            *vp = make_ulonglong2(sub2(dRx, eIx, NEG1), sub2(dRy, eIy, NEG1));
            vp = reinterpret_cast<ulonglong2*>(&Vs[7*1024 + rb]);
            *vp = make_ulonglong2(add2(dIx, eRx), add2(dIy, eRy));
        }
        __syncthreads();
        if (hc < 48) {
            const __half* pR = baseR + (hc + 16 + h0ld)*IND + iq;
            const __half* pI = baseI + (hc + 16 + h0ld)*IND + iq;
            R0u = *reinterpret_cast<const uint2*>(pR);
            R1u = *reinterpret_cast<const uint2*>(pR + 64*IND);
            R2u = *reinterpret_cast<const uint2*>(pR + 128*IND);
            R3u = *reinterpret_cast<const uint2*>(pR + 192*IND);
            I0u = *reinterpret_cast<const uint2*>(pI);
            I1u = *reinterpret_cast<const uint2*>(pI + 64*IND);
            I2u = *reinterpret_cast<const uint2*>(pI + 128*IND);
            I3u = *reinterpret_cast<const uint2*>(pI + 192*IND);
        }
        const float* VRb = &Vs[(c*2 + 0)*1024];
        const float* VIb = &Vs[(c*2 + 1)*1024];
        for (int h0l = 0; h0l < 16; h0l++) {
            ulonglong2 VR = *reinterpret_cast<const ulonglong2*>(&VRb[h0l*64 + i0]);
            ulonglong2 VI = *reinterpret_cast<const ulonglong2*>(&VIb[h0l*64 + i0]);
            ulonglong2 tp4 = *reinterpret_cast<const ulonglong2*>(&twp[p0]);
            ulonglong2 tn4 = *reinterpret_cast<const ulonglong2*>(&twn[p0]);
            fma2(aR[0][0], tp4.x, VR.x); fma2(aR[0][0], tp4.y, VI.x);
            fma2(aR[0][1], tp4.x, VR.y); fma2(aR[0][1], tp4.y, VI.y);
            fma2(aI[0][0], tp4.x, VI.x); fma2(aI[0][0], tn4.y, VR.x);
            fma2(aI[0][1], tp4.x, VI.y); fma2(aI[0][1], tn4.y, VR.y);
            p0 = (p0 + kap0) & 255;
            tp4 = *reinterpret_cast<const ulonglong2*>(&twp[p1]);
            tn4 = *reinterpret_cast<const ulonglong2*>(&twn[p1]);
            fma2(aR[1][0], tp4.x, VR.x); fma2(aR[1][0], tp4.y, VI.x);
            fma2(aR[1][1], tp4.x, VR.y); fma2(aR[1][1], tp4.y, VI.y);
            fma2(aI[1][0], tp4.x, VI.x); fma2(aI[1][0], tn4.y, VR.x);
            fma2(aI[1][1], tp4.x, VI.y); fma2(aI[1][1], tn4.y, VR.y);
            p1 = (p1 + kap1) & 255;
        }
    }
#pragma unroll
    for (int j = 0; j < 2; j++) {
        int kxs = half*32 + kxl0 + 4*j;
        size_t o = (size_t)((ky*KXN + kxs)*NB + n)*IND + i0;
        float2 a0 = unpk(aR[j][0]), a1 = unpk(aR[j][1]);
        *reinterpret_cast<float4*>(&g_XmR[o]) = make_float4(a0.x, a0.y, a1.x, a1.y);
        a0 = unpk(aI[j][0]); a1 = unpk(aI[j][1]);
        *reinterpret_cast<float4*>(&g_XmI[o]) = make_float4(a0.x, a0.y, a1.x, a1.y);
    }
}

// ---------------- K3: per-mode complex channel mix (8x64x64) ----------------
__global__ __launch_bounds__(256) void k3_mix(const float* __restrict__ w0,
                                              const float* __restrict__ w1) {
    __shared__ float Xs2[NB*IND*2];                   // interleaved (R,I)
    const int t = threadIdx.x, b = blockIdx.x;
    const int kx = b >> 5, ky = b & 31;
    size_t xb = (size_t)(ky*KXN + kx)*NB*IND;
#pragma unroll
    for (int it = 0; it < 2; it++) {
        int idx = t + 256*it;
        Xs2[2*idx]     = g_XmR[xb + idx];
        Xs2[2*idx + 1] = g_XmI[xb + idx];
    }
    __syncthreads();
    const float4* wp4 = reinterpret_cast<const float4*>(
        (kx < MD) ? (w0 + (size_t)(kx*MD + ky)*IND*OUTD*2)
                  : (w1 + (size_t)((kx - MD)*MD + ky)*IND*OUTD*2));
    const int o2 = t & 31, n = t >> 5;
    const int wstart = (t >> 5) * 8;                  // desync warp miss streams
    float r0 = 0.f, i0 = 0.f, r1 = 0.f, i1 = 0.f;
#pragma unroll 8
    for (int ii = 0; ii < IND; ii++) {
        int i = (ii + wstart) & 63;
        float4 w = wp4[i*32 + o2];
        float2 xv = *reinterpret_cast<const float2*>(&Xs2[(n*IND + i)*2]);
        r0 = fmaf(xv.x, w.x, fmaf(-xv.y, w.y, r0));
        i0 = fmaf(xv.x, w.y, fmaf( xv.y, w.x, i0));
        r1 = fmaf(xv.x, w.z, fmaf(-xv.y, w.w, r1));
        i1 = fmaf(xv.x, w.w, fmaf( xv.y, w.z, i1));
    }
    size_t gg = (size_t)((n*MD + ky)*KXN + kx)*OUTD + 2*o2;
    *reinterpret_cast<float2*>(&g_OmR[gg]) = make_float2(r0, r1);
    *reinterpret_cast<float2*>(&g_OmI[gg]) = make_float2(i0, i1);
}

// ---------------- K4: inverse h-DFT, radix-4 on output ----------------------
#define K4STEP(CR, CI) { \
    ulonglong2 R0 = *reinterpret_cast<const ulonglong2*>(&sR[kxo]); \
    ulonglong2 R1 = *reinterpret_cast<const ulonglong2*>(&sR[kxo + 4]); \
    ulonglong2 I0 = *reinterpret_cast<const ulonglong2*>(&sI[kxo]); \
    ulonglong2 I1 = *reinterpret_cast<const ulonglong2*>(&sI[kxo + 4]); \
    ulonglong2 tp4 = *reinterpret_cast<const ulonglong2*>(&twp[p]); \
    ulonglong2 tn4 = *reinterpret_cast<const ulonglong2*>(&twn[p]); \
    fma2(CR[0], tn4.x, R0.x); fma2(CR[0], tn4.y, I0.x); \
    fma2(CR[1], tn4.x, R0.y); fma2(CR[1], tn4.y, I0.y); \
    fma2(CR[2], tn4.x, R1.x); fma2(CR[2], tn4.y, I1.x); \
    fma2(CR[3], tn4.x, R1.y); fma2(CR[3], tn4.y, I1.y); \
    fma2(CI[0], tp4.x, I0.x); fma2(CI[0], tp4.y, R0.x); \
    fma2(CI[1], tp4.x, I0.y); fma2(CI[1], tp4.y, R0.y); \
    fma2(CI[2], tp4.x, I1.x); fma2(CI[2], tp4.y, R1.x); \
    fma2(CI[3], tp4.x, I1.y); fma2(CI[3], tp4.y, R1.y); \
    p = (p + h0) & 255; kxo += OUTD; }

__global__ __launch_bounds__(256) void k4_inv_h() {
    __shared__ __align__(16) float sR[KXN*OUTD], sI[KXN*OUTD];
    __shared__ __align__(16) float4 twp[256], twn[256];
    const int t = threadIdx.x;
    twp[t] = g_tw4p[t]; twn[t] = g_tw4n[t];
    const int b = blockIdx.x, grp = b & 1, ky = (b >> 1) & 31, n = b >> 6;
    const float4* pR = reinterpret_cast<const float4*>(g_OmR + (size_t)(n*MD + ky)*KXN*OUTD);
    const float4* pI = reinterpret_cast<const float4*>(g_OmI + (size_t)(n*MD + ky)*KXN*OUTD);
#pragma unroll
    for (int it = 0; it < 4; it++) {
        reinterpret_cast<float4*>(sR)[t + 256*it] = pR[t + 256*it];
        reinterpret_cast<float4*>(sI)[t + 256*it] = pI[t + 256*it];
    }
    __syncthreads();
    const int o0 = (t & 7) * 8, h0 = grp*32 + (t >> 3);
    ull C0R[4], C0I[4], C1R[4], C1I[4], C2R[4], C2I[4], C3R[4], C3I[4];
#pragma unroll
    for (int j = 0; j < 4; j++) {
        C0R[j]=C0I[j]=C1R[j]=C1I[j]=0ull;
        C2R[j]=C2I[j]=C3R[j]=C3I[j]=0ull;
    }
#pragma unroll 1
    for (int kh = 0; kh < 2; kh++) {
        int p = kh ? ((224*h0) & 255) : 0;
        int kxo = (kh*32)*OUTD + o0;
#pragma unroll
        for (int kk = 0; kk < 32; kk += 4) {
            K4STEP(C0R, C0I)
            K4STEP(C1R, C1I)
            K4STEP(C2R, C2I)
            K4STEP(C3R, C3I)
        }
    }
    const ull NEG1 = splat2(-1.f);
    const ull FAC2 = splat2((ky == 0 ? 1.f : 2.f) * (1.f/256.f));
    const size_t obase = (size_t)((n*RR + h0)*MD + ky)*OUTD + o0;
#pragma unroll
    for (int j = 0; j < 4; j++) {
        ull ER = add2(C0R[j], C2R[j]), EI = add2(C0I[j], C2I[j]);
        ull FR = sub2(C0R[j], C2R[j], NEG1), FI = sub2(C0I[j], C2I[j], NEG1);
        ull GR = add2(C1R[j], C3R[j]), GI = add2(C1I[j], C3I[j]);
        ull HR = sub2(C1R[j], C3R[j], NEG1), HI = sub2(C1I[j], C3I[j], NEG1);
        ull YR[4] = { add2(ER, GR), sub2(FR, HI, NEG1), sub2(ER, GR, NEG1), add2(FR, HI) };
        ull YI[4] = { add2(EI, GI), add2(FI, HR), sub2(EI, GI, NEG1), sub2(FI, HR, NEG1) };
#pragma unroll
        for (int q = 0; q < 4; q++) {
            size_t o = obase + (size_t)(64*q)*MD*OUTD + 2*j;
            float2 vr = unpk(mul2(YR[q], FAC2));
            float2 vi = unpk(mul2(YI[q], FAC2));
            *reinterpret_cast<unsigned*>(&g_Y1Rh[o]) = f22h(vr.x, vr.y);
            *reinterpret_cast<unsigned*>(&g_Y1Ih[o]) = f22h(vi.x, vi.y);
        }
    }
}

// ---------------- K5: wmma residual + radix-4 inverse w synthesis + SiLU ----
// dynamic smem (64KB): phase A = x_hi/x_lo bf16 tiles; phase B = res fp32.
__global__ __launch_bounds__(256) void k5_inv_w(const float* __restrict__ x,
                                                const float* __restrict__ res_w,
                                                const float* __restrict__ res_b,
                                                float* __restrict__ out) {
    extern __shared__ __align__(16) float dsm[];                 // 64KB union
    __nv_bfloat16* xhi = reinterpret_cast<__nv_bfloat16*>(dsm);  // [256][64]
    __nv_bfloat16* xlo = xhi + RR*IND;                           // [256][64]
    float* res = dsm;                                            // [256][64] (reuse)
    __shared__ __align__(16) float YsR[MD*OUTD], YsI[MD*OUTD];
    __shared__ __align__(16) __nv_bfloat16 rwh[IND*OUTD], rwl[IND*OUTD];
    __shared__ __align__(16) float4 twp[256], twn[256];
    __shared__ __align__(16) float rbs[64];
    const int t = threadIdx.x, b = blockIdx.x, n = b >> 8, h = b & 255;
    const int wid = t >> 5;
    twp[t] = g_tw4p[t];
    twn[t] = g_tw4n[t];
    // ---- stage x as split-bf16 ----
    const float4* xp = reinterpret_cast<const float4*>(x + (size_t)(n*RR + h)*RR*IND);
#pragma unroll
    for (int it = 0; it < 16; it++) {
        int j = t + 256*it;
        float4 v = xp[j];
        int w = j >> 4, c = (j & 15) * 4;
        uint2 hi, lo;
        bfsplit4(v, hi, lo);
        *reinterpret_cast<uint2*>(&xhi[w*IND + c]) = hi;
        *reinterpret_cast<uint2*>(&xlo[w*IND + c]) = lo;
    }
    // ---- stage rw as split-bf16 ----
#pragma unroll
    for (int it = 0; it < 4; it++) {
        int j = t + 256*it;
        float4 v = reinterpret_cast<const float4*>(res_w)[j];
        uint2 hi, lo;
        bfsplit4(v, hi, lo);
        *reinterpret_cast<uint2*>(&rwh[j*4]) = hi;
        *reinterpret_cast<uint2*>(&rwl[j*4]) = lo;
    }
    {   // Y1 fp16 -> fp32 smem
        const uint4* yRu = reinterpret_cast<const uint4*>(g_Y1Rh + (size_t)(n*RR + h)*MD*OUTD);
        const uint4* yIu = reinterpret_cast<const uint4*>(g_Y1Ih + (size_t)(n*RR + h)*MD*OUTD);
        h8store(&YsR[t*8], yRu[t]);
        h8store(&YsI[t*8], yIu[t]);
    }
    if (t < 64) rbs[t] = res_b[t];
    __syncthreads();

    // ---- wmma residual: res = x_hi@rw_hi + x_lo@rw_hi + x_hi@rw_lo --------
    {
        wmma::fragment<wmma::accumulator, 16, 16, 16, float> cf[2][4];
#pragma unroll
        for (int m = 0; m < 2; m++)
#pragma unroll
            for (int nn = 0; nn < 4; nn++) wmma::fill_fragment(cf[m][nn], 0.f);
#pragma unroll
        for (int k = 0; k < 4; k++) {
            wmma::fragment<wmma::matrix_a, 16, 16, 16, __nv_bfloat16, wmma::row_major> ah[2], al[2];
            wmma::fragment<wmma::matrix_b, 16, 16, 16, __nv_bfloat16, wmma::row_major> bh[4], bl[4];
#pragma unroll
            for (int m = 0; m < 2; m++) {
                wmma::load_matrix_sync(ah[m], xhi + (wid*32 + m*16)*IND + k*16, IND);
                wmma::load_matrix_sync(al[m], xlo + (wid*32 + m*16)*IND + k*16, IND);
            }
#pragma unroll
            for (int nn = 0; nn < 4; nn++) {
                wmma::load_matrix_sync(bh[nn], rwh + (k*16)*OUTD + nn*16, OUTD);
                wmma::load_matrix_sync(bl[nn], rwl + (k*16)*OUTD + nn*16, OUTD);
            }
#pragma unroll
            for (int m = 0; m < 2; m++)
#pragma unroll
                for (int nn = 0; nn < 4; nn++) {
                    wmma::mma_sync(cf[m][nn], ah[m], bh[nn], cf[m][nn]);
                    wmma::mma_sync(cf[m][nn], al[m], bh[nn], cf[m][nn]);
                    wmma::mma_sync(cf[m][nn], ah[m], bl[nn], cf[m][nn]);
                }
        }
        __syncthreads();                               // all loads from xhi/xlo done
#pragma unroll
        for (int m = 0; m < 2; m++)
#pragma unroll
            for (int nn = 0; nn < 4; nn++)
                wmma::store_matrix_sync(res + (wid*32 + m*16)*OUTD + nn*16,
                                        cf[m][nn], OUTD, wmma::mem_row_major);
        __syncthreads();
    }

    // ---- spectral class accumulation (unchanged) ---------------------------
    const int og = t & 7, o0 = og*8, pr = t >> 3;     // w0a = pr, w0b = pr + 32
    const ull NEG1 = splat2(-1.f);
    ull C0R[2][4], C2R[2][4], C1R[2][4], C1I[2][4], C3R[2][4], C3I[2][4];
#pragma unroll
    for (int s = 0; s < 2; s++)
#pragma unroll
        for (int j = 0; j < 4; j++) {
            C0R[s][j]=C2R[s][j]=C1R[s][j]=C1I[s][j]=C3R[s][j]=C3I[s][j]=0ull;
        }
    int pa = 0, pb = 0;
    const int stpa = pr, stpb = pr + 32;
#pragma unroll
    for (int kb = 0; kb < 8; kb++) {
        // c = 0
        {
            const int ky = 4*kb;
            ulonglong2 yr0 = *reinterpret_cast<const ulonglong2*>(&YsR[ky*OUTD + o0]);
            ulonglong2 yr1 = *reinterpret_cast<const ulonglong2*>(&YsR[ky*OUTD + o0 + 4]);
            ulonglong2 yi0 = *reinterpret_cast<const ulonglong2*>(&YsI[ky*OUTD + o0]);
            ulonglong2 yi1 = *reinterpret_cast<const ulonglong2*>(&YsI[ky*OUTD + o0 + 4]);
            ulonglong2 tn4 = *reinterpret_cast<const ulonglong2*>(&twn[pa]);
            fma2(C0R[0][0], tn4.x, yr0.x); fma2(C0R[0][0], tn4.y, yi0.x);
            fma2(C0R[0][1], tn4.x, yr0.y); fma2(C0R[0][1], tn4.y, yi0.y);
            fma2(C0R[0][2], tn4.x, yr1.x); fma2(C0R[0][2], tn4.y, yi1.x);
            fma2(C0R[0][3], tn4.x, yr1.y); fma2(C0R[0][3], tn4.y, yi1.y);
            tn4 = *reinterpret_cast<const ulonglong2*>(&twn[pb]);
            fma2(C0R[1][0], tn4.x, yr0.x); fma2(C0R[1][0], tn4.y, yi0.x);
            fma2(C0R[1][1], tn4.x, yr0.y); fma2(C0R[1][1], tn4.y, yi0.y);
            fma2(C0R[1][2], tn4.x, yr1.x); fma2(C0R[1][2], tn4.y, yi1.x);
            fma2(C0R[1][3], tn4.x, yr1.y); fma2(C0R[1][3], tn4.y, yi1.y);
            pa = (pa + stpa) & 255; pb = (pb + stpb) & 255;
        }
        // c = 1
        {
            const int ky = 4*kb + 1;
            ulonglong2 yr0 = *reinterpret_cast<const ulonglong2*>(&YsR[ky*OUTD + o0]);
            ulonglong2 yr1 = *reinterpret_cast<const ulonglong2*>(&YsR[ky*OUTD + o0 + 4]);
            ulonglong2 yi0 = *reinterpret_cast<const ulonglong2*>(&YsI[ky*OUTD + o0]);
            ulonglong2 yi1 = *reinterpret_cast<const ulonglong2*>(&YsI[ky*OUTD + o0 + 4]);
            ulonglong2 tn4 = *reinterpret_cast<const ulonglong2*>(&twn[pa]);
            ulonglong2 tp4 = *reinterpret_cast<const ulonglong2*>(&twp[pa]);
            fma2(C1R[0][0], tn4.x, yr0.x); fma2(C1R[0][0], tn4.y, yi0.x);
            fma2(C1R[0][1], tn4.x, yr0.y); fma2(C1R[0][1], tn4.y, yi0.y);
            fma2(C1R[0][2], tn4.x, yr1.x); fma2(C1R[0][2], tn4.y, yi1.x);
            fma2(C1R[0][3], tn4.x, yr1.y); fma2(C1R[0][3], tn4.y, yi1.y);
            fma2(C1I[0][0], tp4.x, yi0.x); fma2(C1I[0][0], tp4.y, yr0.x);
            fma2(C1I[0][1], tp4.x, yi0.y); fma2(C1I[0][1], tp4.y, yr0.y);
            fma2(C1I[0][2], tp4.x, yi1.x); fma2(C1I[0][2], tp4.y, yr1.x);
            fma2(C1I[0][3], tp4.x, yi1.y); fma2(C1I[0][3], tp4.y, yr1.y);
            tn4 = *reinterpret_cast<const ulonglong2*>(&twn[pb]);
            tp4 = *reinterpret_cast<const ulonglong2*>(&twp[pb]);
            fma2(C1R[1][0], tn4.x, yr0.x); fma2(C1R[1][0], tn4.y, yi0.x);
            fma2(C1R[1][1], tn4.x, yr0.y); fma2(C1R[1][1], tn4.y, yi0.y);
            fma2(C1R[1][2], tn4.x, yr1.x); fma2(C1R[1][2], tn4.y, yi1.x);
            fma2(C1R[1][3], tn4.x, yr1.y); fma2(C1R[1][3], tn4.y, yi1.y);
            fma2(C1I[1][0], tp4.x, yi0.x); fma2(C1I[1][0], tp4.y, yr0.x);
            fma2(C1I[1][1], tp4.x, yi0.y); fma2(C1I[1][1], tp4.y, yr0.y);
            fma2(C1I[1][2], tp4.x, yi1.x); fma2(C1I[1][2], tp4.y, yr1.x);
            fma2(C1I[1][3], tp4.x, yi1.y); fma2(C1I[1][3], tp4.y, yr1.y);
            pa = (pa + stpa) & 255; pb = (pb + stpb) & 255;
        }
        // c = 2
        {
            const int ky = 4*kb + 2;
            ulonglong2 yr0 = *reinterpret_cast<const ulonglong2*>(&YsR[ky*OUTD + o0]);
            ulonglong2 yr1 = *reinterpret_cast<const ulonglong2*>(&YsR[ky*OUTD + o0 + 4]);
            ulonglong2 yi0 = *reinterpret_cast<const ulonglong2*>(&YsI[ky*OUTD + o0]);
            ulonglong2 yi1 = *reinterpret_cast<const ulonglong2*>(&YsI[ky*OUTD + o0 + 4]);
            ulonglong2 tn4 = *reinterpret_cast<const ulonglong2*>(&twn[pa]);
            fma2(C2R[0][0], tn4.x, yr0.x); fma2(C2R[0][0], tn4.y, yi0.x);
            fma2(C2R[0][1], tn4.x, yr0.y); fma2(C2R[0][1], tn4.y, yi0.y);
            fma2(C2R[0][2], tn4.x, yr1.x); fma2(C2R[0][2], tn4.y, yi1.x);
            fma2(C2R[0][3], tn4.x, yr1.y); fma2(C2R[0][3], tn4.y, yi1.y);
            tn4 = *reinterpret_cast<const ulonglong2*>(&twn[pb]);
            fma2(C2R[1][0], tn4.x, yr0.x); fma2(C2R[1][0], tn4.y, yi0.x);
            fma2(C2R[1][1], tn4.x, yr0.y); fma2(C2R[1][1], tn4.y, yi0.y);
            fma2(C2R[1][2], tn4.x, yr1.x); fma2(C2R[1][2], tn4.y, yi1.x);
            fma2(C2R[1][3], tn4.x, yr1.y); fma2(C2R[1][3], tn4.y, yi1.y);
            pa = (pa + stpa) & 255; pb = (pb + stpb) & 255;
        }
        // c = 3
        {
            const int ky = 4*kb + 3;
            ulonglong2 yr0 = *reinterpret_cast<const ulonglong2*>(&YsR[ky*OUTD + o0]);
            ulonglong2 yr1 = *reinterpret_cast<const ulonglong2*>(&YsR[ky*OUTD + o0 + 4]);
            ulonglong2 yi0 = *reinterpret_cast<const ulonglong2*>(&YsI[ky*OUTD + o0]);
            ulonglong2 yi1 = *reinterpret_cast<const ulonglong2*>(&YsI[ky*OUTD + o0 + 4]);
            ulonglong2 tn4 = *reinterpret_cast<const ulonglong2*>(&twn[pa]);
            ulonglong2 tp4 = *reinterpret_cast<const ulonglong2*>(&twp[pa]);
            fma2(C3R[0][0], tn4.x, yr0.x); fma2(C3R[0][0], tn4.y, yi0.x);
            fma2(C3R[0][1], tn4.x, yr0.y); fma2(C3R[0][1], tn4.y, yi0.y);
            fma2(C3R[0][2], tn4.x, yr1.x); fma2(C3R[0][2], tn4.y, yi1.x);
            fma2(C3R[0][3], tn4.x, yr1.y); fma2(C3R[0][3], tn4.y, yi1.y);
            fma2(C3I[0][0], tp4.x, yi0.x); fma2(C3I[0][0], tp4.y, yr0.x);
            fma2(C3I[0][1], tp4.x, yi0.y); fma2(C3I[0][1], tp4.y, yr0.y);
            fma2(C3I[0][2], tp4.x, yi1.x); fma2(C3I[0][2], tp4.y, yr1.x);
            fma2(C3I[0][3], tp4.x, yi1.y); fma2(C3I[0][3], tp4.y, yr1.y);
            tn4 = *reinterpret_cast<const ulonglong2*>(&twn[pb]);
            tp4 = *reinterpret_cast<const ulonglong2*>(&twp[pb]);
            fma2(C3R[1][0], tn4.x, yr0.x); fma2(C3R[1][0], tn4.y, yi0.x);
            fma2(C3R[1][1], tn4.x, yr0.y); fma2(C3R[1][1], tn4.y, yi0.y);
            fma2(C3R[1][2], tn4.x, yr1.x); fma2(C3R[1][2], tn4.y, yi1.x);
            fma2(C3R[1][3], tn4.x, yr1.y); fma2(C3R[1][3], tn4.y, yi1.y);
            fma2(C3I[1][0], tp4.x, yi0.x); fma2(C3I[1][0], tp4.y, yr0.x);
            fma2(C3I[1][1], tp4.x, yi0.y); fma2(C3I[1][1], tp4.y, yr0.y);
            fma2(C3I[1][2], tp4.x, yi1.x); fma2(C3I[1][2], tp4.y, yr1.x);
            fma2(C3I[1][3], tp4.x, yi1.y); fma2(C3I[1][3], tp4.y, yr1.y);
            pa = (pa + stpa) & 255; pb = (pb + stpb) & 255;
        }
    }
    // ---- combine classes + bias + res, then SiLU + store -------------------
    ull ys[2][4][4];
    {
        ulonglong2 b01 = *reinterpret_cast<const ulonglong2*>(&rbs[o0]);
        ulonglong2 b23 = *reinterpret_cast<const ulonglong2*>(&rbs[o0 + 4]);
        ull bias[4] = {b01.x, b01.y, b23.x, b23.y};
#pragma unroll
        for (int s = 0; s < 2; s++)
#pragma unroll
            for (int j = 0; j < 4; j++) {
                ull e  = add2(C0R[s][j], C2R[s][j]);
                ull f  = sub2(C0R[s][j], C2R[s][j], NEG1);
                ull g  = add2(C1R[s][j], C3R[s][j]);
                ull hh = sub2(C3I[s][j], C1I[s][j], NEG1);
                ys[s][0][j] = add2(add2(e, g),  bias[j]);
                ys[s][2][j] = add2(sub2(e, g,  NEG1), bias[j]);
                ys[s][1][j] = add2(add2(f, hh), bias[j]);
                ys[s][3][j] = add2(sub2(f, hh, NEG1), bias[j]);
            }
    }
#pragma unroll
    for (int s = 0; s < 2; s++) {
        const int wbase = pr + 32*s;
#pragma unroll
        for (int q = 0; q < 4; q++) {
            const int w = wbase + 64*q;
            ulonglong2 r01 = *reinterpret_cast<const ulonglong2*>(&res[w*OUTD + o0]);
            ulonglong2 r23 = *reinterpret_cast<const ulonglong2*>(&res[w*OUTD + o0 + 4]);
            ys[s][q][0] = add2(ys[s][q][0], r01.x);
            ys[s][q][1] = add2(ys[s][q][1], r01.y);
            ys[s][q][2] = add2(ys[s][q][2], r23.x);
            ys[s][q][3] = add2(ys[s][q][3], r23.y);
            float4 v4[2];
#pragma unroll
            for (int c = 0; c < 4; c++) {
                float2 v = unpk(ys[s][q][c]);
                v.x = v.x / (1.f + __expf(-v.x));
                v.y = v.y / (1.f + __expf(-v.y));
                reinterpret_cast<float2*>(v4)[c] = v;
            }
            size_t o = (size_t)((n*RR + h)*RR + w)*OUTD + o0;
            *reinterpret_cast<float4*>(&out[o])     = v4[0];
            *reinterpret_cast<float4*>(&out[o + 4]) = v4[1];
        }
    }
}

// ---------------- launch ----------------------------------------------------
extern "C" void kernel_launch(void* const* d_in, const int* in_sizes, int n_in,
                              void* d_out, int out_size) {
    const float* x   = (const float*)d_in[0];
    const float* w0  = (const float*)d_in[1];
    const float* w1  = (const float*)d_in[2];
    const float* rsw = (const float*)d_in[3];
    const float* rsb = (const float*)d_in[4];
    float* out = (float*)d_out;

    cudaFuncSetAttribute(k1_fwd_w, cudaFuncAttributeMaxDynamicSharedMemorySize, 65536);
    cudaFuncSetAttribute(k5_inv_w, cudaFuncAttributeMaxDynamicSharedMemorySize, 65536);

    k_init_tw<<<1, 256>>>();
    k1_fwd_w<<<NB*RR, 256, 65536>>>(x);
    k2_fwd_h<<<NB*MD*2, 256>>>();
    k3_mix<<<KXN*MD, 256>>>(w0, w1);
    k4_inv_h<<<NB*MD*2, 256>>>();
    k5_inv_w<<<NB*RR, 256, 65536>>>(x, rsw, rsb, out);
}

// round 13
// speedup vs baseline: 1.1634x; 1.1634x over previous
#include <cuda_runtime.h>
#include <cuda_fp16.h>

#define NB   8
#define RR   256
#define IND  64
#define OUTD 64
#define MD   32
#define KXN  64

typedef unsigned long long ull;

// ---------------- scratch (device globals; no allocations allowed) ----------
__device__ __half g_XwRh[NB*MD*RR*IND];   // [n][ky][h][i]  forward w-DFT (fp16)
__device__ __half g_XwIh[NB*MD*RR*IND];
__device__ float g_XmR[NB*MD*KXN*IND];    // [ky][kx][n][i] forward modes
__device__ float g_XmI[NB*MD*KXN*IND];
__device__ float g_OmR[NB*MD*KXN*OUTD];   // [n][ky][kx][o] mixed modes
__device__ float g_OmI[NB*MD*KXN*OUTD];
__device__ __half g_Y1Rh[NB*RR*MD*OUTD];  // [n][h][ky][o]  inverse h-DFT (fp16)
__device__ __half g_Y1Ih[NB*RR*MD*OUTD];
__device__ float4 g_tw4p[256];            // (c, c,  s,  s)
__device__ float4 g_tw4n[256];            // (c, c, -s, -s)

// ---------------- packed f32x2 helpers --------------------------------------
__device__ __forceinline__ void fma2(ull &d, ull a, ull b) {
    asm("fma.rn.f32x2 %0, %1, %2, %0;" : "+l"(d) : "l"(a), "l"(b));
}
__device__ __forceinline__ ull splat2(float x) {
    ull r; asm("mov.b64 %0, {%1, %1};" : "=l"(r) : "f"(x)); return r;
}
__device__ __forceinline__ ull pack2(float x, float y) {
    ull r; asm("mov.b64 %0, {%1, %2};" : "=l"(r) : "f"(x), "f"(y)); return r;
}
__device__ __forceinline__ ull mul2(ull a, ull b) {
    ull r; asm("mul.rn.f32x2 %0, %1, %2;" : "=l"(r) : "l"(a), "l"(b)); return r;
}
__device__ __forceinline__ ull add2(ull a, ull b) {
    ull r; asm("add.rn.f32x2 %0, %1, %2;" : "=l"(r) : "l"(a), "l"(b)); return r;
}
__device__ __forceinline__ ull sub2(ull a, ull b, ull negone) {   // a - b
    ull r; asm("fma.rn.f32x2 %0, %1, %2, %3;" : "=l"(r) : "l"(b), "l"(negone), "l"(a)); return r;
}
__device__ __forceinline__ float2 unpk(ull v) {
    float2 r; asm("mov.b64 {%0, %1}, %2;" : "=f"(r.x), "=f"(r.y) : "l"(v)); return r;
}
// ---------------- fp16 pack/unpack helpers ----------------------------------
__device__ __forceinline__ unsigned f22h(float a, float b) {
    __half2 h = __floats2half2_rn(a, b);
    return *reinterpret_cast<unsigned*>(&h);
}
__device__ __forceinline__ ulonglong2 h4f(uint2 u) {            // 4 halves -> 2 packed f32x2
    __half2 ha = *reinterpret_cast<__half2*>(&u.x);
    __half2 hb = *reinterpret_cast<__half2*>(&u.y);
    float2 fa = __half22float2(ha), fb = __half22float2(hb);
    return make_ulonglong2(pack2(fa.x, fa.y), pack2(fb.x, fb.y));
}
__device__ __forceinline__ void h8store(float* dst, uint4 u) {  // 8 halves -> smem f32
    __half2* hp = reinterpret_cast<__half2*>(&u);
    float2 f0 = __half22float2(hp[0]), f1 = __half22float2(hp[1]);
    float2 f2 = __half22float2(hp[2]), f3 = __half22float2(hp[3]);
    *reinterpret_cast<float4*>(dst)     = make_float4(f0.x, f0.y, f1.x, f1.y);
    *reinterpret_cast<float4*>(dst + 4) = make_float4(f2.x, f2.y, f3.x, f3.y);
}

__global__ void k_init_tw() {
    int k = threadIdx.x;
    double a = 6.283185307179586476925286766559 * (double)k / 256.0;
    float c = (float)cos(a), s = (float)sin(a);
    g_tw4p[k] = make_float4(c, c,  s,  s);
    g_tw4n[k] = make_float4(c, c, -s, -s);
}

// ---------------- K1: forward DFT along w (radix-4, 256 thr, 2 ky/thread) ---
__global__ __launch_bounds__(256) void k1_fwd_w(const float* __restrict__ x) {
    extern __shared__ __align__(16) float us[];   // u0|u2|d02|d13, each [64][64]
    __shared__ __align__(16) float4 twp[256], twn[256];
    const int t = threadIdx.x;
    twp[t] = g_tw4p[t]; twn[t] = g_tw4n[t];
    const int b = blockIdx.x, n = b >> 8, h = b & 255;
    const float* xb = x + (size_t)(n*RR + h)*RR*IND;
    float* u0s = us; float* u2s = us + 4096; float* d2s = us + 8192; float* d3s = us + 12288;
#pragma unroll
    for (int it = 0; it < 16; it++) {
        int idx = t + 256*it;                    // idx = w0*64 + i
        float a0 = xb[idx], a1 = xb[idx + 4096], a2 = xb[idx + 8192], a3 = xb[idx + 12288];
        float s02 = a0 + a2, d02 = a0 - a2, s13 = a1 + a3, d13 = a1 - a3;
        u0s[idx] = s02 + s13; u2s[idx] = s02 - s13; d2s[idx] = d02; d3s[idx] = d13;
    }
    __syncthreads();

    const int i0 = (t & 15) * 4;
    const int slot = (t >> 4) & 7;
    const bool oddky = (t >= 128);               // warp-uniform
    const int ky_a = 2*slot + (oddky ? 1 : 0);
    const int ky_b = ky_a + 16;
    ull aR[2][2] = {{0,0},{0,0}}, aI[2][2] = {{0,0},{0,0}};
    int pa = 0, pb = 0;
    const float sc = 1.f/256.f;
    float iscl = sc;

    if (!oddky) {
        const float* Up = (slot & 1) ? u2s : u0s;
        for (int w0 = 0; w0 < 64; w0++) {
            ulonglong2 U = *reinterpret_cast<const ulonglong2*>(&Up[w0*64 + i0]);
            ulonglong2 ta = *reinterpret_cast<const ulonglong2*>(&twn[pa]);
            fma2(aR[0][0], ta.x, U.x); fma2(aR[0][1], ta.x, U.y);
            fma2(aI[0][0], ta.y, U.x); fma2(aI[0][1], ta.y, U.y);
            ulonglong2 tb = *reinterpret_cast<const ulonglong2*>(&twn[pb]);
            fma2(aR[1][0], tb.x, U.x); fma2(aR[1][1], tb.x, U.y);
            fma2(aI[1][0], tb.y, U.x); fma2(aI[1][1], tb.y, U.y);
            pa = (pa + ky_a) & 255; pb = (pb + ky_b) & 255;
        }
    } else {
        const bool c1 = ((slot & 1) == 0);
        const ull S = splat2(c1 ? 1.f : -1.f);
        iscl = c1 ? -sc : sc;
        for (int w0 = 0; w0 < 64; w0++) {
            ulonglong2 D2 = *reinterpret_cast<const ulonglong2*>(&d2s[w0*64 + i0]);
            ulonglong2 D3 = *reinterpret_cast<const ulonglong2*>(&d3s[w0*64 + i0]);
            ull D3r0 = mul2(D3.x, S), D3r1 = mul2(D3.y, S);
            ull D2i0 = mul2(D2.x, S), D2i1 = mul2(D2.y, S);
            ulonglong2 tpa = *reinterpret_cast<const ulonglong2*>(&twp[pa]);
            ulonglong2 tna = *reinterpret_cast<const ulonglong2*>(&twn[pa]);
            fma2(aR[0][0], tpa.x, D2.x); fma2(aR[0][1], tpa.x, D2.y);
            fma2(aR[0][0], tna.y, D3r0); fma2(aR[0][1], tna.y, D3r1);
            fma2(aI[0][0], tpa.x, D3.x); fma2(aI[0][1], tpa.x, D3.y);
            fma2(aI[0][0], tpa.y, D2i0); fma2(aI[0][1], tpa.y, D2i1);
            ulonglong2 tpb = *reinterpret_cast<const ulonglong2*>(&twp[pb]);
            ulonglong2 tnb = *reinterpret_cast<const ulonglong2*>(&twn[pb]);
            fma2(aR[1][0], tpb.x, D2.x); fma2(aR[1][1], tpb.x, D2.y);
            fma2(aR[1][0], tnb.y, D3r0); fma2(aR[1][1], tnb.y, D3r1);
            fma2(aI[1][0], tpb.x, D3.x); fma2(aI[1][1], tpb.x, D3.y);
            fma2(aI[1][0], tpb.y, D2i0); fma2(aI[1][1], tpb.y, D2i1);
            pa = (pa + ky_a) & 255; pb = (pb + ky_b) & 255;
        }
    }
#pragma unroll
    for (int j = 0; j < 2; j++) {
        const int ky = j ? ky_b : ky_a;
        size_t o = (size_t)((n*MD + ky)*RR + h)*IND + i0;
        float2 a0 = unpk(aR[j][0]), a1 = unpk(aR[j][1]);
        *reinterpret_cast<uint2*>(&g_XwRh[o]) =
            make_uint2(f22h(a0.x*sc, a0.y*sc), f22h(a1.x*sc, a1.y*sc));
        a0 = unpk(aI[j][0]); a1 = unpk(aI[j][1]);
        *reinterpret_cast<uint2*>(&g_XwIh[o]) =
            make_uint2(f22h(a0.x*iscl, a0.y*iscl), f22h(a1.x*iscl, a1.y*iscl));
    }
}

// ---------------- K2: forward h-DFT, radix-4, register-prefetch pipeline ----
__global__ __launch_bounds__(256, 3) void k2_fwd_h() {
    __shared__ __align__(16) float Vs[8*16*64];       // 8 planes x [16 h0][64 i] = 32KB
    __shared__ __align__(16) float4 twp[256], twn[256];
    const int t = threadIdx.x;
    twp[t] = g_tw4p[t]; twn[t] = g_tw4n[t];
    const int b = blockIdx.x, half = b & 1, ky = (b >> 1) & 31, n = b >> 6;
    const __half* baseR = g_XwRh + (size_t)(n*MD + ky)*RR*IND;
    const __half* baseI = g_XwIh + (size_t)(n*MD + ky)*RR*IND;
    const int i0 = (t & 15) * 4;
    const int g = t >> 4, c = g & 3, mseg = g >> 2;
    const int kxl0 = 8*mseg + c;                       // slots of class c
    const int kap0 = half ? (224 + kxl0) : kxl0;
    const int kap1 = kap0 + 4;
    const int h0ld = t >> 4, iq = (t & 15) * 4;        // loader role (1 per thread)
    const ull NEG1 = splat2(-1.f);
    ull aR[2][2] = {{0,0},{0,0}}, aI[2][2] = {{0,0},{0,0}};
    int p0 = 0, p1 = 0;

    uint2 R0u, R1u, R2u, R3u, I0u, I1u, I2u, I3u;
    {
        const __half* pR = baseR + h0ld*IND + iq;
        const __half* pI = baseI + h0ld*IND + iq;
        R0u = *reinterpret_cast<const uint2*>(pR);
        R1u = *reinterpret_cast<const uint2*>(pR + 64*IND);
        R2u = *reinterpret_cast<const uint2*>(pR + 128*IND);
        R3u = *reinterpret_cast<const uint2*>(pR + 192*IND);
        I0u = *reinterpret_cast<const uint2*>(pI);
        I1u = *reinterpret_cast<const uint2*>(pI + 64*IND);
        I2u = *reinterpret_cast<const uint2*>(pI + 128*IND);
        I3u = *reinterpret_cast<const uint2*>(pI + 192*IND);
    }

    for (int hc = 0; hc < 64; hc += 16) {
        __syncthreads();
        {   // convert + butterfly registers -> Vs
            ulonglong2 R0 = h4f(R0u), R1 = h4f(R1u), R2 = h4f(R2u), R3 = h4f(R3u);
            ulonglong2 I0 = h4f(I0u), I1 = h4f(I1u), I2 = h4f(I2u), I3 = h4f(I3u);
            ull sRx = add2(R0.x, R2.x), sRy = add2(R0.y, R2.y);
            ull dRx = sub2(R0.x, R2.x, NEG1), dRy = sub2(R0.y, R2.y, NEG1);
            ull uRx = add2(R1.x, R3.x), uRy = add2(R1.y, R3.y);
            ull eRx = sub2(R1.x, R3.x, NEG1), eRy = sub2(R1.y, R3.y, NEG1);
            ull sIx = add2(I0.x, I2.x), sIy = add2(I0.y, I2.y);
            ull dIx = sub2(I0.x, I2.x, NEG1), dIy = sub2(I0.y, I2.y, NEG1);
            ull uIx = add2(I1.x, I3.x), uIy = add2(I1.y, I3.y);
            ull eIx = sub2(I1.x, I3.x, NEG1), eIy = sub2(I1.y, I3.y, NEG1);
            const int rb = h0ld*64 + iq;
            ulonglong2* vp;
            vp = reinterpret_cast<ulonglong2*>(&Vs[0*1024 + rb]);
            *vp = make_ulonglong2(add2(sRx, uRx), add2(sRy, uRy));
            vp = reinterpret_cast<ulonglong2*>(&Vs[1*1024 + rb]);
            *vp = make_ulonglong2(add2(sIx, uIx), add2(sIy, uIy));
            vp = reinterpret_cast<ulonglong2*>(&Vs[2*1024 + rb]);
            *vp = make_ulonglong2(add2(dRx, eIx), add2(dRy, eIy));
            vp = reinterpret_cast<ulonglong2*>(&Vs[3*1024 + rb]);
            *vp = make_ulonglong2(sub2(dIx, eRx, NEG1), sub2(dIy, eRy, NEG1));
            vp = reinterpret_cast<ulonglong2*>(&Vs[4*1024 + rb]);
            *vp = make_ulonglong2(sub2(sRx, uRx, NEG1), sub2(sRy, uRy, NEG1));
            vp = reinterpret_cast<ulonglong2*>(&Vs[5*1024 + rb]);
            *vp = make_ulonglong2(sub2(sIx, uIx, NEG1), sub2(sIy, uIy, NEG1));
            vp = reinterpret_cast<ulonglong2*>(&Vs[6*1024 + rb]);
            *vp = make_ulonglong2(sub2(dRx, eIx, NEG1), sub2(dRy, eIy, NEG1));
            vp = reinterpret_cast<ulonglong2*>(&Vs[7*1024 + rb]);
            *vp = make_ulonglong2(add2(dIx, eRx), add2(dIy, eRy));
        }
        __syncthreads();
        if (hc < 48) {
            const __half* pR = baseR + (hc + 16 + h0ld)*IND + iq;
            const __half* pI = baseI + (hc + 16 + h0ld)*IND + iq;
            R0u = *reinterpret_cast<const uint2*>(pR);
            R1u = *reinterpret_cast<const uint2*>(pR + 64*IND);
            R2u = *reinterpret_cast<const uint2*>(pR + 128*IND);
            R3u = *reinterpret_cast<const uint2*>(pR + 192*IND);
            I0u = *reinterpret_cast<const uint2*>(pI);
            I1u = *reinterpret_cast<const uint2*>(pI + 64*IND);
            I2u = *reinterpret_cast<const uint2*>(pI + 128*IND);
            I3u = *reinterpret_cast<const uint2*>(pI + 192*IND);
        }
        const float* VRb = &Vs[(c*2 + 0)*1024];
        const float* VIb = &Vs[(c*2 + 1)*1024];
        for (int h0l = 0; h0l < 16; h0l++) {
            ulonglong2 VR = *reinterpret_cast<const ulonglong2*>(&VRb[h0l*64 + i0]);
            ulonglong2 VI = *reinterpret_cast<const ulonglong2*>(&VIb[h0l*64 + i0]);
            ulonglong2 tp4 = *reinterpret_cast<const ulonglong2*>(&twp[p0]);
            ulonglong2 tn4 = *reinterpret_cast<const ulonglong2*>(&twn[p0]);
            fma2(aR[0][0], tp4.x, VR.x); fma2(aR[0][0], tp4.y, VI.x);
            fma2(aR[0][1], tp4.x, VR.y); fma2(aR[0][1], tp4.y, VI.y);
            fma2(aI[0][0], tp4.x, VI.x); fma2(aI[0][0], tn4.y, VR.x);
            fma2(aI[0][1], tp4.x, VI.y); fma2(aI[0][1], tn4.y, VR.y);
            p0 = (p0 + kap0) & 255;
            tp4 = *reinterpret_cast<const ulonglong2*>(&twp[p1]);
            tn4 = *reinterpret_cast<const ulonglong2*>(&twn[p1]);
            fma2(aR[1][0], tp4.x, VR.x); fma2(aR[1][0], tp4.y, VI.x);
            fma2(aR[1][1], tp4.x, VR.y); fma2(aR[1][1], tp4.y, VI.y);
            fma2(aI[1][0], tp4.x, VI.x); fma2(aI[1][0], tn4.y, VR.x);
            fma2(aI[1][1], tp4.x, VI.y); fma2(aI[1][1], tn4.y, VR.y);
            p1 = (p1 + kap1) & 255;
        }
    }
#pragma unroll
    for (int j = 0; j < 2; j++) {
        int kxs = half*32 + kxl0 + 4*j;
        size_t o = (size_t)((ky*KXN + kxs)*NB + n)*IND + i0;
        float2 a0 = unpk(aR[j][0]), a1 = unpk(aR[j][1]);
        *reinterpret_cast<float4*>(&g_XmR[o]) = make_float4(a0.x, a0.y, a1.x, a1.y);
        a0 = unpk(aI[j][0]); a1 = unpk(aI[j][1]);
        *reinterpret_cast<float4*>(&g_XmI[o]) = make_float4(a0.x, a0.y, a1.x, a1.y);
    }
}

// ---------------- K3: per-mode complex channel mix (8x64x64) ----------------
__global__ __launch_bounds__(256) void k3_mix(const float* __restrict__ w0,
                                              const float* __restrict__ w1) {
    __shared__ float Xs2[NB*IND*2];                   // interleaved (R,I)
    const int t = threadIdx.x, b = blockIdx.x;
    const int kx = b >> 5, ky = b & 31;
    size_t xb = (size_t)(ky*KXN + kx)*NB*IND;
#pragma unroll
    for (int it = 0; it < 2; it++) {
        int idx = t + 256*it;
        Xs2[2*idx]     = g_XmR[xb + idx];
        Xs2[2*idx + 1] = g_XmI[xb + idx];
    }
    __syncthreads();
    const float4* wp4 = reinterpret_cast<const float4*>(
        (kx < MD) ? (w0 + (size_t)(kx*MD + ky)*IND*OUTD*2)
                  : (w1 + (size_t)((kx - MD)*MD + ky)*IND*OUTD*2));
    const int o2 = t & 31, n = t >> 5;                // o0 = 2*o2, one n per thread
    float r0 = 0.f, i0 = 0.f, r1 = 0.f, i1 = 0.f;
#pragma unroll 8
    for (int i = 0; i < IND; i++) {
        float4 w = wp4[i*32 + o2];                    // (wR0,wI0,wR1,wI1)
        float2 xv = *reinterpret_cast<const float2*>(&Xs2[(n*IND + i)*2]);
        r0 = fmaf(xv.x, w.x, fmaf(-xv.y, w.y, r0));
        i0 = fmaf(xv.x, w.y, fmaf( xv.y, w.x, i0));
        r1 = fmaf(xv.x, w.z, fmaf(-xv.y, w.w, r1));
        i1 = fmaf(xv.x, w.w, fmaf( xv.y, w.z, i1));
    }
    size_t gg = (size_t)((n*MD + ky)*KXN + kx)*OUTD + 2*o2;
    *reinterpret_cast<float2*>(&g_OmR[gg]) = make_float2(r0, r1);
    *reinterpret_cast<float2*>(&g_OmI[gg]) = make_float2(i0, i1);
}

// ---------------- K4: inverse h-DFT, radix-4 on output ----------------------
#define K4STEP(CR, CI) { \
    ulonglong2 R0 = *reinterpret_cast<const ulonglong2*>(&sR[kxo]); \
    ulonglong2 R1 = *reinterpret_cast<const ulonglong2*>(&sR[kxo + 4]); \
    ulonglong2 I0 = *reinterpret_cast<const ulonglong2*>(&sI[kxo]); \
    ulonglong2 I1 = *reinterpret_cast<const ulonglong2*>(&sI[kxo + 4]); \
    ulonglong2 tp4 = *reinterpret_cast<const ulonglong2*>(&twp[p]); \
    ulonglong2 tn4 = *reinterpret_cast<const ulonglong2*>(&twn[p]); \
    fma2(CR[0], tn4.x, R0.x); fma2(CR[0], tn4.y, I0.x); \
    fma2(CR[1], tn4.x, R0.y); fma2(CR[1], tn4.y, I0.y); \
    fma2(CR[2], tn4.x, R1.x); fma2(CR[2], tn4.y, I1.x); \
    fma2(CR[3], tn4.x, R1.y); fma2(CR[3], tn4.y, I1.y); \
    fma2(CI[0], tp4.x, I0.x); fma2(CI[0], tp4.y, R0.x); \
    fma2(CI[1], tp4.x, I0.y); fma2(CI[1], tp4.y, R0.y); \
    fma2(CI[2], tp4.x, I1.x); fma2(CI[2], tp4.y, R1.x); \
    fma2(CI[3], tp4.x, I1.y); fma2(CI[3], tp4.y, R1.y); \
    p = (p + h0) & 255; kxo += OUTD; }

__global__ __launch_bounds__(256) void k4_inv_h() {
    __shared__ __align__(16) float sR[KXN*OUTD], sI[KXN*OUTD];
    __shared__ __align__(16) float4 twp[256], twn[256];
    const int t = threadIdx.x;
    twp[t] = g_tw4p[t]; twn[t] = g_tw4n[t];
    const int b = blockIdx.x, grp = b & 1, ky = (b >> 1) & 31, n = b >> 6;
    const float4* pR = reinterpret_cast<const float4*>(g_OmR + (size_t)(n*MD + ky)*KXN*OUTD);
    const float4* pI = reinterpret_cast<const float4*>(g_OmI + (size_t)(n*MD + ky)*KXN*OUTD);
#pragma unroll
    for (int it = 0; it < 4; it++) {
        reinterpret_cast<float4*>(sR)[t + 256*it] = pR[t + 256*it];
        reinterpret_cast<float4*>(sI)[t + 256*it] = pI[t + 256*it];
    }
    __syncthreads();
    const int o0 = (t & 7) * 8, h0 = grp*32 + (t >> 3);
    ull C0R[4], C0I[4], C1R[4], C1I[4], C2R[4], C2I[4], C3R[4], C3I[4];
#pragma unroll
    for (int j = 0; j < 4; j++) {
        C0R[j]=C0I[j]=C1R[j]=C1I[j]=0ull;
        C2R[j]=C2I[j]=C3R[j]=C3I[j]=0ull;
    }
#pragma unroll 1
    for (int kh = 0; kh < 2; kh++) {
        int p = kh ? ((224*h0) & 255) : 0;
        int kxo = (kh*32)*OUTD + o0;
#pragma unroll
        for (int kk = 0; kk < 32; kk += 4) {
            K4STEP(C0R, C0I)
            K4STEP(C1R, C1I)
            K4STEP(C2R, C2I)
            K4STEP(C3R, C3I)
        }
    }
    const ull NEG1 = splat2(-1.f);
    const ull FAC2 = splat2((ky == 0 ? 1.f : 2.f) * (1.f/256.f));
    const size_t obase = (size_t)((n*RR + h0)*MD + ky)*OUTD + o0;
#pragma unroll
    for (int j = 0; j < 4; j++) {
        ull ER = add2(C0R[j], C2R[j]), EI = add2(C0I[j], C2I[j]);
        ull FR = sub2(C0R[j], C2R[j], NEG1), FI = sub2(C0I[j], C2I[j], NEG1);
        ull GR = add2(C1R[j], C3R[j]), GI = add2(C1I[j], C3I[j]);
        ull HR = sub2(C1R[j], C3R[j], NEG1), HI = sub2(C1I[j], C3I[j], NEG1);
        ull YR[4] = { add2(ER, GR), sub2(FR, HI, NEG1), sub2(ER, GR, NEG1), add2(FR, HI) };
        ull YI[4] = { add2(EI, GI), add2(FI, HR), sub2(EI, GI, NEG1), sub2(FI, HR, NEG1) };
#pragma unroll
        for (int q = 0; q < 4; q++) {
            size_t o = obase + (size_t)(64*q)*MD*OUTD + 2*j;
            float2 vr = unpk(mul2(YR[q], FAC2));
            float2 vi = unpk(mul2(YI[q], FAC2));
            *reinterpret_cast<unsigned*>(&g_Y1Rh[o]) = f22h(vr.x, vr.y);
            *reinterpret_cast<unsigned*>(&g_Y1Ih[o]) = f22h(vi.x, vi.y);
        }
    }
}

// ---------------- K5: radix-4 inverse w synthesis + residual + SiLU ---------
#define XPAD 68
__global__ __launch_bounds__(256) void k5_inv_w(const float* __restrict__ x,
                                                const float* __restrict__ res_w,
                                                const float* __restrict__ res_b,
                                                float* __restrict__ out) {
    extern __shared__ __align__(16) float xs[];       // [256][XPAD]
    __shared__ __align__(16) float YsR[MD*OUTD], YsI[MD*OUTD];
    __shared__ __align__(16) float rws[IND*OUTD];
    __shared__ __align__(16) float4 twp[256], twn[256];
    __shared__ __align__(16) float rbs[64];
    const int t = threadIdx.x, b = blockIdx.x, n = b >> 8, h = b & 255;
    twp[t] = g_tw4p[t];
    twn[t] = g_tw4n[t];
    const float4* xp = reinterpret_cast<const float4*>(x + (size_t)(n*RR + h)*RR*IND);
#pragma unroll
    for (int it = 0; it < 16; it++) {
        int j = t + 256*it;
        float4 v = xp[j];
        int w = j >> 4, c = j & 15;
        *reinterpret_cast<float4*>(&xs[w*XPAD + c*4]) = v;
    }
    {   // Y1 fp16 -> fp32 smem (one uint4 = 8 halves per thread per plane)
        const uint4* yRu = reinterpret_cast<const uint4*>(g_Y1Rh + (size_t)(n*RR + h)*MD*OUTD);
        const uint4* yIu = reinterpret_cast<const uint4*>(g_Y1Ih + (size_t)(n*RR + h)*MD*OUTD);
        h8store(&YsR[t*8], yRu[t]);
        h8store(&YsI[t*8], yIu[t]);
    }
#pragma unroll
    for (int it = 0; it < 4; it++)
        reinterpret_cast<float4*>(rws)[t + 256*it] =
            reinterpret_cast<const float4*>(res_w)[t + 256*it];
    if (t < 64) rbs[t] = res_b[t];
    __syncthreads();

    const int og = t & 7, o0 = og*8, pr = t >> 3;     // w0a = pr, w0b = pr + 32
    const ull NEG1 = splat2(-1.f);
    ull C0R[2][4], C2R[2][4], C1R[2][4], C1I[2][4], C3R[2][4], C3I[2][4];
#pragma unroll
    for (int s = 0; s < 2; s++)
#pragma unroll
        for (int j = 0; j < 4; j++) {
            C0R[s][j]=C2R[s][j]=C1R[s][j]=C1I[s][j]=C3R[s][j]=C3I[s][j]=0ull;
        }
    int pa = 0, pb = 0;
    const int stpa = pr, stpb = pr + 32;
#pragma unroll
    for (int kb = 0; kb < 8; kb++) {
        // c = 0
        {
            const int ky = 4*kb;
            ulonglong2 yr0 = *reinterpret_cast<const ulonglong2*>(&YsR[ky*OUTD + o0]);
            ulonglong2 yr1 = *reinterpret_cast<const ulonglong2*>(&YsR[ky*OUTD + o0 + 4]);
            ulonglong2 yi0 = *reinterpret_cast<const ulonglong2*>(&YsI[ky*OUTD + o0]);
            ulonglong2 yi1 = *reinterpret_cast<const ulonglong2*>(&YsI[ky*OUTD + o0 + 4]);
            ulonglong2 tn4 = *reinterpret_cast<const ulonglong2*>(&twn[pa]);
            fma2(C0R[0][0], tn4.x, yr0.x); fma2(C0R[0][0], tn4.y, yi0.x);
            fma2(C0R[0][1], tn4.x, yr0.y); fma2(C0R[0][1], tn4.y, yi0.y);
            fma2(C0R[0][2], tn4.x, yr1.x); fma2(C0R[0][2], tn4.y, yi1.x);
            fma2(C0R[0][3], tn4.x, yr1.y); fma2(C0R[0][3], tn4.y, yi1.y);
            tn4 = *reinterpret_cast<const ulonglong2*>(&twn[pb]);
            fma2(C0R[1][0], tn4.x, yr0.x); fma2(C0R[1][0], tn4.y, yi0.x);
            fma2(C0R[1][1], tn4.x, yr0.y); fma2(C0R[1][1], tn4.y, yi0.y);
            fma2(C0R[1][2], tn4.x, yr1.x); fma2(C0R[1][2], tn4.y, yi1.x);
            fma2(C0R[1][3], tn4.x, yr1.y); fma2(C0R[1][3], tn4.y, yi1.y);
            pa = (pa + stpa) & 255; pb = (pb + stpb) & 255;
        }
        // c = 1
        {
            const int ky = 4*kb + 1;
            ulonglong2 yr0 = *reinterpret_cast<const ulonglong2*>(&YsR[ky*OUTD + o0]);
            ulonglong2 yr1 = *reinterpret_cast<const ulonglong2*>(&YsR[ky*OUTD + o0 + 4]);
            ulonglong2 yi0 = *reinterpret_cast<const ulonglong2*>(&YsI[ky*OUTD + o0]);
            ulonglong2 yi1 = *reinterpret_cast<const ulonglong2*>(&YsI[ky*OUTD + o0 + 4]);
            ulonglong2 tn4 = *reinterpret_cast<const ulonglong2*>(&twn[pa]);
            ulonglong2 tp4 = *reinterpret_cast<const ulonglong2*>(&twp[pa]);
            fma2(C1R[0][0], tn4.x, yr0.x); fma2(C1R[0][0], tn4.y, yi0.x);
            fma2(C1R[0][1], tn4.x, yr0.y); fma2(C1R[0][1], tn4.y, yi0.y);
            fma2(C1R[0][2], tn4.x, yr1.x); fma2(C1R[0][2], tn4.y, yi1.x);
            fma2(C1R[0][3], tn4.x, yr1.y); fma2(C1R[0][3], tn4.y, yi1.y);
            fma2(C1I[0][0], tp4.x, yi0.x); fma2(C1I[0][0], tp4.y, yr0.x);
            fma2(C1I[0][1], tp4.x, yi0.y); fma2(C1I[0][1], tp4.y, yr0.y);
            fma2(C1I[0][2], tp4.x, yi1.x); fma2(C1I[0][2], tp4.y, yr1.x);
            fma2(C1I[0][3], tp4.x, yi1.y); fma2(C1I[0][3], tp4.y, yr1.y);
            tn4 = *reinterpret_cast<const ulonglong2*>(&twn[pb]);
            tp4 = *reinterpret_cast<const ulonglong2*>(&twp[pb]);
            fma2(C1R[1][0], tn4.x, yr0.x); fma2(C1R[1][0], tn4.y, yi0.x);
            fma2(C1R[1][1], tn4.x, yr0.y); fma2(C1R[1][1], tn4.y, yi0.y);
            fma2(C1R[1][2], tn4.x, yr1.x); fma2(C1R[1][2], tn4.y, yi1.x);
            fma2(C1R[1][3], tn4.x, yr1.y); fma2(C1R[1][3], tn4.y, yi1.y);
            fma2(C1I[1][0], tp4.x, yi0.x); fma2(C1I[1][0], tp4.y, yr0.x);
            fma2(C1I[1][1], tp4.x, yi0.y); fma2(C1I[1][1], tp4.y, yr0.y);
            fma2(C1I[1][2], tp4.x, yi1.x); fma2(C1I[1][2], tp4.y, yr1.x);
            fma2(C1I[1][3], tp4.x, yi1.y); fma2(C1I[1][3], tp4.y, yr1.y);
            pa = (pa + stpa) & 255; pb = (pb + stpb) & 255;
        }
        // c = 2
        {
            const int ky = 4*kb + 2;
            ulonglong2 yr0 = *reinterpret_cast<const ulonglong2*>(&YsR[ky*OUTD + o0]);
            ulonglong2 yr1 = *reinterpret_cast<const ulonglong2*>(&YsR[ky*OUTD + o0 + 4]);
            ulonglong2 yi0 = *reinterpret_cast<const ulonglong2*>(&YsI[ky*OUTD + o0]);
            ulonglong2 yi1 = *reinterpret_cast<const ulonglong2*>(&YsI[ky*OUTD + o0 + 4]);
            ulonglong2 tn4 = *reinterpret_cast<const ulonglong2*>(&twn[pa]);
            fma2(C2R[0][0], tn4.x, yr0.x); fma2(C2R[0][0], tn4.y, yi0.x);
            fma2(C2R[0][1], tn4.x, yr0.y); fma2(C2R[0][1], tn4.y, yi0.y);
            fma2(C2R[0][2], tn4.x, yr1.x); fma2(C2R[0][2], tn4.y, yi1.x);
            fma2(C2R[0][3], tn4.x, yr1.y); fma2(C2R[0][3], tn4.y, yi1.y);
            tn4 = *reinterpret_cast<const ulonglong2*>(&twn[pb]);
            fma2(C2R[1][0], tn4.x, yr0.x); fma2(C2R[1][0], tn4.y, yi0.x);
            fma2(C2R[1][1], tn4.x, yr0.y); fma2(C2R[1][1], tn4.y, yi0.y);
            fma2(C2R[1][2], tn4.x, yr1.x); fma2(C2R[1][2], tn4.y, yi1.x);
            fma2(C2R[1][3], tn4.x, yr1.y); fma2(C2R[1][3], tn4.y, yi1.y);
            pa = (pa + stpa) & 255; pb = (pb + stpb) & 255;
        }
        // c = 3
        {
            const int ky = 4*kb + 3;
            ulonglong2 yr0 = *reinterpret_cast<const ulonglong2*>(&YsR[ky*OUTD + o0]);
            ulonglong2 yr1 = *reinterpret_cast<const ulonglong2*>(&YsR[ky*OUTD + o0 + 4]);
            ulonglong2 yi0 = *reinterpret_cast<const ulonglong2*>(&YsI[ky*OUTD + o0]);
            ulonglong2 yi1 = *reinterpret_cast<const ulonglong2*>(&YsI[ky*OUTD + o0 + 4]);
            ulonglong2 tn4 = *reinterpret_cast<const ulonglong2*>(&twn[pa]);
            ulonglong2 tp4 = *reinterpret_cast<const ulonglong2*>(&twp[pa]);
            fma2(C3R[0][0], tn4.x, yr0.x); fma2(C3R[0][0], tn4.y, yi0.x);
            fma2(C3R[0][1], tn4.x, yr0.y); fma2(C3R[0][1], tn4.y, yi0.y);
            fma2(C3R[0][2], tn4.x, yr1.x); fma2(C3R[0][2], tn4.y, yi1.x);
            fma2(C3R[0][3], tn4.x, yr1.y); fma2(C3R[0][3], tn4.y, yi1.y);
            fma2(C3I[0][0], tp4.x, yi0.x); fma2(C3I[0][0], tp4.y, yr0.x);
            fma2(C3I[0][1], tp4.x, yi0.y); fma2(C3I[0][1], tp4.y, yr0.y);
            fma2(C3I[0][2], tp4.x, yi1.x); fma2(C3I[0][2], tp4.y, yr1.x);
            fma2(C3I[0][3], tp4.x, yi1.y); fma2(C3I[0][3], tp4.y, yr1.y);
            tn4 = *reinterpret_cast<const ulonglong2*>(&twn[pb]);
            tp4 = *reinterpret_cast<const ulonglong2*>(&twp[pb]);
            fma2(C3R[1][0], tn4.x, yr0.x); fma2(C3R[1][0], tn4.y, yi0.x);
            fma2(C3R[1][1], tn4.x, yr0.y); fma2(C3R[1][1], tn4.y, yi0.y);
            fma2(C3R[1][2], tn4.x, yr1.x); fma2(C3R[1][2], tn4.y, yi1.x);
            fma2(C3R[1][3], tn4.x, yr1.y); fma2(C3R[1][3], tn4.y, yi1.y);
            fma2(C3I[1][0], tp4.x, yi0.x); fma2(C3I[1][0], tp4.y, yr0.x);
            fma2(C3I[1][1], tp4.x, yi0.y); fma2(C3I[1][1], tp4.y, yr0.y);
            fma2(C3I[1][2], tp4.x, yi1.x); fma2(C3I[1][2], tp4.y, yr1.x);
            fma2(C3I[1][3], tp4.x, yi1.y); fma2(C3I[1][3], tp4.y, yr1.y);
            pa = (pa + stpa) & 255; pb = (pb + stpb) & 255;
        }
    }
    // ---- combine classes into 4 output rows + bias, both w0 ----
    ull ys[2][4][4];
    {
        ulonglong2 b01 = *reinterpret_cast<const ulonglong2*>(&rbs[o0]);
        ulonglong2 b23 = *reinterpret_cast<const ulonglong2*>(&rbs[o0 + 4]);
        ull bias[4] = {b01.x, b01.y, b23.x, b23.y};
#pragma unroll
        for (int s = 0; s < 2; s++)
#pragma unroll
            for (int j = 0; j < 4; j++) {
                ull e  = add2(C0R[s][j], C2R[s][j]);
                ull f  = sub2(C0R[s][j], C2R[s][j], NEG1);
                ull g  = add2(C1R[s][j], C3R[s][j]);
                ull hh = sub2(C3I[s][j], C1I[s][j], NEG1);
                ys[s][0][j] = add2(add2(e, g),  bias[j]);
                ys[s][2][j] = add2(sub2(e, g,  NEG1), bias[j]);
                ys[s][1][j] = add2(add2(f, hh), bias[j]);
                ys[s][3][j] = add2(sub2(f, hh, NEG1), bias[j]);
            }
    }
    // ---- residual GEMM into ys (2 i per step, vector x loads) ----
    for (int i = 0; i < IND; i += 2) {
        ulonglong2 rA01 = *reinterpret_cast<const ulonglong2*>(&rws[i*OUTD + o0]);
        ulonglong2 rA23 = *reinterpret_cast<const ulonglong2*>(&rws[i*OUTD + o0 + 4]);
        ulonglong2 rB01 = *reinterpret_cast<const ulonglong2*>(&rws[(i+1)*OUTD + o0]);
        ulonglong2 rB23 = *reinterpret_cast<const ulonglong2*>(&rws[(i+1)*OUTD + o0 + 4]);
#pragma unroll
        for (int s = 0; s < 2; s++) {
            const int wbase = pr + 32*s;
#pragma unroll
            for (int q = 0; q < 4; q++) {
                float2 xv = *reinterpret_cast<const float2*>(&xs[(wbase + 64*q)*XPAD + i]);
                ull sxA = splat2(xv.x), sxB = splat2(xv.y);
                fma2(ys[s][q][0], sxA, rA01.x); fma2(ys[s][q][1], sxA, rA01.y);
                fma2(ys[s][q][2], sxA, rA23.x); fma2(ys[s][q][3], sxA, rA23.y);
                fma2(ys[s][q][0], sxB, rB01.x); fma2(ys[s][q][1], sxB, rB01.y);
                fma2(ys[s][q][2], sxB, rB23.x); fma2(ys[s][q][3], sxB, rB23.y);
            }
        }
    }
    // ---- SiLU + store ----
#pragma unroll
    for (int s = 0; s < 2; s++) {
        const int wbase = pr + 32*s;
#pragma unroll
        for (int q = 0; q < 4; q++) {
            float4 v4[2];
#pragma unroll
            for (int c = 0; c < 4; c++) {
                float2 v = unpk(ys[s][q][c]);
                v.x = v.x / (1.f + __expf(-v.x));
                v.y = v.y / (1.f + __expf(-v.y));
                reinterpret_cast<float2*>(v4)[c] = v;
            }
            size_t o = (size_t)((n*RR + h)*RR + (wbase + 64*q))*OUTD + o0;
            *reinterpret_cast<float4*>(&out[o])     = v4[0];
            *reinterpret_cast<float4*>(&out[o + 4]) = v4[1];
        }
    }
}

// ---------------- launch ----------------------------------------------------
extern "C" void kernel_launch(void* const* d_in, const int* in_sizes, int n_in,
                              void* d_out, int out_size) {
    const float* x   = (const float*)d_in[0];
    const float* w0  = (const float*)d_in[1];
    const float* w1  = (const float*)d_in[2];
    const float* rsw = (const float*)d_in[3];
    const float* rsb = (const float*)d_in[4];
    float* out = (float*)d_out;

    cudaFuncSetAttribute(k1_fwd_w, cudaFuncAttributeMaxDynamicSharedMemorySize, 65536);
    cudaFuncSetAttribute(k5_inv_w, cudaFuncAttributeMaxDynamicSharedMemorySize, RR*XPAD*4);

    k_init_tw<<<1, 256>>>();
    k1_fwd_w<<<NB*RR, 256, 65536>>>(x);
    k2_fwd_h<<<NB*MD*2, 256>>>();
    k3_mix<<<KXN*MD, 256>>>(w0, w1);
    k4_inv_h<<<NB*MD*2, 256>>>();
    k5_inv_w<<<NB*RR, 256, RR*XPAD*4>>>(x, rsw, rsb, out);
}

// round 14
// speedup vs baseline: 1.2062x; 1.0368x over previous
#include <cuda_runtime.h>
#include <cuda_fp16.h>

#define NB   8
#define RR   256
#define IND  64
#define OUTD 64
#define MD   32
#define KXN  64

typedef unsigned long long ull;

// ---------------- scratch (device globals; no allocations allowed) ----------
__device__ __half g_XwRh[NB*MD*RR*IND];   // [n][ky][h][i]  forward w-DFT (fp16)
__device__ __half g_XwIh[NB*MD*RR*IND];
__device__ float g_XmR[NB*MD*KXN*IND];    // [ky][kx][n][i] forward modes
__device__ float g_XmI[NB*MD*KXN*IND];
__device__ float g_OmR[NB*MD*KXN*OUTD];   // [n][ky][kx][o] mixed modes
__device__ float g_OmI[NB*MD*KXN*OUTD];
__device__ __half g_Y1Rh[NB*RR*MD*OUTD];  // [n][h][ky][o]  inverse h-DFT (fp16)
__device__ __half g_Y1Ih[NB*RR*MD*OUTD];
__device__ float4 g_tw4p[256];            // (c, c,  s,  s)
__device__ float4 g_tw4n[256];            // (c, c, -s, -s)

// ---------------- packed f32x2 helpers --------------------------------------
__device__ __forceinline__ void fma2(ull &d, ull a, ull b) {
    asm("fma.rn.f32x2 %0, %1, %2, %0;" : "+l"(d) : "l"(a), "l"(b));
}
__device__ __forceinline__ ull splat2(float x) {
    ull r; asm("mov.b64 %0, {%1, %1};" : "=l"(r) : "f"(x)); return r;
}
__device__ __forceinline__ ull pack2(float x, float y) {
    ull r; asm("mov.b64 %0, {%1, %2};" : "=l"(r) : "f"(x), "f"(y)); return r;
}
__device__ __forceinline__ ull mul2(ull a, ull b) {
    ull r; asm("mul.rn.f32x2 %0, %1, %2;" : "=l"(r) : "l"(a), "l"(b)); return r;
}
__device__ __forceinline__ ull add2(ull a, ull b) {
    ull r; asm("add.rn.f32x2 %0, %1, %2;" : "=l"(r) : "l"(a), "l"(b)); return r;
}
__device__ __forceinline__ ull sub2(ull a, ull b, ull negone) {   // a - b
    ull r; asm("fma.rn.f32x2 %0, %1, %2, %3;" : "=l"(r) : "l"(b), "l"(negone), "l"(a)); return r;
}
__device__ __forceinline__ ull neg2(ull a, ull negone) {
    ull r; asm("mul.rn.f32x2 %0, %1, %2;" : "=l"(r) : "l"(a), "l"(negone)); return r;
}
__device__ __forceinline__ float2 unpk(ull v) {
    float2 r; asm("mov.b64 {%0, %1}, %2;" : "=f"(r.x), "=f"(r.y) : "l"(v)); return r;
}
// ---------------- fp16 pack/unpack helpers ----------------------------------
__device__ __forceinline__ unsigned f22h(float a, float b) {
    __half2 h = __floats2half2_rn(a, b);
    return *reinterpret_cast<unsigned*>(&h);
}
__device__ __forceinline__ ulonglong2 h4f(uint2 u) {            // 4 halves -> 2 packed f32x2
    __half2 ha = *reinterpret_cast<__half2*>(&u.x);
    __half2 hb = *reinterpret_cast<__half2*>(&u.y);
    float2 fa = __half22float2(ha), fb = __half22float2(hb);
    return make_ulonglong2(pack2(fa.x, fa.y), pack2(fb.x, fb.y));
}
__device__ __forceinline__ void h8store(float* dst, uint4 u) {  // 8 halves -> smem f32
    __half2* hp = reinterpret_cast<__half2*>(&u);
    float2 f0 = __half22float2(hp[0]), f1 = __half22float2(hp[1]);
    float2 f2 = __half22float2(hp[2]), f3 = __half22float2(hp[3]);
    *reinterpret_cast<float4*>(dst)     = make_float4(f0.x, f0.y, f1.x, f1.y);
    *reinterpret_cast<float4*>(dst + 4) = make_float4(f2.x, f2.y, f3.x, f3.y);
}

__global__ void k_init_tw() {
    int k = threadIdx.x;
    double a = 6.283185307179586476925286766559 * (double)k / 256.0;
    float c = (float)cos(a), s = (float)sin(a);
    g_tw4p[k] = make_float4(c, c,  s,  s);
    g_tw4n[k] = make_float4(c, c, -s, -s);
}

// ---------------- K1: forward DFT along w (radix-8, 256 thr, 2 ky/thread) ---
// Planes: 0:U0 1:U4 2:U1R 3:U1I 4:U2R 5:U2I 6:U3R 7:U3I, each [32 w0][64 i].
// warp k handles class k = ky mod 8 (slots 2k,2k+1 -> ky = k, k+8; +16 pair same class).
__global__ __launch_bounds__(256) void k1_fwd_w(const float* __restrict__ x) {
    extern __shared__ __align__(16) float us[];       // 8 x 2048 floats = 64KB
    __shared__ __align__(16) float4 twp[256], twn[256];
    const int t = threadIdx.x;
    twp[t] = g_tw4p[t]; twn[t] = g_tw4n[t];
    const int b = blockIdx.x, n = b >> 8, h = b & 255;
    const float* xb = x + (size_t)(n*RR + h)*RR*IND;
    const ull NEG1 = splat2(-1.f);
    const ull RSQ2 = splat2(0.70710678118654752440f);
#pragma unroll
    for (int rr = 0; rr < 2; rr++) {                  // 512 loader roles
        const int role = t + 256*rr;
        const int w0 = role >> 4, iq = (role & 15) * 4;
        const float* p = xb + w0*IND + iq;
        ulonglong2 A0 = *reinterpret_cast<const ulonglong2*>(p);
        ulonglong2 A1 = *reinterpret_cast<const ulonglong2*>(p + 32*IND);
        ulonglong2 A2 = *reinterpret_cast<const ulonglong2*>(p + 64*IND);
        ulonglong2 A3 = *reinterpret_cast<const ulonglong2*>(p + 96*IND);
        ulonglong2 A4 = *reinterpret_cast<const ulonglong2*>(p + 128*IND);
        ulonglong2 A5 = *reinterpret_cast<const ulonglong2*>(p + 160*IND);
        ulonglong2 A6 = *reinterpret_cast<const ulonglong2*>(p + 192*IND);
        ulonglong2 A7 = *reinterpret_cast<const ulonglong2*>(p + 224*IND);
        const int rb = w0*64 + iq;
#pragma unroll
        for (int l = 0; l < 2; l++) {
            ull a0 = l ? A0.y : A0.x, a1 = l ? A1.y : A1.x;
            ull a2 = l ? A2.y : A2.x, a3 = l ? A3.y : A3.x;
            ull a4 = l ? A4.y : A4.x, a5 = l ? A5.y : A5.x;
            ull a6 = l ? A6.y : A6.x, a7 = l ? A7.y : A7.x;
            ull s0 = add2(a0, a4), s1 = add2(a1, a5);
            ull s2 = add2(a2, a6), s3 = add2(a3, a7);
            ull d0 = sub2(a0, a4, NEG1), d1 = sub2(a1, a5, NEG1);
            ull d2 = sub2(a2, a6, NEG1), d3 = sub2(a3, a7, NEG1);
            ull e  = add2(s0, s2), f  = add2(s1, s3);
            ull g  = sub2(s0, s2, NEG1), hh = sub2(s1, s3, NEG1);
            ull m  = mul2(sub2(d1, d3, NEG1), RSQ2);
            ull pp = mul2(add2(d1, d3), RSQ2);
            const int off = rb + 2*l;
            *reinterpret_cast<ull*>(&us[0*2048 + off]) = add2(e, f);                 // U0
            *reinterpret_cast<ull*>(&us[1*2048 + off]) = sub2(e, f, NEG1);           // U4
            *reinterpret_cast<ull*>(&us[2*2048 + off]) = add2(d0, m);                // U1R
            *reinterpret_cast<ull*>(&us[3*2048 + off]) = neg2(add2(d2, pp), NEG1);   // U1I
            *reinterpret_cast<ull*>(&us[4*2048 + off]) = g;                          // U2R
            *reinterpret_cast<ull*>(&us[5*2048 + off]) = neg2(hh, NEG1);             // U2I
            *reinterpret_cast<ull*>(&us[6*2048 + off]) = sub2(d0, m, NEG1);          // U3R
            *reinterpret_cast<ull*>(&us[7*2048 + off]) = sub2(d2, pp, NEG1);         // U3I
        }
    }
    __syncthreads();

    const int i0 = (t & 15) * 4;
    const int slot = t >> 4;
    const int cls = slot >> 1;                        // 0..7, warp-uniform
    const int ky_a = cls + 8*(slot & 1);
    const int ky_b = ky_a + 16;
    ull aR[2][2] = {{0,0},{0,0}}, aI[2][2] = {{0,0},{0,0}};
    int pa = 0, pb = 0;
    const float sc = 1.f/256.f;
    float iscl = sc;

    if (cls == 0 || cls == 4) {                       // real classes
        const float* Up = us + (cls == 0 ? 0 : 2048);
        for (int w0 = 0; w0 < 32; w0++) {
            ulonglong2 U = *reinterpret_cast<const ulonglong2*>(&Up[w0*64 + i0]);
            ulonglong2 ta = *reinterpret_cast<const ulonglong2*>(&twn[pa]);
            fma2(aR[0][0], ta.x, U.x); fma2(aR[0][1], ta.x, U.y);
            fma2(aI[0][0], ta.y, U.x); fma2(aI[0][1], ta.y, U.y);
            ulonglong2 tb = *reinterpret_cast<const ulonglong2*>(&twn[pb]);
            fma2(aR[1][0], tb.x, U.x); fma2(aR[1][1], tb.x, U.y);
            fma2(aI[1][0], tb.y, U.x); fma2(aI[1][1], tb.y, U.y);
            pa = (pa + ky_a) & 255; pb = (pb + ky_b) & 255;
        }
    } else if (cls < 4) {                             // complex classes 1,2,3
        const float* pRb = us + 2048 * (2*cls);
        const float* pIb = pRb + 2048;
        for (int w0 = 0; w0 < 32; w0++) {
            ulonglong2 UR = *reinterpret_cast<const ulonglong2*>(&pRb[w0*64 + i0]);
            ulonglong2 UI = *reinterpret_cast<const ulonglong2*>(&pIb[w0*64 + i0]);
            // e^{-i th}(UR + i UI): R = c UR + s UI ; I = c UI - s UR
            ulonglong2 tp4 = *reinterpret_cast<const ulonglong2*>(&twp[pa]);
            ulonglong2 tn4 = *reinterpret_cast<const ulonglong2*>(&twn[pa]);
            fma2(aR[0][0], tp4.x, UR.x); fma2(aR[0][0], tp4.y, UI.x);
            fma2(aR[0][1], tp4.x, UR.y); fma2(aR[0][1], tp4.y, UI.y);
            fma2(aI[0][0], tp4.x, UI.x); fma2(aI[0][0], tn4.y, UR.x);
            fma2(aI[0][1], tp4.x, UI.y); fma2(aI[0][1], tn4.y, UR.y);
            tp4 = *reinterpret_cast<const ulonglong2*>(&twp[pb]);
            tn4 = *reinterpret_cast<const ulonglong2*>(&twn[pb]);
            fma2(aR[1][0], tp4.x, UR.x); fma2(aR[1][0], tp4.y, UI.x);
            fma2(aR[1][1], tp4.x, UR.y); fma2(aR[1][1], tp4.y, UI.y);
            fma2(aI[1][0], tp4.x, UI.x); fma2(aI[1][0], tn4.y, UR.x);
            fma2(aI[1][1], tp4.x, UI.y); fma2(aI[1][1], tn4.y, UR.y);
            pa = (pa + ky_a) & 255; pb = (pb + ky_b) & 255;
        }
    } else {                                          // conj classes 5,6,7 -> planes 3,2,1
        const int cc = 8 - cls;
        const float* pRb = us + 2048 * (2*cc);
        const float* pIb = pRb + 2048;
        iscl = -sc;                                   // I = -(accumulated)
        for (int w0 = 0; w0 < 32; w0++) {
            ulonglong2 UR = *reinterpret_cast<const ulonglong2*>(&pRb[w0*64 + i0]);
            ulonglong2 UI = *reinterpret_cast<const ulonglong2*>(&pIb[w0*64 + i0]);
            // e^{-i th}(UR - i UI): R = c UR - s UI ; Iacc = c UI + s UR (negate at store)
            ulonglong2 tp4 = *reinterpret_cast<const ulonglong2*>(&twp[pa]);
            ulonglong2 tn4 = *reinterpret_cast<const ulonglong2*>(&twn[pa]);
            fma2(aR[0][0], tp4.x, UR.x); fma2(aR[0][0], tn4.y, UI.x);
            fma2(aR[0][1], tp4.x, UR.y); fma2(aR[0][1], tn4.y, UI.y);
            fma2(aI[0][0], tp4.x, UI.x); fma2(aI[0][0], tp4.y, UR.x);
            fma2(aI[0][1], tp4.x, UI.y); fma2(aI[0][1], tp4.y, UR.y);
            tp4 = *reinterpret_cast<const ulonglong2*>(&twp[pb]);
            tn4 = *reinterpret_cast<const ulonglong2*>(&twn[pb]);
            fma2(aR[1][0], tp4.x, UR.x); fma2(aR[1][0], tn4.y, UI.x);
            fma2(aR[1][1], tp4.x, UR.y); fma2(aR[1][1], tn4.y, UI.y);
            fma2(aI[1][0], tp4.x, UI.x); fma2(aI[1][0], tp4.y, UR.x);
            fma2(aI[1][1], tp4.x, UI.y); fma2(aI[1][1], tp4.y, UR.y);
            pa = (pa + ky_a) & 255; pb = (pb + ky_b) & 255;
        }
    }
#pragma unroll
    for (int j = 0; j < 2; j++) {
        const int ky = j ? ky_b : ky_a;
        size_t o = (size_t)((n*MD + ky)*RR + h)*IND + i0;
        float2 a0 = unpk(aR[j][0]), a1 = unpk(aR[j][1]);
        *reinterpret_cast<uint2*>(&g_XwRh[o]) =
            make_uint2(f22h(a0.x*sc, a0.y*sc), f22h(a1.x*sc, a1.y*sc));
        a0 = unpk(aI[j][0]); a1 = unpk(aI[j][1]);
        *reinterpret_cast<uint2*>(&g_XwIh[o]) =
            make_uint2(f22h(a0.x*iscl, a0.y*iscl), f22h(a1.x*iscl, a1.y*iscl));
    }
}

// ---------------- K2: forward h-DFT, radix-4, register-prefetch pipeline ----
__global__ __launch_bounds__(256, 3) void k2_fwd_h() {
    __shared__ __align__(16) float Vs[8*16*64];       // 8 planes x [16 h0][64 i] = 32KB
    __shared__ __align__(16) float4 twp[256], twn[256];
    const int t = threadIdx.x;
    twp[t] = g_tw4p[t]; twn[t] = g_tw4n[t];
    const int b = blockIdx.x, half = b & 1, ky = (b >> 1) & 31, n = b >> 6;
    const __half* baseR = g_XwRh + (size_t)(n*MD + ky)*RR*IND;
    const __half* baseI = g_XwIh + (size_t)(n*MD + ky)*RR*IND;
    const int i0 = (t & 15) * 4;
    const int g = t >> 4, c = g & 3, mseg = g >> 2;
    const int kxl0 = 8*mseg + c;                       // slots of class c
    const int kap0 = half ? (224 + kxl0) : kxl0;
    const int kap1 = kap0 + 4;
    const int h0ld = t >> 4, iq = (t & 15) * 4;        // loader role (1 per thread)
    const ull NEG1 = splat2(-1.f);
    ull aR[2][2] = {{0,0},{0,0}}, aI[2][2] = {{0,0},{0,0}};
    int p0 = 0, p1 = 0;

    uint2 R0u, R1u, R2u, R3u, I0u, I1u, I2u, I3u;
    {
        const __half* pR = baseR + h0ld*IND + iq;
        const __half* pI = baseI + h0ld*IND + iq;
        R0u = *reinterpret_cast<const uint2*>(pR);
        R1u = *reinterpret_cast<const uint2*>(pR + 64*IND);
        R2u = *reinterpret_cast<const uint2*>(pR + 128*IND);
        R3u = *reinterpret_cast<const uint2*>(pR + 192*IND);
        I0u = *reinterpret_cast<const uint2*>(pI);
        I1u = *reinterpret_cast<const uint2*>(pI + 64*IND);
        I2u = *reinterpret_cast<const uint2*>(pI + 128*IND);
        I3u = *reinterpret_cast<const uint2*>(pI + 192*IND);
    }

    for (int hc = 0; hc < 64; hc += 16) {
        __syncthreads();
        {   // convert + butterfly registers -> Vs
            ulonglong2 R0 = h4f(R0u), R1 = h4f(R1u), R2 = h4f(R2u), R3 = h4f(R3u);
            ulonglong2 I0 = h4f(I0u), I1 = h4f(I1u), I2 = h4f(I2u), I3 = h4f(I3u);
            ull sRx = add2(R0.x, R2.x), sRy = add2(R0.y, R2.y);
            ull dRx = sub2(R0.x, R2.x, NEG1), dRy = sub2(R0.y, R2.y, NEG1);
            ull uRx = add2(R1.x, R3.x), uRy = add2(R1.y, R3.y);
            ull eRx = sub2(R1.x, R3.x, NEG1), eRy = sub2(R1.y, R3.y, NEG1);
            ull sIx = add2(I0.x, I2.x), sIy = add2(I0.y, I2.y);
            ull dIx = sub2(I0.x, I2.x, NEG1), dIy = sub2(I0.y, I2.y, NEG1);
            ull uIx = add2(I1.x, I3.x), uIy = add2(I1.y, I3.y);
            ull eIx = sub2(I1.x, I3.x, NEG1), eIy = sub2(I1.y, I3.y, NEG1);
            const int rb = h0ld*64 + iq;
            ulonglong2* vp;
            vp = reinterpret_cast<ulonglong2*>(&Vs[0*1024 + rb]);
            *vp = make_ulonglong2(add2(sRx, uRx), add2(sRy, uRy));
            vp = reinterpret_cast<ulonglong2*>(&Vs[1*1024 + rb]);
            *vp = make_ulonglong2(add2(sIx, uIx), add2(sIy, uIy));
            vp = reinterpret_cast<ulonglong2*>(&Vs[2*1024 + rb]);
            *vp = make_ulonglong2(add2(dRx, eIx), add2(dRy, eIy));
            vp = reinterpret_cast<ulonglong2*>(&Vs[3*1024 + rb]);
            *vp = make_ulonglong2(sub2(dIx, eRx, NEG1), sub2(dIy, eRy, NEG1));
            vp = reinterpret_cast<ulonglong2*>(&Vs[4*1024 + rb]);
            *vp = make_ulonglong2(sub2(sRx, uRx, NEG1), sub2(sRy, uRy, NEG1));
            vp = reinterpret_cast<ulonglong2*>(&Vs[5*1024 + rb]);
            *vp = make_ulonglong2(sub2(sIx, uIx, NEG1), sub2(sIy, uIy, NEG1));
            vp = reinterpret_cast<ulonglong2*>(&Vs[6*1024 + rb]);
            *vp = make_ulonglong2(sub2(dRx, eIx, NEG1), sub2(dRy, eIy, NEG1));
            vp = reinterpret_cast<ulonglong2*>(&Vs[7*1024 + rb]);
            *vp = make_ulonglong2(add2(dIx, eRx), add2(dIy, eRy));
        }
        __syncthreads();
        if (hc < 48) {
            const __half* pR = baseR + (hc + 16 + h0ld)*IND + iq;
            const __half* pI = baseI + (hc + 16 + h0ld)*IND + iq;
            R0u = *reinterpret_cast<const uint2*>(pR);
            R1u = *reinterpret_cast<const uint2*>(pR + 64*IND);
            R2u = *reinterpret_cast<const uint2*>(pR + 128*IND);
            R3u = *reinterpret_cast<const uint2*>(pR + 192*IND);
            I0u = *reinterpret_cast<const uint2*>(pI);
            I1u = *reinterpret_cast<const uint2*>(pI + 64*IND);
            I2u = *reinterpret_cast<const uint2*>(pI + 128*IND);
            I3u = *reinterpret_cast<const uint2*>(pI + 192*IND);
        }
        const float* VRb = &Vs[(c*2 + 0)*1024];
        const float* VIb = &Vs[(c*2 + 1)*1024];
        for (int h0l = 0; h0l < 16; h0l++) {
            ulonglong2 VR = *reinterpret_cast<const ulonglong2*>(&VRb[h0l*64 + i0]);
            ulonglong2 VI = *reinterpret_cast<const ulonglong2*>(&VIb[h0l*64 + i0]);
            ulonglong2 tp4 = *reinterpret_cast<const ulonglong2*>(&twp[p0]);
            ulonglong2 tn4 = *reinterpret_cast<const ulonglong2*>(&twn[p0]);
            fma2(aR[0][0], tp4.x, VR.x); fma2(aR[0][0], tp4.y, VI.x);
            fma2(aR[0][1], tp4.x, VR.y); fma2(aR[0][1], tp4.y, VI.y);
            fma2(aI[0][0], tp4.x, VI.x); fma2(aI[0][0], tn4.y, VR.x);
            fma2(aI[0][1], tp4.x, VI.y); fma2(aI[0][1], tn4.y, VR.y);
            p0 = (p0 + kap0) & 255;
            tp4 = *reinterpret_cast<const ulonglong2*>(&twp[p1]);
            tn4 = *reinterpret_cast<const ulonglong2*>(&twn[p1]);
            fma2(aR[1][0], tp4.x, VR.x); fma2(aR[1][0], tp4.y, VI.x);
            fma2(aR[1][1], tp4.x, VR.y); fma2(aR[1][1], tp4.y, VI.y);
            fma2(aI[1][0], tp4.x, VI.x); fma2(aI[1][0], tn4.y, VR.x);
            fma2(aI[1][1], tp4.x, VI.y); fma2(aI[1][1], tn4.y, VR.y);
            p1 = (p1 + kap1) & 255;
        }
    }
#pragma unroll
    for (int j = 0; j < 2; j++) {
        int kxs = half*32 + kxl0 + 4*j;
        size_t o = (size_t)((ky*KXN + kxs)*NB + n)*IND + i0;
        float2 a0 = unpk(aR[j][0]), a1 = unpk(aR[j][1]);
        *reinterpret_cast<float4*>(&g_XmR[o]) = make_float4(a0.x, a0.y, a1.x, a1.y);
        a0 = unpk(aI[j][0]); a1 = unpk(aI[j][1]);
        *reinterpret_cast<float4*>(&g_XmI[o]) = make_float4(a0.x, a0.y, a1.x, a1.y);
    }
}

// ---------------- K3: per-mode complex channel mix (8x64x64) ----------------
__global__ __launch_bounds__(256) void k3_mix(const float* __restrict__ w0,
                                              const float* __restrict__ w1) {
    __shared__ float Xs2[NB*IND*2];                   // interleaved (R,I)
    const int t = threadIdx.x, b = blockIdx.x;
    const int kx = b >> 5, ky = b & 31;
    size_t xb = (size_t)(ky*KXN + kx)*NB*IND;
#pragma unroll
    for (int it = 0; it < 2; it++) {
        int idx = t + 256*it;
        Xs2[2*idx]     = g_XmR[xb + idx];
        Xs2[2*idx + 1] = g_XmI[xb + idx];
    }
    __syncthreads();
    const float4* wp4 = reinterpret_cast<const float4*>(
        (kx < MD) ? (w0 + (size_t)(kx*MD + ky)*IND*OUTD*2)
                  : (w1 + (size_t)((kx - MD)*MD + ky)*IND*OUTD*2));
    const int o2 = t & 31, n = t >> 5;                // o0 = 2*o2, one n per thread
    float r0 = 0.f, i0 = 0.f, r1 = 0.f, i1 = 0.f;
#pragma unroll 8
    for (int i = 0; i < IND; i++) {
        float4 w = wp4[i*32 + o2];                    // (wR0,wI0,wR1,wI1)
        float2 xv = *reinterpret_cast<const float2*>(&Xs2[(n*IND + i)*2]);
        r0 = fmaf(xv.x, w.x, fmaf(-xv.y, w.y, r0));
        i0 = fmaf(xv.x, w.y, fmaf( xv.y, w.x, i0));
        r1 = fmaf(xv.x, w.z, fmaf(-xv.y, w.w, r1));
        i1 = fmaf(xv.x, w.w, fmaf( xv.y, w.z, i1));
    }
    size_t gg = (size_t)((n*MD + ky)*KXN + kx)*OUTD + 2*o2;
    *reinterpret_cast<float2*>(&g_OmR[gg]) = make_float2(r0, r1);
    *reinterpret_cast<float2*>(&g_OmI[gg]) = make_float2(i0, i1);
}

// ---------------- K4: inverse h-DFT, radix-4 on output ----------------------
#define K4STEP(CR, CI) { \
    ulonglong2 R0 = *reinterpret_cast<const ulonglong2*>(&sR[kxo]); \
    ulonglong2 R1 = *reinterpret_cast<const ulonglong2*>(&sR[kxo + 4]); \
    ulonglong2 I0 = *reinterpret_cast<const ulonglong2*>(&sI[kxo]); \
    ulonglong2 I1 = *reinterpret_cast<const ulonglong2*>(&sI[kxo + 4]); \
    ulonglong2 tp4 = *reinterpret_cast<const ulonglong2*>(&twp[p]); \
    ulonglong2 tn4 = *reinterpret_cast<const ulonglong2*>(&twn[p]); \
    fma2(CR[0], tn4.x, R0.x); fma2(CR[0], tn4.y, I0.x); \
    fma2(CR[1], tn4.x, R0.y); fma2(CR[1], tn4.y, I0.y); \
    fma2(CR[2], tn4.x, R1.x); fma2(CR[2], tn4.y, I1.x); \
    fma2(CR[3], tn4.x, R1.y); fma2(CR[3], tn4.y, I1.y); \
    fma2(CI[0], tp4.x, I0.x); fma2(CI[0], tp4.y, R0.x); \
    fma2(CI[1], tp4.x, I0.y); fma2(CI[1], tp4.y, R0.y); \
    fma2(CI[2], tp4.x, I1.x); fma2(CI[2], tp4.y, R1.x); \
    fma2(CI[3], tp4.x, I1.y); fma2(CI[3], tp4.y, R1.y); \
    p = (p + h0) & 255; kxo += OUTD; }

__global__ __launch_bounds__(256) void k4_inv_h() {
    __shared__ __align__(16) float sR[KXN*OUTD], sI[KXN*OUTD];
    __shared__ __align__(16) float4 twp[256], twn[256];
    const int t = threadIdx.x;
    twp[t] = g_tw4p[t]; twn[t] = g_tw4n[t];
    const int b = blockIdx.x, grp = b & 1, ky = (b >> 1) & 31, n = b >> 6;
    const float4* pR = reinterpret_cast<const float4*>(g_OmR + (size_t)(n*MD + ky)*KXN*OUTD);
    const float4* pI = reinterpret_cast<const float4*>(g_OmI + (size_t)(n*MD + ky)*KXN*OUTD);
#pragma unroll
    for (int it = 0; it < 4; it++) {
        reinterpret_cast<float4*>(sR)[t + 256*it] = pR[t + 256*it];
        reinterpret_cast<float4*>(sI)[t + 256*it] = pI[t + 256*it];
    }
    __syncthreads();
    const int o0 = (t & 7) * 8, h0 = grp*32 + (t >> 3);
    ull C0R[4], C0I[4], C1R[4], C1I[4], C2R[4], C2I[4], C3R[4], C3I[4];
#pragma unroll
    for (int j = 0; j < 4; j++) {
        C0R[j]=C0I[j]=C1R[j]=C1I[j]=0ull;
        C2R[j]=C2I[j]=C3R[j]=C3I[j]=0ull;
    }
#pragma unroll 1
    for (int kh = 0; kh < 2; kh++) {
        int p = kh ? ((224*h0) & 255) : 0;
        int kxo = (kh*32)*OUTD + o0;
#pragma unroll
        for (int kk = 0; kk < 32; kk += 4) {
            K4STEP(C0R, C0I)
            K4STEP(C1R, C1I)
            K4STEP(C2R, C2I)
            K4STEP(C3R, C3I)
        }
    }
    const ull NEG1 = splat2(-1.f);
    const ull FAC2 = splat2((ky == 0 ? 1.f : 2.f) * (1.f/256.f));
    const size_t obase = (size_t)((n*RR + h0)*MD + ky)*OUTD + o0;
#pragma unroll
    for (int j = 0; j < 4; j++) {
        ull ER = add2(C0R[j], C2R[j]), EI = add2(C0I[j], C2I[j]);
        ull FR = sub2(C0R[j], C2R[j], NEG1), FI = sub2(C0I[j], C2I[j], NEG1);
        ull GR = add2(C1R[j], C3R[j]), GI = add2(C1I[j], C3I[j]);
        ull HR = sub2(C1R[j], C3R[j], NEG1), HI = sub2(C1I[j], C3I[j], NEG1);
        ull YR[4] = { add2(ER, GR), sub2(FR, HI, NEG1), sub2(ER, GR, NEG1), add2(FR, HI) };
        ull YI[4] = { add2(EI, GI), add2(FI, HR), sub2(EI, GI, NEG1), sub2(FI, HR, NEG1) };
#pragma unroll
        for (int q = 0; q < 4; q++) {
            size_t o = obase + (size_t)(64*q)*MD*OUTD + 2*j;
            float2 vr = unpk(mul2(YR[q], FAC2));
            float2 vi = unpk(mul2(YI[q], FAC2));
            *reinterpret_cast<unsigned*>(&g_Y1Rh[o]) = f22h(vr.x, vr.y);
            *reinterpret_cast<unsigned*>(&g_Y1Ih[o]) = f22h(vi.x, vi.y);
        }
    }
}

// ---------------- K5: radix-4 inverse w synthesis + residual + SiLU ---------
#define XPAD 68
__global__ __launch_bounds__(256) void k5_inv_w(const float* __restrict__ x,
                                                const float* __restrict__ res_w,
                                                const float* __restrict__ res_b,
                                                float* __restrict__ out) {
    extern __shared__ __align__(16) float xs[];       // [256][XPAD]
    __shared__ __align__(16) float YsR[MD*OUTD], YsI[MD*OUTD];
    __shared__ __align__(16) float rws[IND*OUTD];
    __shared__ __align__(16) float4 twp[256], twn[256];
    __shared__ __align__(16) float rbs[64];
    const int t = threadIdx.x, b = blockIdx.x, n = b >> 8, h = b & 255;
    twp[t] = g_tw4p[t];
    twn[t] = g_tw4n[t];
    const float4* xp = reinterpret_cast<const float4*>(x + (size_t)(n*RR + h)*RR*IND);
#pragma unroll
    for (int it = 0; it < 16; it++) {
        int j = t + 256*it;
        float4 v = xp[j];
        int w = j >> 4, c = j & 15;
        *reinterpret_cast<float4*>(&xs[w*XPAD + c*4]) = v;
    }
    {   // Y1 fp16 -> fp32 smem (one uint4 = 8 halves per thread per plane)
        const uint4* yRu = reinterpret_cast<const uint4*>(g_Y1Rh + (size_t)(n*RR + h)*MD*OUTD);
        const uint4* yIu = reinterpret_cast<const uint4*>(g_Y1Ih + (size_t)(n*RR + h)*MD*OUTD);
        h8store(&YsR[t*8], yRu[t]);
        h8store(&YsI[t*8], yIu[t]);
    }
#pragma unroll
    for (int it = 0; it < 4; it++)
        reinterpret_cast<float4*>(rws)[t + 256*it] =
            reinterpret_cast<const float4*>(res_w)[t + 256*it];
    if (t < 64) rbs[t] = res_b[t];
    __syncthreads();

    const int og = t & 7, o0 = og*8, pr = t >> 3;     // w0a = pr, w0b = pr + 32
    const ull NEG1 = splat2(-1.f);
    ull C0R[2][4], C2R[2][4], C1R[2][4], C1I[2][4], C3R[2][4], C3I[2][4];
#pragma unroll
    for (int s = 0; s < 2; s++)
#pragma unroll
        for (int j = 0; j < 4; j++) {
            C0R[s][j]=C2R[s][j]=C1R[s][j]=C1I[s][j]=C3R[s][j]=C3I[s][j]=0ull;
        }
    int pa = 0, pb = 0;
    const int stpa = pr, stpb = pr + 32;
#pragma unroll
    for (int kb = 0; kb < 8; kb++) {
        // c = 0
        {
            const int ky = 4*kb;
            ulonglong2 yr0 = *reinterpret_cast<const ulonglong2*>(&YsR[ky*OUTD + o0]);
            ulonglong2 yr1 = *reinterpret_cast<const ulonglong2*>(&YsR[ky*OUTD + o0 + 4]);
            ulonglong2 yi0 = *reinterpret_cast<const ulonglong2*>(&YsI[ky*OUTD + o0]);
            ulonglong2 yi1 = *reinterpret_cast<const ulonglong2*>(&YsI[ky*OUTD + o0 + 4]);
            ulonglong2 tn4 = *reinterpret_cast<const ulonglong2*>(&twn[pa]);
            fma2(C0R[0][0], tn4.x, yr0.x); fma2(C0R[0][0], tn4.y, yi0.x);
            fma2(C0R[0][1], tn4.x, yr0.y); fma2(C0R[0][1], tn4.y, yi0.y);
            fma2(C0R[0][2], tn4.x, yr1.x); fma2(C0R[0][2], tn4.y, yi1.x);
            fma2(C0R[0][3], tn4.x, yr1.y); fma2(C0R[0][3], tn4.y, yi1.y);
            tn4 = *reinterpret_cast<const ulonglong2*>(&twn[pb]);
            fma2(C0R[1][0], tn4.x, yr0.x); fma2(C0R[1][0], tn4.y, yi0.x);
            fma2(C0R[1][1], tn4.x, yr0.y); fma2(C0R[1][1], tn4.y, yi0.y);
            fma2(C0R[1][2], tn4.x, yr1.x); fma2(C0R[1][2], tn4.y, yi1.x);
            fma2(C0R[1][3], tn4.x, yr1.y); fma2(C0R[1][3], tn4.y, yi1.y);
            pa = (pa + stpa) & 255; pb = (pb + stpb) & 255;
        }
        // c = 1
        {
            const int ky = 4*kb + 1;
            ulonglong2 yr0 = *reinterpret_cast<const ulonglong2*>(&YsR[ky*OUTD + o0]);
            ulonglong2 yr1 = *reinterpret_cast<const ulonglong2*>(&YsR[ky*OUTD + o0 + 4]);
            ulonglong2 yi0 = *reinterpret_cast<const ulonglong2*>(&YsI[ky*OUTD + o0]);
            ulonglong2 yi1 = *reinterpret_cast<const ulonglong2*>(&YsI[ky*OUTD + o0 + 4]);
            ulonglong2 tn4 = *reinterpret_cast<const ulonglong2*>(&twn[pa]);
            ulonglong2 tp4 = *reinterpret_cast<const ulonglong2*>(&twp[pa]);
            fma2(C1R[0][0], tn4.x, yr0.x); fma2(C1R[0][0], tn4.y, yi0.x);
            fma2(C1R[0][1], tn4.x, yr0.y); fma2(C1R[0][1], tn4.y, yi0.y);
            fma2(C1R[0][2], tn4.x, yr1.x); fma2(C1R[0][2], tn4.y, yi1.x);
            fma2(C1R[0][3], tn4.x, yr1.y); fma2(C1R[0][3], tn4.y, yi1.y);
            fma2(C1I[0][0], tp4.x, yi0.x); fma2(C1I[0][0], tp4.y, yr0.x);
            fma2(C1I[0][1], tp4.x, yi0.y); fma2(C1I[0][1], tp4.y, yr0.y);
            fma2(C1I[0][2], tp4.x, yi1.x); fma2(C1I[0][2], tp4.y, yr1.x);
            fma2(C1I[0][3], tp4.x, yi1.y); fma2(C1I[0][3], tp4.y, yr1.y);
            tn4 = *reinterpret_cast<const ulonglong2*>(&twn[pb]);
            tp4 = *reinterpret_cast<const ulonglong2*>(&twp[pb]);
            fma2(C1R[1][0], tn4.x, yr0.x); fma2(C1R[1][0], tn4.y, yi0.x);
            fma2(C1R[1][1], tn4.x, yr0.y); fma2(C1R[1][1], tn4.y, yi0.y);
            fma2(C1R[1][2], tn4.x, yr1.x); fma2(C1R[1][2], tn4.y, yi1.x);
            fma2(C1R[1][3], tn4.x, yr1.y); fma2(C1R[1][3], tn4.y, yi1.y);
            fma2(C1I[1][0], tp4.x, yi0.x); fma2(C1I[1][0], tp4.y, yr0.x);
            fma2(C1I[1][1], tp4.x, yi0.y); fma2(C1I[1][1], tp4.y, yr0.y);
            fma2(C1I[1][2], tp4.x, yi1.x); fma2(C1I[1][2], tp4.y, yr1.x);
            fma2(C1I[1][3], tp4.x, yi1.y); fma2(C1I[1][3], tp4.y, yr1.y);
            pa = (pa + stpa) & 255; pb = (pb + stpb) & 255;
        }
        // c = 2
        {
            const int ky = 4*kb + 2;
            ulonglong2 yr0 = *reinterpret_cast<const ulonglong2*>(&YsR[ky*OUTD + o0]);
            ulonglong2 yr1 = *reinterpret_cast<const ulonglong2*>(&YsR[ky*OUTD + o0 + 4]);
            ulonglong2 yi0 = *reinterpret_cast<const ulonglong2*>(&YsI[ky*OUTD + o0]);
            ulonglong2 yi1 = *reinterpret_cast<const ulonglong2*>(&YsI[ky*OUTD + o0 + 4]);
            ulonglong2 tn4 = *reinterpret_cast<const ulonglong2*>(&twn[pa]);
            fma2(C2R[0][0], tn4.x, yr0.x); fma2(C2R[0][0], tn4.y, yi0.x);
            fma2(C2R[0][1], tn4.x, yr0.y); fma2(C2R[0][1], tn4.y, yi0.y);
            fma2(C2R[0][2], tn4.x, yr1.x); fma2(C2R[0][2], tn4.y, yi1.x);
            fma2(C2R[0][3], tn4.x, yr1.y); fma2(C2R[0][3], tn4.y, yi1.y);
            tn4 = *reinterpret_cast<const ulonglong2*>(&twn[pb]);
            fma2(C2R[1][0], tn4.x, yr0.x); fma2(C2R[1][0], tn4.y, yi0.x);
            fma2(C2R[1][1], tn4.x, yr0.y); fma2(C2R[1][1], tn4.y, yi0.y);
            fma2(C2R[1][2], tn4.x, yr1.x); fma2(C2R[1][2], tn4.y, yi1.x);
            fma2(C2R[1][3], tn4.x, yr1.y); fma2(C2R[1][3], tn4.y, yi1.y);
            pa = (pa + stpa) & 255; pb = (pb + stpb) & 255;
        }
        // c = 3
        {
            const int ky = 4*kb + 3;
            ulonglong2 yr0 = *reinterpret_cast<const ulonglong2*>(&YsR[ky*OUTD + o0]);
            ulonglong2 yr1 = *reinterpret_cast<const ulonglong2*>(&YsR[ky*OUTD + o0 + 4]);
            ulonglong2 yi0 = *reinterpret_cast<const ulonglong2*>(&YsI[ky*OUTD + o0]);
            ulonglong2 yi1 = *reinterpret_cast<const ulonglong2*>(&YsI[ky*OUTD + o0 + 4]);
            ulonglong2 tn4 = *reinterpret_cast<const ulonglong2*>(&twn[pa]);
            ulonglong2 tp4 = *reinterpret_cast<const ulonglong2*>(&twp[pa]);
            fma2(C3R[0][0], tn4.x, yr0.x); fma2(C3R[0][0], tn4.y, yi0.x);
            fma2(C3R[0][1], tn4.x, yr0.y); fma2(C3R[0][1], tn4.y, yi0.y);
            fma2(C3R[0][2], tn4.x, yr1.x); fma2(C3R[0][2], tn4.y, yi1.x);
            fma2(C3R[0][3], tn4.x, yr1.y); fma2(C3R[0][3], tn4.y, yi1.y);
            fma2(C3I[0][0], tp4.x, yi0.x); fma2(C3I[0][0], tp4.y, yr0.x);
            fma2(C3I[0][1], tp4.x, yi0.y); fma2(C3I[0][1], tp4.y, yr0.y);
            fma2(C3I[0][2], tp4.x, yi1.x); fma2(C3I[0][2], tp4.y, yr1.x);
            fma2(C3I[0][3], tp4.x, yi1.y); fma2(C3I[0][3], tp4.y, yr1.y);
            tn4 = *reinterpret_cast<const ulonglong2*>(&twn[pb]);
            tp4 = *reinterpret_cast<const ulonglong2*>(&twp[pb]);
            fma2(C3R[1][0], tn4.x, yr0.x); fma2(C3R[1][0], tn4.y, yi0.x);
            fma2(C3R[1][1], tn4.x, yr0.y); fma2(C3R[1][1], tn4.y, yi0.y);
            fma2(C3R[1][2], tn4.x, yr1.x); fma2(C3R[1][2], tn4.y, yi1.x);
            fma2(C3R[1][3], tn4.x, yr1.y); fma2(C3R[1][3], tn4.y, yi1.y);
            fma2(C3I[1][0], tp4.x, yi0.x); fma2(C3I[1][0], tp4.y, yr0.x);
            fma2(C3I[1][1], tp4.x, yi0.y); fma2(C3I[1][1], tp4.y, yr0.y);
            fma2(C3I[1][2], tp4.x, yi1.x); fma2(C3I[1][2], tp4.y, yr1.x);
            fma2(C3I[1][3], tp4.x, yi1.y); fma2(C3I[1][3], tp4.y, yr1.y);
            pa = (pa + stpa) & 255; pb = (pb + stpb) & 255;
        }
    }
    // ---- combine classes into 4 output rows + bias, both w0 ----
    ull ys[2][4][4];
    {
        ulonglong2 b01 = *reinterpret_cast<const ulonglong2*>(&rbs[o0]);
        ulonglong2 b23 = *reinterpret_cast<const ulonglong2*>(&rbs[o0 + 4]);
        ull bias[4] = {b01.x, b01.y, b23.x, b23.y};
#pragma unroll
        for (int s = 0; s < 2; s++)
#pragma unroll
            for (int j = 0; j < 4; j++) {
                ull e  = add2(C0R[s][j], C2R[s][j]);
                ull f  = sub2(C0R[s][j], C2R[s][j], NEG1);
                ull g  = add2(C1R[s][j], C3R[s][j]);
                ull hh = sub2(C3I[s][j], C1I[s][j], NEG1);
                ys[s][0][j] = add2(add2(e, g),  bias[j]);
                ys[s][2][j] = add2(sub2(e, g,  NEG1), bias[j]);
                ys[s][1][j] = add2(add2(f, hh), bias[j]);
                ys[s][3][j] = add2(sub2(f, hh, NEG1), bias[j]);
            }
    }
    // ---- residual GEMM into ys (2 i per step, vector x loads) ----
    for (int i = 0; i < IND; i += 2) {
        ulonglong2 rA01 = *reinterpret_cast<const ulonglong2*>(&rws[i*OUTD + o0]);
        ulonglong2 rA23 = *reinterpret_cast<const ulonglong2*>(&rws[i*OUTD + o0 + 4]);
        ulonglong2 rB01 = *reinterpret_cast<const ulonglong2*>(&rws[(i+1)*OUTD + o0]);
        ulonglong2 rB23 = *reinterpret_cast<const ulonglong2*>(&rws[(i+1)*OUTD + o0 + 4]);
#pragma unroll
        for (int s = 0; s < 2; s++) {
            const int wbase = pr + 32*s;
#pragma unroll
            for (int q = 0; q < 4; q++) {
                float2 xv = *reinterpret_cast<const float2*>(&xs[(wbase + 64*q)*XPAD + i]);
                ull sxA = splat2(xv.x), sxB = splat2(xv.y);
                fma2(ys[s][q][0], sxA, rA01.x); fma2(ys[s][q][1], sxA, rA01.y);
                fma2(ys[s][q][2], sxA, rA23.x); fma2(ys[s][q][3], sxA, rA23.y);
                fma2(ys[s][q][0], sxB, rB01.x); fma2(ys[s][q][1], sxB, rB01.y);
                fma2(ys[s][q][2], sxB, rB23.x); fma2(ys[s][q][3], sxB, rB23.y);
            }
        }
    }
    // ---- SiLU + store ----
#pragma unroll
    for (int s = 0; s < 2; s++) {
        const int wbase = pr + 32*s;
#pragma unroll
        for (int q = 0; q < 4; q++) {
            float4 v4[2];
#pragma unroll
            for (int c = 0; c < 4; c++) {
                float2 v = unpk(ys[s][q][c]);
                v.x = v.x / (1.f + __expf(-v.x));
                v.y = v.y / (1.f + __expf(-v.y));
                reinterpret_cast<float2*>(v4)[c] = v;
            }
            size_t o = (size_t)((n*RR + h)*RR + (wbase + 64*q))*OUTD + o0;
            *reinterpret_cast<float4*>(&out[o])     = v4[0];
            *reinterpret_cast<float4*>(&out[o + 4]) = v4[1];
        }
    }
}

// ---------------- launch ----------------------------------------------------
extern "C" void kernel_launch(void* const* d_in, const int* in_sizes, int n_in,
                              void* d_out, int out_size) {
    const float* x   = (const float*)d_in[0];
    const float* w0  = (const float*)d_in[1];
    const float* w1  = (const float*)d_in[2];
    const float* rsw = (const float*)d_in[3];
    const float* rsb = (const float*)d_in[4];
    float* out = (float*)d_out;

    cudaFuncSetAttribute(k1_fwd_w, cudaFuncAttributeMaxDynamicSharedMemorySize, 65536);
    cudaFuncSetAttribute(k5_inv_w, cudaFuncAttributeMaxDynamicSharedMemorySize, RR*XPAD*4);

    k_init_tw<<<1, 256>>>();
    k1_fwd_w<<<NB*RR, 256, 65536>>>(x);
    k2_fwd_h<<<NB*MD*2, 256>>>();
    k3_mix<<<KXN*MD, 256>>>(w0, w1);
    k4_inv_h<<<NB*MD*2, 256>>>();
    k5_inv_w<<<NB*RR, 256, RR*XPAD*4>>>(x, rsw, rsb, out);
}

// round 15
// speedup vs baseline: 1.2263x; 1.0167x over previous
#include <cuda_runtime.h>
#include <cuda_fp16.h>

#define NB   8
#define RR   256
#define IND  64
#define OUTD 64
#define MD   32
#define KXN  64

typedef unsigned long long ull;

// ---------------- scratch (device globals; no allocations allowed) ----------
__device__ __half g_XwRh[NB*MD*RR*IND];   // [n][ky][h][i]  forward w-DFT (fp16)
__device__ __half g_XwIh[NB*MD*RR*IND];
__device__ __half g_XmRh[NB*MD*KXN*IND];  // [ky][kx][n][i] forward modes (fp16)
__device__ __half g_XmIh[NB*MD*KXN*IND];
__device__ __half g_OmRh[NB*MD*KXN*OUTD]; // [n][ky][kx][o] mixed modes (fp16)
__device__ __half g_OmIh[NB*MD*KXN*OUTD];
__device__ __half g_Y1Rh[NB*RR*MD*OUTD];  // [n][h][ky][o]  inverse h-DFT (fp16)
__device__ __half g_Y1Ih[NB*RR*MD*OUTD];

// ---------------- packed f32x2 helpers --------------------------------------
__device__ __forceinline__ void fma2(ull &d, ull a, ull b) {
    asm("fma.rn.f32x2 %0, %1, %2, %0;" : "+l"(d) : "l"(a), "l"(b));
}
__device__ __forceinline__ ull splat2(float x) {
    ull r; asm("mov.b64 %0, {%1, %1};" : "=l"(r) : "f"(x)); return r;
}
__device__ __forceinline__ ull pack2(float x, float y) {
    ull r; asm("mov.b64 %0, {%1, %2};" : "=l"(r) : "f"(x), "f"(y)); return r;
}
__device__ __forceinline__ ull mul2(ull a, ull b) {
    ull r; asm("mul.rn.f32x2 %0, %1, %2;" : "=l"(r) : "l"(a), "l"(b)); return r;
}
__device__ __forceinline__ ull add2(ull a, ull b) {
    ull r; asm("add.rn.f32x2 %0, %1, %2;" : "=l"(r) : "l"(a), "l"(b)); return r;
}
__device__ __forceinline__ ull sub2(ull a, ull b, ull negone) {   // a - b
    ull r; asm("fma.rn.f32x2 %0, %1, %2, %3;" : "=l"(r) : "l"(b), "l"(negone), "l"(a)); return r;
}
__device__ __forceinline__ ull neg2(ull a, ull negone) {
    ull r; asm("mul.rn.f32x2 %0, %1, %2;" : "=l"(r) : "l"(a), "l"(negone)); return r;
}
__device__ __forceinline__ float2 unpk(ull v) {
    float2 r; asm("mov.b64 {%0, %1}, %2;" : "=f"(r.x), "=f"(r.y) : "l"(v)); return r;
}
// ---------------- fp16 pack/unpack helpers ----------------------------------
__device__ __forceinline__ unsigned f22h(float a, float b) {
    __half2 h = __floats2half2_rn(a, b);
    return *reinterpret_cast<unsigned*>(&h);
}
__device__ __forceinline__ ulonglong2 h4f(uint2 u) {            // 4 halves -> 2 packed f32x2
    __half2 ha = *reinterpret_cast<__half2*>(&u.x);
    __half2 hb = *reinterpret_cast<__half2*>(&u.y);
    float2 fa = __half22float2(ha), fb = __half22float2(hb);
    return make_ulonglong2(pack2(fa.x, fa.y), pack2(fb.x, fb.y));
}
__device__ __forceinline__ void h8store(float* dst, uint4 u) {  // 8 halves -> smem f32
    __half2* hp = reinterpret_cast<__half2*>(&u);
    float2 f0 = __half22float2(hp[0]), f1 = __half22float2(hp[1]);
    float2 f2 = __half22float2(hp[2]), f3 = __half22float2(hp[3]);
    *reinterpret_cast<float4*>(dst)     = make_float4(f0.x, f0.y, f1.x, f1.y);
    *reinterpret_cast<float4*>(dst + 4) = make_float4(f2.x, f2.y, f3.x, f3.y);
}
// per-kernel twiddle table init (replaces init kernel): angle = 2*pi*t/256
#define INIT_TW(twp, twn, t) { \
    float sv_, cv_; sincospif((float)(t) * 0.0078125f, &sv_, &cv_); \
    twp[t] = make_float4(cv_, cv_,  sv_,  sv_); \
    twn[t] = make_float4(cv_, cv_, -sv_, -sv_); }

// ---------------- K1: forward DFT along w (radix-8, 256 thr, 2 ky/thread) ---
// Planes: 0:U0 1:U4 2:U1R 3:U1I 4:U2R 5:U2I 6:U3R 7:U3I, each [32 w0][64 i].
__global__ __launch_bounds__(256) void k1_fwd_w(const float* __restrict__ x) {
    extern __shared__ __align__(16) float us[];       // 8 x 2048 floats = 64KB
    __shared__ __align__(16) float4 twp[256], twn[256];
    const int t = threadIdx.x;
    INIT_TW(twp, twn, t)
    const int b = blockIdx.x, n = b >> 8, h = b & 255;
    const float* xb = x + (size_t)(n*RR + h)*RR*IND;
    const ull NEG1 = splat2(-1.f);
    const ull RSQ2 = splat2(0.70710678118654752440f);
#pragma unroll
    for (int rr = 0; rr < 2; rr++) {                  // 512 loader roles
        const int role = t + 256*rr;
        const int w0 = role >> 4, iq = (role & 15) * 4;
        const float* p = xb + w0*IND + iq;
        float4 F0 = __ldcs(reinterpret_cast<const float4*>(p));
        float4 F1 = __ldcs(reinterpret_cast<const float4*>(p + 32*IND));
        float4 F2 = __ldcs(reinterpret_cast<const float4*>(p + 64*IND));
        float4 F3 = __ldcs(reinterpret_cast<const float4*>(p + 96*IND));
        float4 F4 = __ldcs(reinterpret_cast<const float4*>(p + 128*IND));
        float4 F5 = __ldcs(reinterpret_cast<const float4*>(p + 160*IND));
        float4 F6 = __ldcs(reinterpret_cast<const float4*>(p + 192*IND));
        float4 F7 = __ldcs(reinterpret_cast<const float4*>(p + 224*IND));
        ulonglong2 A0 = *reinterpret_cast<ulonglong2*>(&F0);
        ulonglong2 A1 = *reinterpret_cast<ulonglong2*>(&F1);
        ulonglong2 A2 = *reinterpret_cast<ulonglong2*>(&F2);
        ulonglong2 A3 = *reinterpret_cast<ulonglong2*>(&F3);
        ulonglong2 A4 = *reinterpret_cast<ulonglong2*>(&F4);
        ulonglong2 A5 = *reinterpret_cast<ulonglong2*>(&F5);
        ulonglong2 A6 = *reinterpret_cast<ulonglong2*>(&F6);
        ulonglong2 A7 = *reinterpret_cast<ulonglong2*>(&F7);
        const int rb = w0*64 + iq;
#pragma unroll
        for (int l = 0; l < 2; l++) {
            ull a0 = l ? A0.y : A0.x, a1 = l ? A1.y : A1.x;
            ull a2 = l ? A2.y : A2.x, a3 = l ? A3.y : A3.x;
            ull a4 = l ? A4.y : A4.x, a5 = l ? A5.y : A5.x;
            ull a6 = l ? A6.y : A6.x, a7 = l ? A7.y : A7.x;
            ull s0 = add2(a0, a4), s1 = add2(a1, a5);
            ull s2 = add2(a2, a6), s3 = add2(a3, a7);
            ull d0 = sub2(a0, a4, NEG1), d1 = sub2(a1, a5, NEG1);
            ull d2 = sub2(a2, a6, NEG1), d3 = sub2(a3, a7, NEG1);
            ull e  = add2(s0, s2), f  = add2(s1, s3);
            ull g  = sub2(s0, s2, NEG1), hh = sub2(s1, s3, NEG1);
            ull m  = mul2(sub2(d1, d3, NEG1), RSQ2);
            ull pp = mul2(add2(d1, d3), RSQ2);
            const int off = rb + 2*l;
            *reinterpret_cast<ull*>(&us[0*2048 + off]) = add2(e, f);                 // U0
            *reinterpret_cast<ull*>(&us[1*2048 + off]) = sub2(e, f, NEG1);           // U4
            *reinterpret_cast<ull*>(&us[2*2048 + off]) = add2(d0, m);                // U1R
            *reinterpret_cast<ull*>(&us[3*2048 + off]) = neg2(add2(d2, pp), NEG1);   // U1I
            *reinterpret_cast<ull*>(&us[4*2048 + off]) = g;                          // U2R
            *reinterpret_cast<ull*>(&us[5*2048 + off]) = neg2(hh, NEG1);             // U2I
            *reinterpret_cast<ull*>(&us[6*2048 + off]) = sub2(d0, m, NEG1);          // U3R
            *reinterpret_cast<ull*>(&us[7*2048 + off]) = sub2(d2, pp, NEG1);         // U3I
        }
    }
    __syncthreads();

    const int i0 = (t & 15) * 4;
    const int slot = t >> 4;
    const int cls = slot >> 1;                        // 0..7, warp-uniform
    const int ky_a = cls + 8*(slot & 1);
    const int ky_b = ky_a + 16;
    ull aR[2][2] = {{0,0},{0,0}}, aI[2][2] = {{0,0},{0,0}};
    int pa = 0, pb = 0;
    const float sc = 1.f/256.f;
    float iscl = sc;

    if (cls == 0 || cls == 4) {                       // real classes
        const float* Up = us + (cls == 0 ? 0 : 2048);
        for (int w0 = 0; w0 < 32; w0++) {
            ulonglong2 U = *reinterpret_cast<const ulonglong2*>(&Up[w0*64 + i0]);
            ulonglong2 ta = *reinterpret_cast<const ulonglong2*>(&twn[pa]);
            fma2(aR[0][0], ta.x, U.x); fma2(aR[0][1], ta.x, U.y);
            fma2(aI[0][0], ta.y, U.x); fma2(aI[0][1], ta.y, U.y);
            ulonglong2 tb = *reinterpret_cast<const ulonglong2*>(&twn[pb]);
            fma2(aR[1][0], tb.x, U.x); fma2(aR[1][1], tb.x, U.y);
            fma2(aI[1][0], tb.y, U.x); fma2(aI[1][1], tb.y, U.y);
            pa = (pa + ky_a) & 255; pb = (pb + ky_b) & 255;
        }
    } else if (cls < 4) {                             // complex classes 1,2,3
        const float* pRb = us + 2048 * (2*cls);
        const float* pIb = pRb + 2048;
        for (int w0 = 0; w0 < 32; w0++) {
            ulonglong2 UR = *reinterpret_cast<const ulonglong2*>(&pRb[w0*64 + i0]);
            ulonglong2 UI = *reinterpret_cast<const ulonglong2*>(&pIb[w0*64 + i0]);
            ulonglong2 tp4 = *reinterpret_cast<const ulonglong2*>(&twp[pa]);
            ulonglong2 tn4 = *reinterpret_cast<const ulonglong2*>(&twn[pa]);
            fma2(aR[0][0], tp4.x, UR.x); fma2(aR[0][0], tp4.y, UI.x);
            fma2(aR[0][1], tp4.x, UR.y); fma2(aR[0][1], tp4.y, UI.y);
            fma2(aI[0][0], tp4.x, UI.x); fma2(aI[0][0], tn4.y, UR.x);
            fma2(aI[0][1], tp4.x, UI.y); fma2(aI[0][1], tn4.y, UR.y);
            tp4 = *reinterpret_cast<const ulonglong2*>(&twp[pb]);
            tn4 = *reinterpret_cast<const ulonglong2*>(&twn[pb]);
            fma2(aR[1][0], tp4.x, UR.x); fma2(aR[1][0], tp4.y, UI.x);
            fma2(aR[1][1], tp4.x, UR.y); fma2(aR[1][1], tp4.y, UI.y);
            fma2(aI[1][0], tp4.x, UI.x); fma2(aI[1][0], tn4.y, UR.x);
            fma2(aI[1][1], tp4.x, UI.y); fma2(aI[1][1], tn4.y, UR.y);
            pa = (pa + ky_a) & 255; pb = (pb + ky_b) & 255;
        }
    } else {                                          // conj classes 5,6,7 -> planes 3,2,1
        const int cc = 8 - cls;
        const float* pRb = us + 2048 * (2*cc);
        const float* pIb = pRb + 2048;
        iscl = -sc;
        for (int w0 = 0; w0 < 32; w0++) {
            ulonglong2 UR = *reinterpret_cast<const ulonglong2*>(&pRb[w0*64 + i0]);
            ulonglong2 UI = *reinterpret_cast<const ulonglong2*>(&pIb[w0*64 + i0]);
            ulonglong2 tp4 = *reinterpret_cast<const ulonglong2*>(&twp[pa]);
            ulonglong2 tn4 = *reinterpret_cast<const ulonglong2*>(&twn[pa]);
            fma2(aR[0][0], tp4.x, UR.x); fma2(aR[0][0], tn4.y, UI.x);
            fma2(aR[0][1], tp4.x, UR.y); fma2(aR[0][1], tn4.y, UI.y);
            fma2(aI[0][0], tp4.x, UI.x); fma2(aI[0][0], tp4.y, UR.x);
            fma2(aI[0][1], tp4.x, UI.y); fma2(aI[0][1], tp4.y, UR.y);
            tp4 = *reinterpret_cast<const ulonglong2*>(&twp[pb]);
            tn4 = *reinterpret_cast<const ulonglong2*>(&twn[pb]);
            fma2(aR[1][0], tp4.x, UR.x); fma2(aR[1][0], tn4.y, UI.x);
            fma2(aR[1][1], tp4.x, UR.y); fma2(aR[1][1], tn4.y, UI.y);
            fma2(aI[1][0], tp4.x, UI.x); fma2(aI[1][0], tp4.y, UR.x);
            fma2(aI[1][1], tp4.x, UI.y); fma2(aI[1][1], tp4.y, UR.y);
            pa = (pa + ky_a) & 255; pb = (pb + ky_b) & 255;
        }
    }
#pragma unroll
    for (int j = 0; j < 2; j++) {
        const int ky = j ? ky_b : ky_a;
        size_t o = (size_t)((n*MD + ky)*RR + h)*IND + i0;
        float2 a0 = unpk(aR[j][0]), a1 = unpk(aR[j][1]);
        *reinterpret_cast<uint2*>(&g_XwRh[o]) =
            make_uint2(f22h(a0.x*sc, a0.y*sc), f22h(a1.x*sc, a1.y*sc));
        a0 = unpk(aI[j][0]); a1 = unpk(aI[j][1]);
        *reinterpret_cast<uint2*>(&g_XwIh[o]) =
            make_uint2(f22h(a0.x*iscl, a0.y*iscl), f22h(a1.x*iscl, a1.y*iscl));
    }
}

// ---------------- K2: forward h-DFT, radix-4, register-prefetch pipeline ----
__global__ __launch_bounds__(256, 3) void k2_fwd_h() {
    __shared__ __align__(16) float Vs[8*16*64];       // 8 planes x [16 h0][64 i] = 32KB
    __shared__ __align__(16) float4 twp[256], twn[256];
    const int t = threadIdx.x;
    INIT_TW(twp, twn, t)
    const int b = blockIdx.x, half = b & 1, ky = (b >> 1) & 31, n = b >> 6;
    const __half* baseR = g_XwRh + (size_t)(n*MD + ky)*RR*IND;
    const __half* baseI = g_XwIh + (size_t)(n*MD + ky)*RR*IND;
    const int i0 = (t & 15) * 4;
    const int g = t >> 4, c = g & 3, mseg = g >> 2;
    const int kxl0 = 8*mseg + c;                       // slots of class c
    const int kap0 = half ? (224 + kxl0) : kxl0;
    const int kap1 = kap0 + 4;
    const int h0ld = t >> 4, iq = (t & 15) * 4;        // loader role (1 per thread)
    const ull NEG1 = splat2(-1.f);
    ull aR[2][2] = {{0,0},{0,0}}, aI[2][2] = {{0,0},{0,0}};
    int p0 = 0, p1 = 0;

    uint2 R0u, R1u, R2u, R3u, I0u, I1u, I2u, I3u;
    {
        const __half* pR = baseR + h0ld*IND + iq;
        const __half* pI = baseI + h0ld*IND + iq;
        R0u = *reinterpret_cast<const uint2*>(pR);
        R1u = *reinterpret_cast<const uint2*>(pR + 64*IND);
        R2u = *reinterpret_cast<const uint2*>(pR + 128*IND);
        R3u = *reinterpret_cast<const uint2*>(pR + 192*IND);
        I0u = *reinterpret_cast<const uint2*>(pI);
        I1u = *reinterpret_cast<const uint2*>(pI + 64*IND);
        I2u = *reinterpret_cast<const uint2*>(pI + 128*IND);
        I3u = *reinterpret_cast<const uint2*>(pI + 192*IND);
    }

    for (int hc = 0; hc < 64; hc += 16) {
        __syncthreads();
        {   // convert + butterfly registers -> Vs
            ulonglong2 R0 = h4f(R0u), R1 = h4f(R1u), R2 = h4f(R2u), R3 = h4f(R3u);
            ulonglong2 I0 = h4f(I0u), I1 = h4f(I1u), I2 = h4f(I2u), I3 = h4f(I3u);
            ull sRx = add2(R0.x, R2.x), sRy = add2(R0.y, R2.y);
            ull dRx = sub2(R0.x, R2.x, NEG1), dRy = sub2(R0.y, R2.y, NEG1);
            ull uRx = add2(R1.x, R3.x), uRy = add2(R1.y, R3.y);
            ull eRx = sub2(R1.x, R3.x, NEG1), eRy = sub2(R1.y, R3.y, NEG1);
            ull sIx = add2(I0.x, I2.x), sIy = add2(I0.y, I2.y);
            ull dIx = sub2(I0.x, I2.x, NEG1), dIy = sub2(I0.y, I2.y, NEG1);
            ull uIx = add2(I1.x, I3.x), uIy = add2(I1.y, I3.y);
            ull eIx = sub2(I1.x, I3.x, NEG1), eIy = sub2(I1.y, I3.y, NEG1);
            const int rb = h0ld*64 + iq;
            ulonglong2* vp;
            vp = reinterpret_cast<ulonglong2*>(&Vs[0*1024 + rb]);
            *vp = make_ulonglong2(add2(sRx, uRx), add2(sRy, uRy));
            vp = reinterpret_cast<ulonglong2*>(&Vs[1*1024 + rb]);
            *vp = make_ulonglong2(add2(sIx, uIx), add2(sIy, uIy));
            vp = reinterpret_cast<ulonglong2*>(&Vs[2*1024 + rb]);
            *vp = make_ulonglong2(add2(dRx, eIx), add2(dRy, eIy));
            vp = reinterpret_cast<ulonglong2*>(&Vs[3*1024 + rb]);
            *vp = make_ulonglong2(sub2(dIx, eRx, NEG1), sub2(dIy, eRy, NEG1));
            vp = reinterpret_cast<ulonglong2*>(&Vs[4*1024 + rb]);
            *vp = make_ulonglong2(sub2(sRx, uRx, NEG1), sub2(sRy, uRy, NEG1));
            vp = reinterpret_cast<ulonglong2*>(&Vs[5*1024 + rb]);
            *vp = make_ulonglong2(sub2(sIx, uIx, NEG1), sub2(sIy, uIy, NEG1));
            vp = reinterpret_cast<ulonglong2*>(&Vs[6*1024 + rb]);
            *vp = make_ulonglong2(sub2(dRx, eIx, NEG1), sub2(dRy, eIy, NEG1));
            vp = reinterpret_cast<ulonglong2*>(&Vs[7*1024 + rb]);
            *vp = make_ulonglong2(add2(dIx, eRx), add2(dIy, eRy));
        }
        __syncthreads();
        if (hc < 48) {
            const __half* pR = baseR + (hc + 16 + h0ld)*IND + iq;
            const __half* pI = baseI + (hc + 16 + h0ld)*IND + iq;
            R0u = *reinterpret_cast<const uint2*>(pR);
            R1u = *reinterpret_cast<const uint2*>(pR + 64*IND);
            R2u = *reinterpret_cast<const uint2*>(pR + 128*IND);
            R3u = *reinterpret_cast<const uint2*>(pR + 192*IND);
            I0u = *reinterpret_cast<const uint2*>(pI);
            I1u = *reinterpret_cast<const uint2*>(pI + 64*IND);
            I2u = *reinterpret_cast<const uint2*>(pI + 128*IND);
            I3u = *reinterpret_cast<const uint2*>(pI + 192*IND);
        }
        const float* VRb = &Vs[(c*2 + 0)*1024];
        const float* VIb = &Vs[(c*2 + 1)*1024];
        for (int h0l = 0; h0l < 16; h0l++) {
            ulonglong2 VR = *reinterpret_cast<const ulonglong2*>(&VRb[h0l*64 + i0]);
            ulonglong2 VI = *reinterpret_cast<const ulonglong2*>(&VIb[h0l*64 + i0]);
            ulonglong2 tp4 = *reinterpret_cast<const ulonglong2*>(&twp[p0]);
            ulonglong2 tn4 = *reinterpret_cast<const ulonglong2*>(&twn[p0]);
            fma2(aR[0][0], tp4.x, VR.x); fma2(aR[0][0], tp4.y, VI.x);
            fma2(aR[0][1], tp4.x, VR.y); fma2(aR[0][1], tp4.y, VI.y);
            fma2(aI[0][0], tp4.x, VI.x); fma2(aI[0][0], tn4.y, VR.x);
            fma2(aI[0][1], tp4.x, VI.y); fma2(aI[0][1], tn4.y, VR.y);
            p0 = (p0 + kap0) & 255;
            tp4 = *reinterpret_cast<const ulonglong2*>(&twp[p1]);
            tn4 = *reinterpret_cast<const ulonglong2*>(&twn[p1]);
            fma2(aR[1][0], tp4.x, VR.x); fma2(aR[1][0], tp4.y, VI.x);
            fma2(aR[1][1], tp4.x, VR.y); fma2(aR[1][1], tp4.y, VI.y);
            fma2(aI[1][0], tp4.x, VI.x); fma2(aI[1][0], tn4.y, VR.x);
            fma2(aI[1][1], tp4.x, VI.y); fma2(aI[1][1], tn4.y, VR.y);
            p1 = (p1 + kap1) & 255;
        }
    }
#pragma unroll
    for (int j = 0; j < 2; j++) {
        int kxs = half*32 + kxl0 + 4*j;
        size_t o = (size_t)((ky*KXN + kxs)*NB + n)*IND + i0;
        float2 a0 = unpk(aR[j][0]), a1 = unpk(aR[j][1]);
        *reinterpret_cast<uint2*>(&g_XmRh[o]) =
            make_uint2(f22h(a0.x, a0.y), f22h(a1.x, a1.y));
        a0 = unpk(aI[j][0]); a1 = unpk(aI[j][1]);
        *reinterpret_cast<uint2*>(&g_XmIh[o]) =
            make_uint2(f22h(a0.x, a0.y), f22h(a1.x, a1.y));
    }
}

// ---------------- K3: per-mode complex channel mix (8x64x64) ----------------
__global__ __launch_bounds__(256) void k3_mix(const float* __restrict__ w0,
                                              const float* __restrict__ w1) {
    __shared__ float Xs2[NB*IND*2];                   // interleaved (R,I)
    const int t = threadIdx.x, b = blockIdx.x;
    const int kx = b >> 5, ky = b & 31;
    size_t xb = (size_t)(ky*KXN + kx)*NB*IND;
    {   // fp16 -> interleaved fp32 smem (each thread: 2 idx)
        __half2 hR = *reinterpret_cast<const __half2*>(g_XmRh + xb + 2*t);
        __half2 hI = *reinterpret_cast<const __half2*>(g_XmIh + xb + 2*t);
        float2 fR = __half22float2(hR), fI = __half22float2(hI);
        Xs2[4*t]     = fR.x; Xs2[4*t + 1] = fI.x;
        Xs2[4*t + 2] = fR.y; Xs2[4*t + 3] = fI.y;
    }
    __syncthreads();
    const float4* wp4 = reinterpret_cast<const float4*>(
        (kx < MD) ? (w0 + (size_t)(kx*MD + ky)*IND*OUTD*2)
                  : (w1 + (size_t)((kx - MD)*MD + ky)*IND*OUTD*2));
    const int o2 = t & 31, n = t >> 5;                // o0 = 2*o2, one n per thread
    float r0 = 0.f, i0 = 0.f, r1 = 0.f, i1 = 0.f;
#pragma unroll 8
    for (int i = 0; i < IND; i++) {
        float4 w = wp4[i*32 + o2];                    // (wR0,wI0,wR1,wI1)
        float2 xv = *reinterpret_cast<const float2*>(&Xs2[(n*IND + i)*2]);
        r0 = fmaf(xv.x, w.x, fmaf(-xv.y, w.y, r0));
        i0 = fmaf(xv.x, w.y, fmaf( xv.y, w.x, i0));
        r1 = fmaf(xv.x, w.z, fmaf(-xv.y, w.w, r1));
        i1 = fmaf(xv.x, w.w, fmaf( xv.y, w.z, i1));
    }
    size_t gg = (size_t)((n*MD + ky)*KXN + kx)*OUTD + 2*o2;
    *reinterpret_cast<unsigned*>(&g_OmRh[gg]) = f22h(r0, r1);
    *reinterpret_cast<unsigned*>(&g_OmIh[gg]) = f22h(i0, i1);
}

// ---------------- K4: inverse h-DFT, radix-4 on output ----------------------
#define K4STEP(CR, CI) { \
    ulonglong2 R0 = *reinterpret_cast<const ulonglong2*>(&sR[kxo]); \
    ulonglong2 R1 = *reinterpret_cast<const ulonglong2*>(&sR[kxo + 4]); \
    ulonglong2 I0 = *reinterpret_cast<const ulonglong2*>(&sI[kxo]); \
    ulonglong2 I1 = *reinterpret_cast<const ulonglong2*>(&sI[kxo + 4]); \
    ulonglong2 tp4 = *reinterpret_cast<const ulonglong2*>(&twp[p]); \
    ulonglong2 tn4 = *reinterpret_cast<const ulonglong2*>(&twn[p]); \
    fma2(CR[0], tn4.x, R0.x); fma2(CR[0], tn4.y, I0.x); \
    fma2(CR[1], tn4.x, R0.y); fma2(CR[1], tn4.y, I0.y); \
    fma2(CR[2], tn4.x, R1.x); fma2(CR[2], tn4.y, I1.x); \
    fma2(CR[3], tn4.x, R1.y); fma2(CR[3], tn4.y, I1.y); \
    fma2(CI[0], tp4.x, I0.x); fma2(CI[0], tp4.y, R0.x); \
    fma2(CI[1], tp4.x, I0.y); fma2(CI[1], tp4.y, R0.y); \
    fma2(CI[2], tp4.x, I1.x); fma2(CI[2], tp4.y, R1.x); \
    fma2(CI[3], tp4.x, I1.y); fma2(CI[3], tp4.y, R1.y); \
    p = (p + h0) & 255; kxo += OUTD; }

__global__ __launch_bounds__(256) void k4_inv_h() {
    __shared__ __align__(16) float sR[KXN*OUTD], sI[KXN*OUTD];
    __shared__ __align__(16) float4 twp[256], twn[256];
    const int t = threadIdx.x;
    INIT_TW(twp, twn, t)
    const int b = blockIdx.x, grp = b & 1, ky = (b >> 1) & 31, n = b >> 6;
    {   // fp16 Om tile -> fp32 smem (2 uint4 = 16 halves per thread per plane)
        const uint4* pR = reinterpret_cast<const uint4*>(g_OmRh + (size_t)(n*MD + ky)*KXN*OUTD);
        const uint4* pI = reinterpret_cast<const uint4*>(g_OmIh + (size_t)(n*MD + ky)*KXN*OUTD);
        h8store(&sR[t*16],     pR[2*t]);
        h8store(&sR[t*16 + 8], pR[2*t + 1]);
        h8store(&sI[t*16],     pI[2*t]);
        h8store(&sI[t*16 + 8], pI[2*t + 1]);
    }
    __syncthreads();
    const int o0 = (t & 7) * 8, h0 = grp*32 + (t >> 3);
    ull C0R[4], C0I[4], C1R[4], C1I[4], C2R[4], C2I[4], C3R[4], C3I[4];
#pragma unroll
    for (int j = 0; j < 4; j++) {
        C0R[j]=C0I[j]=C1R[j]=C1I[j]=0ull;
        C2R[j]=C2I[j]=C3R[j]=C3I[j]=0ull;
    }
#pragma unroll 1
    for (int kh = 0; kh < 2; kh++) {
        int p = kh ? ((224*h0) & 255) : 0;
        int kxo = (kh*32)*OUTD + o0;
#pragma unroll
        for (int kk = 0; kk < 32; kk += 4) {
            K4STEP(C0R, C0I)
            K4STEP(C1R, C1I)
            K4STEP(C2R, C2I)
            K4STEP(C3R, C3I)
        }
    }
    const ull NEG1 = splat2(-1.f);
    const ull FAC2 = splat2((ky == 0 ? 1.f : 2.f) * (1.f/256.f));
    const size_t obase = (size_t)((n*RR + h0)*MD + ky)*OUTD + o0;
#pragma unroll
    for (int j = 0; j < 4; j++) {
        ull ER = add2(C0R[j], C2R[j]), EI = add2(C0I[j], C2I[j]);
        ull FR = sub2(C0R[j], C2R[j], NEG1), FI = sub2(C0I[j], C2I[j], NEG1);
        ull GR = add2(C1R[j], C3R[j]), GI = add2(C1I[j], C3I[j]);
        ull HR = sub2(C1R[j], C3R[j], NEG1), HI = sub2(C1I[j], C3I[j], NEG1);
        ull YR[4] = { add2(ER, GR), sub2(FR, HI, NEG1), sub2(ER, GR, NEG1), add2(FR, HI) };
        ull YI[4] = { add2(EI, GI), add2(FI, HR), sub2(EI, GI, NEG1), sub2(FI, HR, NEG1) };
#pragma unroll
        for (int q = 0; q < 4; q++) {
            size_t o = obase + (size_t)(64*q)*MD*OUTD + 2*j;
            float2 vr = unpk(mul2(YR[q], FAC2));
            float2 vi = unpk(mul2(YI[q], FAC2));
            *reinterpret_cast<unsigned*>(&g_Y1Rh[o]) = f22h(vr.x, vr.y);
            *reinterpret_cast<unsigned*>(&g_Y1Ih[o]) = f22h(vi.x, vi.y);
        }
    }
}

// ---------------- K5: radix-4 inverse w synthesis + residual + SiLU ---------
#define XPAD 68
__global__ __launch_bounds__(256) void k5_inv_w(const float* __restrict__ x,
                                                const float* __restrict__ res_w,
                                                const float* __restrict__ res_b,
                                                float* __restrict__ out) {
    extern __shared__ __align__(16) float xs[];       // [256][XPAD]
    __shared__ __align__(16) float YsR[MD*OUTD], YsI[MD*OUTD];
    __shared__ __align__(16) float rws[IND*OUTD];
    __shared__ __align__(16) float4 twp[256], twn[256];
    __shared__ __align__(16) float rbs[64];
    const int t = threadIdx.x, b = blockIdx.x, n = b >> 8, h = b & 255;
    INIT_TW(twp, twn, t)
    const float4* xp = reinterpret_cast<const float4*>(x + (size_t)(n*RR + h)*RR*IND);
#pragma unroll
    for (int it = 0; it < 16; it++) {
        int j = t + 256*it;
        float4 v = __ldcs(xp + j);
        int w = j >> 4, c = j & 15;
        *reinterpret_cast<float4*>(&xs[w*XPAD + c*4]) = v;
    }
    {   // Y1 fp16 -> fp32 smem (one uint4 = 8 halves per thread per plane)
        const uint4* yRu = reinterpret_cast<const uint4*>(g_Y1Rh + (size_t)(n*RR + h)*MD*OUTD);
        const uint4* yIu = reinterpret_cast<const uint4*>(g_Y1Ih + (size_t)(n*RR + h)*MD*OUTD);
        h8store(&YsR[t*8], yRu[t]);
        h8store(&YsI[t*8], yIu[t]);
    }
#pragma unroll
    for (int it = 0; it < 4; it++)
        reinterpret_cast<float4*>(rws)[t + 256*it] =
            reinterpret_cast<const float4*>(res_w)[t + 256*it];
    if (t < 64) rbs[t] = res_b[t];
    __syncthreads();

    const int og = t & 7, o0 = og*8, pr = t >> 3;     // w0a = pr, w0b = pr + 32
    const ull NEG1 = splat2(-1.f);
    ull C0R[2][4], C2R[2][4], C1R[2][4], C1I[2][4], C3R[2][4], C3I[2][4];
#pragma unroll
    for (int s = 0; s < 2; s++)
#pragma unroll
        for (int j = 0; j < 4; j++) {
            C0R[s][j]=C2R[s][j]=C1R[s][j]=C1I[s][j]=C3R[s][j]=C3I[s][j]=0ull;
        }
    int pa = 0, pb = 0;
    const int stpa = pr, stpb = pr + 32;
#pragma unroll
    for (int kb = 0; kb < 8; kb++) {
        // c = 0
        {
            const int ky = 4*kb;
            ulonglong2 yr0 = *reinterpret_cast<const ulonglong2*>(&YsR[ky*OUTD + o0]);
            ulonglong2 yr1 = *reinterpret_cast<const ulonglong2*>(&YsR[ky*OUTD + o0 + 4]);
            ulonglong2 yi0 = *reinterpret_cast<const ulonglong2*>(&YsI[ky*OUTD + o0]);
            ulonglong2 yi1 = *reinterpret_cast<const ulonglong2*>(&YsI[ky*OUTD + o0 + 4]);
            ulonglong2 tn4 = *reinterpret_cast<const ulonglong2*>(&twn[pa]);
            fma2(C0R[0][0], tn4.x, yr0.x); fma2(C0R[0][0], tn4.y, yi0.x);
            fma2(C0R[0][1], tn4.x, yr0.y); fma2(C0R[0][1], tn4.y, yi0.y);
            fma2(C0R[0][2], tn4.x, yr1.x); fma2(C0R[0][2], tn4.y, yi1.x);
            fma2(C0R[0][3], tn4.x, yr1.y); fma2(C0R[0][3], tn4.y, yi1.y);
            tn4 = *reinterpret_cast<const ulonglong2*>(&twn[pb]);
            fma2(C0R[1][0], tn4.x, yr0.x); fma2(C0R[1][0], tn4.y, yi0.x);
            fma2(C0R[1][1], tn4.x, yr0.y); fma2(C0R[1][1], tn4.y, yi0.y);
            fma2(C0R[1][2], tn4.x, yr1.x); fma2(C0R[1][2], tn4.y, yi1.x);
            fma2(C0R[1][3], tn4.x, yr1.y); fma2(C0R[1][3], tn4.y, yi1.y);
            pa = (pa + stpa) & 255; pb = (pb + stpb) & 255;
        }
        // c = 1
        {
            const int ky = 4*kb + 1;
            ulonglong2 yr0 = *reinterpret_cast<const ulonglong2*>(&YsR[ky*OUTD + o0]);
            ulonglong2 yr1 = *reinterpret_cast<const ulonglong2*>(&YsR[ky*OUTD + o0 + 4]);
            ulonglong2 yi0 = *reinterpret_cast<const ulonglong2*>(&YsI[ky*OUTD + o0]);
            ulonglong2 yi1 = *reinterpret_cast<const ulonglong2*>(&YsI[ky*OUTD + o0 + 4]);
            ulonglong2 tn4 = *reinterpret_cast<const ulonglong2*>(&twn[pa]);
            ulonglong2 tp4 = *reinterpret_cast<const ulonglong2*>(&twp[pa]);
            fma2(C1R[0][0], tn4.x, yr0.x); fma2(C1R[0][0], tn4.y, yi0.x);
            fma2(C1R[0][1], tn4.x, yr0.y); fma2(C1R[0][1], tn4.y, yi0.y);
            fma2(C1R[0][2], tn4.x, yr1.x); fma2(C1R[0][2], tn4.y, yi1.x);
            fma2(C1R[0][3], tn4.x, yr1.y); fma2(C1R[0][3], tn4.y, yi1.y);
            fma2(C1I[0][0], tp4.x, yi0.x); fma2(C1I[0][0], tp4.y, yr0.x);
            fma2(C1I[0][1], tp4.x, yi0.y); fma2(C1I[0][1], tp4.y, yr0.y);
            fma2(C1I[0][2], tp4.x, yi1.x); fma2(C1I[0][2], tp4.y, yr1.x);
            fma2(C1I[0][3], tp4.x, yi1.y); fma2(C1I[0][3], tp4.y, yr1.y);
            tn4 = *reinterpret_cast<const ulonglong2*>(&twn[pb]);
            tp4 = *reinterpret_cast<const ulonglong2*>(&twp[pb]);
            fma2(C1R[1][0], tn4.x, yr0.x); fma2(C1R[1][0], tn4.y, yi0.x);
            fma2(C1R[1][1], tn4.x, yr0.y); fma2(C1R[1][1], tn4.y, yi0.y);
            fma2(C1R[1][2], tn4.x, yr1.x); fma2(C1R[1][2], tn4.y, yi1.x);
            fma2(C1R[1][3], tn4.x, yr1.y); fma2(C1R[1][3], tn4.y, yi1.y);
            fma2(C1I[1][0], tp4.x, yi0.x); fma2(C1I[1][0], tp4.y, yr0.x);
            fma2(C1I[1][1], tp4.x, yi0.y); fma2(C1I[1][1], tp4.y, yr0.y);
            fma2(C1I[1][2], tp4.x, yi1.x); fma2(C1I[1][2], tp4.y, yr1.x);
            fma2(C1I[1][3], tp4.x, yi1.y); fma2(C1I[1][3], tp4.y, yr1.y);
            pa = (pa + stpa) & 255; pb = (pb + stpb) & 255;
        }
        // c = 2
        {
            const int ky = 4*kb + 2;
            ulonglong2 yr0 = *reinterpret_cast<const ulonglong2*>(&YsR[ky*OUTD + o0]);
            ulonglong2 yr1 = *reinterpret_cast<const ulonglong2*>(&YsR[ky*OUTD + o0 + 4]);
            ulonglong2 yi0 = *reinterpret_cast<const ulonglong2*>(&YsI[ky*OUTD + o0]);
            ulonglong2 yi1 = *reinterpret_cast<const ulonglong2*>(&YsI[ky*OUTD + o0 + 4]);
            ulonglong2 tn4 = *reinterpret_cast<const ulonglong2*>(&twn[pa]);
            fma2(C2R[0][0], tn4.x, yr0.x); fma2(C2R[0][0], tn4.y, yi0.x);
            fma2(C2R[0][1], tn4.x, yr0.y); fma2(C2R[0][1], tn4.y, yi0.y);
            fma2(C2R[0][2], tn4.x, yr1.x); fma2(C2R[0][2], tn4.y, yi1.x);
            fma2(C2R[0][3], tn4.x, yr1.y); fma2(C2R[0][3], tn4.y, yi1.y);
            tn4 = *reinterpret_cast<const ulonglong2*>(&twn[pb]);
            fma2(C2R[1][0], tn4.x, yr0.x); fma2(C2R[1][0], tn4.y, yi0.x);
            fma2(C2R[1][1], tn4.x, yr0.y); fma2(C2R[1][1], tn4.y, yi0.y);
            fma2(C2R[1][2], tn4.x, yr1.x); fma2(C2R[1][2], tn4.y, yi1.x);
            fma2(C2R[1][3], tn4.x, yr1.y); fma2(C2R[1][3], tn4.y, yi1.y);
            pa = (pa + stpa) & 255; pb = (pb + stpb) & 255;
        }
        // c = 3
        {
            const int ky = 4*kb + 3;
            ulonglong2 yr0 = *reinterpret_cast<const ulonglong2*>(&YsR[ky*OUTD + o0]);
            ulonglong2 yr1 = *reinterpret_cast<const ulonglong2*>(&YsR[ky*OUTD + o0 + 4]);
            ulonglong2 yi0 = *reinterpret_cast<const ulonglong2*>(&YsI[ky*OUTD + o0]);
            ulonglong2 yi1 = *reinterpret_cast<const ulonglong2*>(&YsI[ky*OUTD + o0 + 4]);
            ulonglong2 tn4 = *reinterpret_cast<const ulonglong2*>(&twn[pa]);
            ulonglong2 tp4 = *reinterpret_cast<const ulonglong2*>(&twp[pa]);
            fma2(C3R[0][0], tn4.x, yr0.x); fma2(C3R[0][0], tn4.y, yi0.x);
            fma2(C3R[0][1], tn4.x, yr0.y); fma2(C3R[0][1], tn4.y, yi0.y);
            fma2(C3R[0][2], tn4.x, yr1.x); fma2(C3R[0][2], tn4.y, yi1.x);
            fma2(C3R[0][3], tn4.x, yr1.y); fma2(C3R[0][3], tn4.y, yi1.y);
            fma2(C3I[0][0], tp4.x, yi0.x); fma2(C3I[0][0], tp4.y, yr0.x);
            fma2(C3I[0][1], tp4.x, yi0.y); fma2(C3I[0][1], tp4.y, yr0.y);
            fma2(C3I[0][2], tp4.x, yi1.x); fma2(C3I[0][2], tp4.y, yr1.x);
            fma2(C3I[0][3], tp4.x, yi1.y); fma2(C3I[0][3], tp4.y, yr1.y);
            tn4 = *reinterpret_cast<const ulonglong2*>(&twn[pb]);
            tp4 = *reinterpret_cast<const ulonglong2*>(&twp[pb]);
            fma2(C3R[1][0], tn4.x, yr0.x); fma2(C3R[1][0], tn4.y, yi0.x);
            fma2(C3R[1][1], tn4.x, yr0.y); fma2(C3R[1][1], tn4.y, yi0.y);
            fma2(C3R[1][2], tn4.x, yr1.x); fma2(C3R[1][2], tn4.y, yi1.x);
            fma2(C3R[1][3], tn4.x, yr1.y); fma2(C3R[1][3], tn4.y, yi1.y);
            fma2(C3I[1][0], tp4.x, yi0.x); fma2(C3I[1][0], tp4.y, yr0.x);
            fma2(C3I[1][1], tp4.x, yi0.y); fma2(C3I[1][1], tp4.y, yr0.y);
            fma2(C3I[1][2], tp4.x, yi1.x); fma2(C3I[1][2], tp4.y, yr1.x);
            fma2(C3I[1][3], tp4.x, yi1.y); fma2(C3I[1][3], tp4.y, yr1.y);
            pa = (pa + stpa) & 255; pb = (pb + stpb) & 255;
        }
    }
    // ---- combine classes into 4 output rows + bias, both w0 ----
    ull ys[2][4][4];
    {
        ulonglong2 b01 = *reinterpret_cast<const ulonglong2*>(&rbs[o0]);
        ulonglong2 b23 = *reinterpret_cast<const ulonglong2*>(&rbs[o0 + 4]);
        ull bias[4] = {b01.x, b01.y, b23.x, b23.y};
#pragma unroll
        for (int s = 0; s < 2; s++)
#pragma unroll
            for (int j = 0; j < 4; j++) {
                ull e  = add2(C0R[s][j], C2R[s][j]);
                ull f  = sub2(C0R[s][j], C2R[s][j], NEG1);
                ull g  = add2(C1R[s][j], C3R[s][j]);
                ull hh = sub2(C3I[s][j], C1I[s][j], NEG1);
                ys[s][0][j] = add2(add2(e, g),  bias[j]);
                ys[s][2][j] = add2(sub2(e, g,  NEG1), bias[j]);
                ys[s][1][j] = add2(add2(f, hh), bias[j]);
                ys[s][3][j] = add2(sub2(f, hh, NEG1), bias[j]);
            }
    }
    // ---- residual GEMM into ys (2 i per step, vector x loads) ----
    for (int i = 0; i < IND; i += 2) {
        ulonglong2 rA01 = *reinterpret_cast<const ulonglong2*>(&rws[i*OUTD + o0]);
        ulonglong2 rA23 = *reinterpret_cast<const ulonglong2*>(&rws[i*OUTD + o0 + 4]);
        ulonglong2 rB01 = *reinterpret_cast<const ulonglong2*>(&rws[(i+1)*OUTD + o0]);
        ulonglong2 rB23 = *reinterpret_cast<const ulonglong2*>(&rws[(i+1)*OUTD + o0 + 4]);
#pragma unroll
        for (int s = 0; s < 2; s++) {
            const int wbase = pr + 32*s;
#pragma unroll
            for (int q = 0; q < 4; q++) {
                float2 xv = *reinterpret_cast<const float2*>(&xs[(wbase + 64*q)*XPAD + i]);
                ull sxA = splat2(xv.x), sxB = splat2(xv.y);
                fma2(ys[s][q][0], sxA, rA01.x); fma2(ys[s][q][1], sxA, rA01.y);
                fma2(ys[s][q][2], sxA, rA23.x); fma2(ys[s][q][3], sxA, rA23.y);
                fma2(ys[s][q][0], sxB, rB01.x); fma2(ys[s][q][1], sxB, rB01.y);
                fma2(ys[s][q][2], sxB, rB23.x); fma2(ys[s][q][3], sxB, rB23.y);
            }
        }
    }
    // ---- SiLU + streaming store ----
#pragma unroll
    for (int s = 0; s < 2; s++) {
        const int wbase = pr + 32*s;
#pragma unroll
        for (int q = 0; q < 4; q++) {
            float4 v4[2];
#pragma unroll
            for (int c = 0; c < 4; c++) {
                float2 v = unpk(ys[s][q][c]);
                v.x = v.x / (1.f + __expf(-v.x));
                v.y = v.y / (1.f + __expf(-v.y));
                reinterpret_cast<float2*>(v4)[c] = v;
            }
            size_t o = (size_t)((n*RR + h)*RR + (wbase + 64*q))*OUTD + o0;
            __stcs(reinterpret_cast<float4*>(&out[o]),     v4[0]);
            __stcs(reinterpret_cast<float4*>(&out[o + 4]), v4[1]);
        }
    }
}

// ---------------- launch ----------------------------------------------------
extern "C" void kernel_launch(void* const* d_in, const int* in_sizes, int n_in,
                              void* d_out, int out_size) {
    const float* x   = (const float*)d_in[0];
    const float* w0  = (const float*)d_in[1];
    const float* w1  = (const float*)d_in[2];
    const float* rsw = (const float*)d_in[3];
    const float* rsb = (const float*)d_in[4];
    float* out = (float*)d_out;

    cudaFuncSetAttribute(k1_fwd_w, cudaFuncAttributeMaxDynamicSharedMemorySize, 65536);
    cudaFuncSetAttribute(k5_inv_w, cudaFuncAttributeMaxDynamicSharedMemorySize, RR*XPAD*4);

    k1_fwd_w<<<NB*RR, 256, 65536>>>(x);
    k2_fwd_h<<<NB*MD*2, 256>>>();
    k3_mix<<<KXN*MD, 256>>>(w0, w1);
    k4_inv_h<<<NB*MD*2, 256>>>();
    k5_inv_w<<<NB*RR, 256, RR*XPAD*4>>>(x, rsw, rsb, out);
}

// round 16
// speedup vs baseline: 1.2319x; 1.0045x over previous
#include <cuda_runtime.h>
#include <cuda_fp16.h>

#define NB   8
#define RR   256
#define IND  64
#define OUTD 64
#define MD   32
#define KXN  64

typedef unsigned long long ull;

// ---------------- scratch (device globals; no allocations allowed) ----------
__device__ __half g_XwRh[NB*MD*RR*IND];   // [n][ky][h][i]  forward w-DFT (fp16)
__device__ __half g_XwIh[NB*MD*RR*IND];
__device__ __half g_XmRh[NB*MD*KXN*IND];  // [ky][kx][n][i] forward modes (fp16)
__device__ __half g_XmIh[NB*MD*KXN*IND];
__device__ __half g_OmRh[NB*MD*KXN*OUTD]; // [n][ky][kx][o] mixed modes (fp16)
__device__ __half g_OmIh[NB*MD*KXN*OUTD];
__device__ __half g_Y1Rh[NB*RR*MD*OUTD];  // [n][h][ky][o]  inverse h-DFT (fp16)
__device__ __half g_Y1Ih[NB*RR*MD*OUTD];

// ---------------- packed f32x2 helpers --------------------------------------
__device__ __forceinline__ void fma2(ull &d, ull a, ull b) {
    asm("fma.rn.f32x2 %0, %1, %2, %0;" : "+l"(d) : "l"(a), "l"(b));
}
__device__ __forceinline__ ull splat2(float x) {
    ull r; asm("mov.b64 %0, {%1, %1};" : "=l"(r) : "f"(x)); return r;
}
__device__ __forceinline__ ull pack2(float x, float y) {
    ull r; asm("mov.b64 %0, {%1, %2};" : "=l"(r) : "f"(x), "f"(y)); return r;
}
__device__ __forceinline__ ull mul2(ull a, ull b) {
    ull r; asm("mul.rn.f32x2 %0, %1, %2;" : "=l"(r) : "l"(a), "l"(b)); return r;
}
__device__ __forceinline__ ull add2(ull a, ull b) {
    ull r; asm("add.rn.f32x2 %0, %1, %2;" : "=l"(r) : "l"(a), "l"(b)); return r;
}
__device__ __forceinline__ ull sub2(ull a, ull b, ull negone) {   // a - b
    ull r; asm("fma.rn.f32x2 %0, %1, %2, %3;" : "=l"(r) : "l"(b), "l"(negone), "l"(a)); return r;
}
__device__ __forceinline__ ull neg2(ull a, ull negone) {
    ull r; asm("mul.rn.f32x2 %0, %1, %2;" : "=l"(r) : "l"(a), "l"(negone)); return r;
}
__device__ __forceinline__ float2 unpk(ull v) {
    float2 r; asm("mov.b64 {%0, %1}, %2;" : "=f"(r.x), "=f"(r.y) : "l"(v)); return r;
}
// ---------------- fp16 pack/unpack helpers ----------------------------------
__device__ __forceinline__ unsigned f22h(float a, float b) {
    __half2 h = __floats2half2_rn(a, b);
    return *reinterpret_cast<unsigned*>(&h);
}
__device__ __forceinline__ ulonglong2 h4f(uint2 u) {            // 4 halves -> 2 packed f32x2
    __half2 ha = *reinterpret_cast<__half2*>(&u.x);
    __half2 hb = *reinterpret_cast<__half2*>(&u.y);
    float2 fa = __half22float2(ha), fb = __half22float2(hb);
    return make_ulonglong2(pack2(fa.x, fa.y), pack2(fb.x, fb.y));
}
// per-kernel twiddle table init (replaces init kernel): angle = 2*pi*t/256
#define INIT_TW(twp, twn, t) { \
    float sv_, cv_; sincospif((float)(t) * 0.0078125f, &sv_, &cv_); \
    twp[t] = make_float4(cv_, cv_,  sv_,  sv_); \
    twn[t] = make_float4(cv_, cv_, -sv_, -sv_); }

// ---------------- K1: forward DFT along w (radix-8, 256 thr, 2 ky/thread) ---
// Planes: 0:U0 1:U4 2:U1R 3:U1I 4:U2R 5:U2I 6:U3R 7:U3I, each [32 w0][64 i].
__global__ __launch_bounds__(256) void k1_fwd_w(const float* __restrict__ x) {
    extern __shared__ __align__(16) float us[];       // 8 x 2048 floats = 64KB
    __shared__ __align__(16) float4 twp[256], twn[256];
    const int t = threadIdx.x;
    INIT_TW(twp, twn, t)
    const int b = blockIdx.x, n = b >> 8, h = b & 255;
    const float* xb = x + (size_t)(n*RR + h)*RR*IND;
    const ull NEG1 = splat2(-1.f);
    const ull RSQ2 = splat2(0.70710678118654752440f);
#pragma unroll
    for (int rr = 0; rr < 2; rr++) {                  // 512 loader roles
        const int role = t + 256*rr;
        const int w0 = role >> 4, iq = (role & 15) * 4;
        const float* p = xb + w0*IND + iq;
        float4 F0 = __ldcs(reinterpret_cast<const float4*>(p));
        float4 F1 = __ldcs(reinterpret_cast<const float4*>(p + 32*IND));
        float4 F2 = __ldcs(reinterpret_cast<const float4*>(p + 64*IND));
        float4 F3 = __ldcs(reinterpret_cast<const float4*>(p + 96*IND));
        float4 F4 = __ldcs(reinterpret_cast<const float4*>(p + 128*IND));
        float4 F5 = __ldcs(reinterpret_cast<const float4*>(p + 160*IND));
        float4 F6 = __ldcs(reinterpret_cast<const float4*>(p + 192*IND));
        float4 F7 = __ldcs(reinterpret_cast<const float4*>(p + 224*IND));
        ulonglong2 A0 = *reinterpret_cast<ulonglong2*>(&F0);
        ulonglong2 A1 = *reinterpret_cast<ulonglong2*>(&F1);
        ulonglong2 A2 = *reinterpret_cast<ulonglong2*>(&F2);
        ulonglong2 A3 = *reinterpret_cast<ulonglong2*>(&F3);
        ulonglong2 A4 = *reinterpret_cast<ulonglong2*>(&F4);
        ulonglong2 A5 = *reinterpret_cast<ulonglong2*>(&F5);
        ulonglong2 A6 = *reinterpret_cast<ulonglong2*>(&F6);
        ulonglong2 A7 = *reinterpret_cast<ulonglong2*>(&F7);
        const int rb = w0*64 + iq;
#pragma unroll
        for (int l = 0; l < 2; l++) {
            ull a0 = l ? A0.y : A0.x, a1 = l ? A1.y : A1.x;
            ull a2 = l ? A2.y : A2.x, a3 = l ? A3.y : A3.x;
            ull a4 = l ? A4.y : A4.x, a5 = l ? A5.y : A5.x;
            ull a6 = l ? A6.y : A6.x, a7 = l ? A7.y : A7.x;
            ull s0 = add2(a0, a4), s1 = add2(a1, a5);
            ull s2 = add2(a2, a6), s3 = add2(a3, a7);
            ull d0 = sub2(a0, a4, NEG1), d1 = sub2(a1, a5, NEG1);
            ull d2 = sub2(a2, a6, NEG1), d3 = sub2(a3, a7, NEG1);
            ull e  = add2(s0, s2), f  = add2(s1, s3);
            ull g  = sub2(s0, s2, NEG1), hh = sub2(s1, s3, NEG1);
            ull m  = mul2(sub2(d1, d3, NEG1), RSQ2);
            ull pp = mul2(add2(d1, d3), RSQ2);
            const int off = rb + 2*l;
            *reinterpret_cast<ull*>(&us[0*2048 + off]) = add2(e, f);                 // U0
            *reinterpret_cast<ull*>(&us[1*2048 + off]) = sub2(e, f, NEG1);           // U4
            *reinterpret_cast<ull*>(&us[2*2048 + off]) = add2(d0, m);                // U1R
            *reinterpret_cast<ull*>(&us[3*2048 + off]) = neg2(add2(d2, pp), NEG1);   // U1I
            *reinterpret_cast<ull*>(&us[4*2048 + off]) = g;                          // U2R
            *reinterpret_cast<ull*>(&us[5*2048 + off]) = neg2(hh, NEG1);             // U2I
            *reinterpret_cast<ull*>(&us[6*2048 + off]) = sub2(d0, m, NEG1);          // U3R
            *reinterpret_cast<ull*>(&us[7*2048 + off]) = sub2(d2, pp, NEG1);         // U3I
        }
    }
    __syncthreads();

    const int i0 = (t & 15) * 4;
    const int slot = t >> 4;
    const int cls = slot >> 1;                        // 0..7, warp-uniform
    const int ky_a = cls + 8*(slot & 1);
    const int ky_b = ky_a + 16;
    ull aR[2][2] = {{0,0},{0,0}}, aI[2][2] = {{0,0},{0,0}};
    int pa = 0, pb = 0;
    const float sc = 1.f/256.f;
    float iscl = sc;

    if (cls == 0 || cls == 4) {                       // real classes
        const float* Up = us + (cls == 0 ? 0 : 2048);
        for (int w0 = 0; w0 < 32; w0++) {
            ulonglong2 U = *reinterpret_cast<const ulonglong2*>(&Up[w0*64 + i0]);
            ulonglong2 ta = *reinterpret_cast<const ulonglong2*>(&twn[pa]);
            fma2(aR[0][0], ta.x, U.x); fma2(aR[0][1], ta.x, U.y);
            fma2(aI[0][0], ta.y, U.x); fma2(aI[0][1], ta.y, U.y);
            ulonglong2 tb = *reinterpret_cast<const ulonglong2*>(&twn[pb]);
            fma2(aR[1][0], tb.x, U.x); fma2(aR[1][1], tb.x, U.y);
            fma2(aI[1][0], tb.y, U.x); fma2(aI[1][1], tb.y, U.y);
            pa = (pa + ky_a) & 255; pb = (pb + ky_b) & 255;
        }
    } else if (cls < 4) {                             // complex classes 1,2,3
        const float* pRb = us + 2048 * (2*cls);
        const float* pIb = pRb + 2048;
        for (int w0 = 0; w0 < 32; w0++) {
            ulonglong2 UR = *reinterpret_cast<const ulonglong2*>(&pRb[w0*64 + i0]);
            ulonglong2 UI = *reinterpret_cast<const ulonglong2*>(&pIb[w0*64 + i0]);
            ulonglong2 tp4 = *reinterpret_cast<const ulonglong2*>(&twp[pa]);
            ulonglong2 tn4 = *reinterpret_cast<const ulonglong2*>(&twn[pa]);
            fma2(aR[0][0], tp4.x, UR.x); fma2(aR[0][0], tp4.y, UI.x);
            fma2(aR[0][1], tp4.x, UR.y); fma2(aR[0][1], tp4.y, UI.y);
            fma2(aI[0][0], tp4.x, UI.x); fma2(aI[0][0], tn4.y, UR.x);
            fma2(aI[0][1], tp4.x, UI.y); fma2(aI[0][1], tn4.y, UR.y);
            tp4 = *reinterpret_cast<const ulonglong2*>(&twp[pb]);
            tn4 = *reinterpret_cast<const ulonglong2*>(&twn[pb]);
            fma2(aR[1][0], tp4.x, UR.x); fma2(aR[1][0], tp4.y, UI.x);
            fma2(aR[1][1], tp4.x, UR.y); fma2(aR[1][1], tp4.y, UI.y);
            fma2(aI[1][0], tp4.x, UI.x); fma2(aI[1][0], tn4.y, UR.x);
            fma2(aI[1][1], tp4.x, UI.y); fma2(aI[1][1], tn4.y, UR.y);
            pa = (pa + ky_a) & 255; pb = (pb + ky_b) & 255;
        }
    } else {                                          // conj classes 5,6,7 -> planes 3,2,1
        const int cc = 8 - cls;
        const float* pRb = us + 2048 * (2*cc);
        const float* pIb = pRb + 2048;
        iscl = -sc;
        for (int w0 = 0; w0 < 32; w0++) {
            ulonglong2 UR = *reinterpret_cast<const ulonglong2*>(&pRb[w0*64 + i0]);
            ulonglong2 UI = *reinterpret_cast<const ulonglong2*>(&pIb[w0*64 + i0]);
            ulonglong2 tp4 = *reinterpret_cast<const ulonglong2*>(&twp[pa]);
            ulonglong2 tn4 = *reinterpret_cast<const ulonglong2*>(&twn[pa]);
            fma2(aR[0][0], tp4.x, UR.x); fma2(aR[0][0], tn4.y, UI.x);
            fma2(aR[0][1], tp4.x, UR.y); fma2(aR[0][1], tn4.y, UI.y);
            fma2(aI[0][0], tp4.x, UI.x); fma2(aI[0][0], tp4.y, UR.x);
            fma2(aI[0][1], tp4.x, UI.y); fma2(aI[0][1], tp4.y, UR.y);
            tp4 = *reinterpret_cast<const ulonglong2*>(&twp[pb]);
            tn4 = *reinterpret_cast<const ulonglong2*>(&twn[pb]);
            fma2(aR[1][0], tp4.x, UR.x); fma2(aR[1][0], tn4.y, UI.x);
            fma2(aR[1][1], tp4.x, UR.y); fma2(aR[1][1], tn4.y, UI.y);
            fma2(aI[1][0], tp4.x, UI.x); fma2(aI[1][0], tp4.y, UR.x);
            fma2(aI[1][1], tp4.x, UI.y); fma2(aI[1][1], tp4.y, UR.y);
            pa = (pa + ky_a) & 255; pb = (pb + ky_b) & 255;
        }
    }
#pragma unroll
    for (int j = 0; j < 2; j++) {
        const int ky = j ? ky_b : ky_a;
        size_t o = (size_t)((n*MD + ky)*RR + h)*IND + i0;
        float2 a0 = unpk(aR[j][0]), a1 = unpk(aR[j][1]);
        *reinterpret_cast<uint2*>(&g_XwRh[o]) =
            make_uint2(f22h(a0.x*sc, a0.y*sc), f22h(a1.x*sc, a1.y*sc));
        a0 = unpk(aI[j][0]); a1 = unpk(aI[j][1]);
        *reinterpret_cast<uint2*>(&g_XwIh[o]) =
            make_uint2(f22h(a0.x*iscl, a0.y*iscl), f22h(a1.x*iscl, a1.y*iscl));
    }
}

// ---------------- K2: forward h-DFT, radix-4, register-prefetch pipeline ----
__global__ __launch_bounds__(256, 3) void k2_fwd_h() {
    __shared__ __align__(16) float Vs[8*16*64];       // 8 planes x [16 h0][64 i] = 32KB
    __shared__ __align__(16) float4 twp[256], twn[256];
    const int t = threadIdx.x;
    INIT_TW(twp, twn, t)
    const int b = blockIdx.x, half = b & 1, ky = (b >> 1) & 31, n = b >> 6;
    const __half* baseR = g_XwRh + (size_t)(n*MD + ky)*RR*IND;
    const __half* baseI = g_XwIh + (size_t)(n*MD + ky)*RR*IND;
    const int i0 = (t & 15) * 4;
    const int g = t >> 4, c = g & 3, mseg = g >> 2;
    const int kxl0 = 8*mseg + c;                       // slots of class c
    const int kap0 = half ? (224 + kxl0) : kxl0;
    const int kap1 = kap0 + 4;
    const int h0ld = t >> 4, iq = (t & 15) * 4;        // loader role (1 per thread)
    const ull NEG1 = splat2(-1.f);
    ull aR[2][2] = {{0,0},{0,0}}, aI[2][2] = {{0,0},{0,0}};
    int p0 = 0, p1 = 0;

    uint2 R0u, R1u, R2u, R3u, I0u, I1u, I2u, I3u;
    {
        const __half* pR = baseR + h0ld*IND + iq;
        const __half* pI = baseI + h0ld*IND + iq;
        R0u = *reinterpret_cast<const uint2*>(pR);
        R1u = *reinterpret_cast<const uint2*>(pR + 64*IND);
        R2u = *reinterpret_cast<const uint2*>(pR + 128*IND);
        R3u = *reinterpret_cast<const uint2*>(pR + 192*IND);
        I0u = *reinterpret_cast<const uint2*>(pI);
        I1u = *reinterpret_cast<const uint2*>(pI + 64*IND);
        I2u = *reinterpret_cast<const uint2*>(pI + 128*IND);
        I3u = *reinterpret_cast<const uint2*>(pI + 192*IND);
    }

    for (int hc = 0; hc < 64; hc += 16) {
        __syncthreads();
        {   // convert + butterfly registers -> Vs
            ulonglong2 R0 = h4f(R0u), R1 = h4f(R1u), R2 = h4f(R2u), R3 = h4f(R3u);
            ulonglong2 I0 = h4f(I0u), I1 = h4f(I1u), I2 = h4f(I2u), I3 = h4f(I3u);
            ull sRx = add2(R0.x, R2.x), sRy = add2(R0.y, R2.y);
            ull dRx = sub2(R0.x, R2.x, NEG1), dRy = sub2(R0.y, R2.y, NEG1);
            ull uRx = add2(R1.x, R3.x), uRy = add2(R1.y, R3.y);
            ull eRx = sub2(R1.x, R3.x, NEG1), eRy = sub2(R1.y, R3.y, NEG1);
            ull sIx = add2(I0.x, I2.x), sIy = add2(I0.y, I2.y);
            ull dIx = sub2(I0.x, I2.x, NEG1), dIy = sub2(I0.y, I2.y, NEG1);
            ull uIx = add2(I1.x, I3.x), uIy = add2(I1.y, I3.y);
            ull eIx = sub2(I1.x, I3.x, NEG1), eIy = sub2(I1.y, I3.y, NEG1);
            const int rb = h0ld*64 + iq;
            ulonglong2* vp;
            vp = reinterpret_cast<ulonglong2*>(&Vs[0*1024 + rb]);
            *vp = make_ulonglong2(add2(sRx, uRx), add2(sRy, uRy));
            vp = reinterpret_cast<ulonglong2*>(&Vs[1*1024 + rb]);
            *vp = make_ulonglong2(add2(sIx, uIx), add2(sIy, uIy));
            vp = reinterpret_cast<ulonglong2*>(&Vs[2*1024 + rb]);
            *vp = make_ulonglong2(add2(dRx, eIx), add2(dRy, eIy));
            vp = reinterpret_cast<ulonglong2*>(&Vs[3*1024 + rb]);
            *vp = make_ulonglong2(sub2(dIx, eRx, NEG1), sub2(dIy, eRy, NEG1));
            vp = reinterpret_cast<ulonglong2*>(&Vs[4*1024 + rb]);
            *vp = make_ulonglong2(sub2(sRx, uRx, NEG1), sub2(sRy, uRy, NEG1));
            vp = reinterpret_cast<ulonglong2*>(&Vs[5*1024 + rb]);
            *vp = make_ulonglong2(sub2(sIx, uIx, NEG1), sub2(sIy, uIy, NEG1));
            vp = reinterpret_cast<ulonglong2*>(&Vs[6*1024 + rb]);
            *vp = make_ulonglong2(sub2(dRx, eIx, NEG1), sub2(dRy, eIy, NEG1));
            vp = reinterpret_cast<ulonglong2*>(&Vs[7*1024 + rb]);
            *vp = make_ulonglong2(add2(dIx, eRx), add2(dIy, eRy));
        }
        __syncthreads();
        if (hc < 48) {
            const __half* pR = baseR + (hc + 16 + h0ld)*IND + iq;
            const __half* pI = baseI + (hc + 16 + h0ld)*IND + iq;
            R0u = *reinterpret_cast<const uint2*>(pR);
            R1u = *reinterpret_cast<const uint2*>(pR + 64*IND);
            R2u = *reinterpret_cast<const uint2*>(pR + 128*IND);
            R3u = *reinterpret_cast<const uint2*>(pR + 192*IND);
            I0u = *reinterpret_cast<const uint2*>(pI);
            I1u = *reinterpret_cast<const uint2*>(pI + 64*IND);
            I2u = *reinterpret_cast<const uint2*>(pI + 128*IND);
            I3u = *reinterpret_cast<const uint2*>(pI + 192*IND);
        }
        const float* VRb = &Vs[(c*2 + 0)*1024];
        const float* VIb = &Vs[(c*2 + 1)*1024];
        for (int h0l = 0; h0l < 16; h0l++) {
            ulonglong2 VR = *reinterpret_cast<const ulonglong2*>(&VRb[h0l*64 + i0]);
            ulonglong2 VI = *reinterpret_cast<const ulonglong2*>(&VIb[h0l*64 + i0]);
            ulonglong2 tp4 = *reinterpret_cast<const ulonglong2*>(&twp[p0]);
            ulonglong2 tn4 = *reinterpret_cast<const ulonglong2*>(&twn[p0]);
            fma2(aR[0][0], tp4.x, VR.x); fma2(aR[0][0], tp4.y, VI.x);
            fma2(aR[0][1], tp4.x, VR.y); fma2(aR[0][1], tp4.y, VI.y);
            fma2(aI[0][0], tp4.x, VI.x); fma2(aI[0][0], tn4.y, VR.x);
            fma2(aI[0][1], tp4.x, VI.y); fma2(aI[0][1], tn4.y, VR.y);
            p0 = (p0 + kap0) & 255;
            tp4 = *reinterpret_cast<const ulonglong2*>(&twp[p1]);
            tn4 = *reinterpret_cast<const ulonglong2*>(&twn[p1]);
            fma2(aR[1][0], tp4.x, VR.x); fma2(aR[1][0], tp4.y, VI.x);
            fma2(aR[1][1], tp4.x, VR.y); fma2(aR[1][1], tp4.y, VI.y);
            fma2(aI[1][0], tp4.x, VI.x); fma2(aI[1][0], tn4.y, VR.x);
            fma2(aI[1][1], tp4.x, VI.y); fma2(aI[1][1], tn4.y, VR.y);
            p1 = (p1 + kap1) & 255;
        }
    }
#pragma unroll
    for (int j = 0; j < 2; j++) {
        int kxs = half*32 + kxl0 + 4*j;
        size_t o = (size_t)((ky*KXN + kxs)*NB + n)*IND + i0;
        float2 a0 = unpk(aR[j][0]), a1 = unpk(aR[j][1]);
        *reinterpret_cast<uint2*>(&g_XmRh[o]) =
            make_uint2(f22h(a0.x, a0.y), f22h(a1.x, a1.y));
        a0 = unpk(aI[j][0]); a1 = unpk(aI[j][1]);
        *reinterpret_cast<uint2*>(&g_XmIh[o]) =
            make_uint2(f22h(a0.x, a0.y), f22h(a1.x, a1.y));
    }
}

// ---------------- K3: per-mode complex channel mix (8x64x64) ----------------
__global__ __launch_bounds__(256) void k3_mix(const float* __restrict__ w0,
                                              const float* __restrict__ w1) {
    __shared__ float Xs2[NB*IND*2];                   // interleaved (R,I)
    const int t = threadIdx.x, b = blockIdx.x;
    const int kx = b >> 5, ky = b & 31;
    size_t xb = (size_t)(ky*KXN + kx)*NB*IND;
    {   // fp16 -> interleaved fp32 smem (each thread: 2 idx)
        __half2 hR = *reinterpret_cast<const __half2*>(g_XmRh + xb + 2*t);
        __half2 hI = *reinterpret_cast<const __half2*>(g_XmIh + xb + 2*t);
        float2 fR = __half22float2(hR), fI = __half22float2(hI);
        Xs2[4*t]     = fR.x; Xs2[4*t + 1] = fI.x;
        Xs2[4*t + 2] = fR.y; Xs2[4*t + 3] = fI.y;
    }
    __syncthreads();
    const float4* wp4 = reinterpret_cast<const float4*>(
        (kx < MD) ? (w0 + (size_t)(kx*MD + ky)*IND*OUTD*2)
                  : (w1 + (size_t)((kx - MD)*MD + ky)*IND*OUTD*2));
    const int o2 = t & 31, n = t >> 5;                // o0 = 2*o2, one n per thread
    float r0 = 0.f, i0 = 0.f, r1 = 0.f, i1 = 0.f;
#pragma unroll 8
    for (int i = 0; i < IND; i++) {
        float4 w = wp4[i*32 + o2];                    // (wR0,wI0,wR1,wI1)
        float2 xv = *reinterpret_cast<const float2*>(&Xs2[(n*IND + i)*2]);
        r0 = fmaf(xv.x, w.x, fmaf(-xv.y, w.y, r0));
        i0 = fmaf(xv.x, w.y, fmaf( xv.y, w.x, i0));
        r1 = fmaf(xv.x, w.z, fmaf(-xv.y, w.w, r1));
        i1 = fmaf(xv.x, w.w, fmaf( xv.y, w.z, i1));
    }
    size_t gg = (size_t)((n*MD + ky)*KXN + kx)*OUTD + 2*o2;
    *reinterpret_cast<unsigned*>(&g_OmRh[gg]) = f22h(r0, r1);
    *reinterpret_cast<unsigned*>(&g_OmIh[gg]) = f22h(i0, i1);
}

// ---------------- K4: inverse h-DFT, radix-4 on output ----------------------
#define K4STEP(CR, CI) { \
    ulonglong2 R0 = *reinterpret_cast<const ulonglong2*>(&sR[kxo]); \
    ulonglong2 R1 = *reinterpret_cast<const ulonglong2*>(&sR[kxo + 4]); \
    ulonglong2 I0 = *reinterpret_cast<const ulonglong2*>(&sI[kxo]); \
    ulonglong2 I1 = *reinterpret_cast<const ulonglong2*>(&sI[kxo + 4]); \
    ulonglong2 tp4 = *reinterpret_cast<const ulonglong2*>(&twp[p]); \
    ulonglong2 tn4 = *reinterpret_cast<const ulonglong2*>(&twn[p]); \
    fma2(CR[0], tn4.x, R0.x); fma2(CR[0], tn4.y, I0.x); \
    fma2(CR[1], tn4.x, R0.y); fma2(CR[1], tn4.y, I0.y); \
    fma2(CR[2], tn4.x, R1.x); fma2(CR[2], tn4.y, I1.x); \
    fma2(CR[3], tn4.x, R1.y); fma2(CR[3], tn4.y, I1.y); \
    fma2(CI[0], tp4.x, I0.x); fma2(CI[0], tp4.y, R0.x); \
    fma2(CI[1], tp4.x, I0.y); fma2(CI[1], tp4.y, R0.y); \
    fma2(CI[2], tp4.x, I1.x); fma2(CI[2], tp4.y, R1.x); \
    fma2(CI[3], tp4.x, I1.y); fma2(CI[3], tp4.y, R1.y); \
    p = (p + h0) & 255; kxo += OUTD; }

__global__ __launch_bounds__(256) void k4_inv_h() {
    __shared__ __align__(16) float sR[KXN*OUTD], sI[KXN*OUTD];
    __shared__ __align__(16) float4 twp[256], twn[256];
    const int t = threadIdx.x;
    INIT_TW(twp, twn, t)
    const int b = blockIdx.x, grp = b & 1, ky = (b >> 1) & 31, n = b >> 6;
    {   // fp16 Om tile -> fp32 smem, conflict-free: 4 halves/thread/iter
        const uint2* pR = reinterpret_cast<const uint2*>(g_OmRh + (size_t)(n*MD + ky)*KXN*OUTD);
        const uint2* pI = reinterpret_cast<const uint2*>(g_OmIh + (size_t)(n*MD + ky)*KXN*OUTD);
#pragma unroll
        for (int it = 0; it < 4; it++) {
            int j = t + 256*it;
            *reinterpret_cast<ulonglong2*>(&sR[j*4]) = h4f(pR[j]);
            *reinterpret_cast<ulonglong2*>(&sI[j*4]) = h4f(pI[j]);
        }
    }
    __syncthreads();
    const int o0 = (t & 7) * 8, h0 = grp*32 + (t >> 3);
    ull C0R[4], C0I[4], C1R[4], C1I[4], C2R[4], C2I[4], C3R[4], C3I[4];
#pragma unroll
    for (int j = 0; j < 4; j++) {
        C0R[j]=C0I[j]=C1R[j]=C1I[j]=0ull;
        C2R[j]=C2I[j]=C3R[j]=C3I[j]=0ull;
    }
#pragma unroll 1
    for (int kh = 0; kh < 2; kh++) {
        int p = kh ? ((224*h0) & 255) : 0;
        int kxo = (kh*32)*OUTD + o0;
#pragma unroll
        for (int kk = 0; kk < 32; kk += 4) {
            K4STEP(C0R, C0I)
            K4STEP(C1R, C1I)
            K4STEP(C2R, C2I)
            K4STEP(C3R, C3I)
        }
    }
    const ull NEG1 = splat2(-1.f);
    const ull FAC2 = splat2((ky == 0 ? 1.f : 2.f) * (1.f/256.f));
    const size_t obase = (size_t)((n*RR + h0)*MD + ky)*OUTD + o0;
#pragma unroll
    for (int j = 0; j < 4; j++) {
        ull ER = add2(C0R[j], C2R[j]), EI = add2(C0I[j], C2I[j]);
        ull FR = sub2(C0R[j], C2R[j], NEG1), FI = sub2(C0I[j], C2I[j], NEG1);
        ull GR = add2(C1R[j], C3R[j]), GI = add2(C1I[j], C3I[j]);
        ull HR = sub2(C1R[j], C3R[j], NEG1), HI = sub2(C1I[j], C3I[j], NEG1);
        ull YR[4] = { add2(ER, GR), sub2(FR, HI, NEG1), sub2(ER, GR, NEG1), add2(FR, HI) };
        ull YI[4] = { add2(EI, GI), add2(FI, HR), sub2(EI, GI, NEG1), sub2(FI, HR, NEG1) };
#pragma unroll
        for (int q = 0; q < 4; q++) {
            size_t o = obase + (size_t)(64*q)*MD*OUTD + 2*j;
            float2 vr = unpk(mul2(YR[q], FAC2));
            float2 vi = unpk(mul2(YI[q], FAC2));
            *reinterpret_cast<unsigned*>(&g_Y1Rh[o]) = f22h(vr.x, vr.y);
            *reinterpret_cast<unsigned*>(&g_Y1Ih[o]) = f22h(vi.x, vi.y);
        }
    }
}

// ---------------- K5: radix-4 inverse w synthesis + residual + SiLU ---------
#define XPAD 68
__global__ __launch_bounds__(256) void k5_inv_w(const float* __restrict__ x,
                                                const float* __restrict__ res_w,
                                                const float* __restrict__ res_b,
                                                float* __restrict__ out) {
    extern __shared__ __align__(16) float xs[];       // [256][XPAD]
    __shared__ __align__(16) float YsR[MD*OUTD], YsI[MD*OUTD];
    __shared__ __align__(16) float rws[IND*OUTD];
    __shared__ __align__(16) float4 twp[256], twn[256];
    __shared__ __align__(16) float rbs[64];
    const int t = threadIdx.x, b = blockIdx.x, n = b >> 8, h = b & 255;
    INIT_TW(twp, twn, t)
    const float4* xp = reinterpret_cast<const float4*>(x + (size_t)(n*RR + h)*RR*IND);
#pragma unroll
    for (int it = 0; it < 16; it++) {
        int j = t + 256*it;
        float4 v = __ldcs(xp + j);
        int w = j >> 4, c = j & 15;
        *reinterpret_cast<float4*>(&xs[w*XPAD + c*4]) = v;
    }
    {   // Y1 fp16 -> fp32 smem, conflict-free: 4 halves/thread/iter
        const uint2* yRu = reinterpret_cast<const uint2*>(g_Y1Rh + (size_t)(n*RR + h)*MD*OUTD);
        const uint2* yIu = reinterpret_cast<const uint2*>(g_Y1Ih + (size_t)(n*RR + h)*MD*OUTD);
#pragma unroll
        for (int it = 0; it < 2; it++) {
            int j = t + 256*it;
            *reinterpret_cast<ulonglong2*>(&YsR[j*4]) = h4f(yRu[j]);
            *reinterpret_cast<ulonglong2*>(&YsI[j*4]) = h4f(yIu[j]);
        }
    }
#pragma unroll
    for (int it = 0; it < 4; it++)
        reinterpret_cast<float4*>(rws)[t + 256*it] =
            reinterpret_cast<const float4*>(res_w)[t + 256*it];
    if (t < 64) rbs[t] = res_b[t];
    __syncthreads();

    const int og = t & 7, o0 = og*8, pr = t >> 3;     // w0a = pr, w0b = pr + 32
    const ull NEG1 = splat2(-1.f);
    ull C0R[2][4], C2R[2][4], C1R[2][4], C1I[2][4], C3R[2][4], C3I[2][4];
#pragma unroll
    for (int s = 0; s < 2; s++)
#pragma unroll
        for (int j = 0; j < 4; j++) {
            C0R[s][j]=C2R[s][j]=C1R[s][j]=C1I[s][j]=C3R[s][j]=C3I[s][j]=0ull;
        }
    int pa = 0, pb = 0;
    const int stpa = pr, stpb = pr + 32;
#pragma unroll
    for (int kb = 0; kb < 8; kb++) {
        // c = 0
        {
            const int ky = 4*kb;
            ulonglong2 yr0 = *reinterpret_cast<const ulonglong2*>(&YsR[ky*OUTD + o0]);
            ulonglong2 yr1 = *reinterpret_cast<const ulonglong2*>(&YsR[ky*OUTD + o0 + 4]);
            ulonglong2 yi0 = *reinterpret_cast<const ulonglong2*>(&YsI[ky*OUTD + o0]);
            ulonglong2 yi1 = *reinterpret_cast<const ulonglong2*>(&YsI[ky*OUTD + o0 + 4]);
            ulonglong2 tn4 = *reinterpret_cast<const ulonglong2*>(&twn[pa]);
            fma2(C0R[0][0], tn4.x, yr0.x); fma2(C0R[0][0], tn4.y, yi0.x);
            fma2(C0R[0][1], tn4.x, yr0.y); fma2(C0R[0][1], tn4.y, yi0.y);
            fma2(C0R[0][2], tn4.x, yr1.x); fma2(C0R[0][2], tn4.y, yi1.x);
            fma2(C0R[0][3], tn4.x, yr1.y); fma2(C0R[0][3], tn4.y, yi1.y);
            tn4 = *reinterpret_cast<const ulonglong2*>(&twn[pb]);
            fma2(C0R[1][0], tn4.x, yr0.x); fma2(C0R[1][0], tn4.y, yi0.x);
            fma2(C0R[1][1], tn4.x, yr0.y); fma2(C0R[1][1], tn4.y, yi0.y);
            fma2(C0R[1][2], tn4.x, yr1.x); fma2(C0R[1][2], tn4.y, yi1.x);
            fma2(C0R[1][3], tn4.x, yr1.y); fma2(C0R[1][3], tn4.y, yi1.y);
            pa = (pa + stpa) & 255; pb = (pb + stpb) & 255;
        }
        // c = 1
        {
            const int ky = 4*kb + 1;
            ulonglong2 yr0 = *reinterpret_cast<const ulonglong2*>(&YsR[ky*OUTD + o0]);
            ulonglong2 yr1 = *reinterpret_cast<const ulonglong2*>(&YsR[ky*OUTD + o0 + 4]);
            ulonglong2 yi0 = *reinterpret_cast<const ulonglong2*>(&YsI[ky*OUTD + o0]);
            ulonglong2 yi1 = *reinterpret_cast<const ulonglong2*>(&YsI[ky*OUTD + o0 + 4]);
            ulonglong2 tn4 = *reinterpret_cast<const ulonglong2*>(&twn[pa]);
            ulonglong2 tp4 = *reinterpret_cast<const ulonglong2*>(&twp[pa]);
            fma2(C1R[0][0], tn4.x, yr0.x); fma2(C1R[0][0], tn4.y, yi0.x);
            fma2(C1R[0][1], tn4.x, yr0.y); fma2(C1R[0][1], tn4.y, yi0.y);
            fma2(C1R[0][2], tn4.x, yr1.x); fma2(C1R[0][2], tn4.y, yi1.x);
            fma2(C1R[0][3], tn4.x, yr1.y); fma2(C1R[0][3], tn4.y, yi1.y);
            fma2(C1I[0][0], tp4.x, yi0.x); fma2(C1I[0][0], tp4.y, yr0.x);
            fma2(C1I[0][1], tp4.x, yi0.y); fma2(C1I[0][1], tp4.y, yr0.y);
            fma2(C1I[0][2], tp4.x, yi1.x); fma2(C1I[0][2], tp4.y, yr1.x);
            fma2(C1I[0][3], tp4.x, yi1.y); fma2(C1I[0][3], tp4.y, yr1.y);
            tn4 = *reinterpret_cast<const ulonglong2*>(&twn[pb]);
            tp4 = *reinterpret_cast<const ulonglong2*>(&twp[pb]);
            fma2(C1R[1][0], tn4.x, yr0.x); fma2(C1R[1][0], tn4.y, yi0.x);
            fma2(C1R[1][1], tn4.x, yr0.y); fma2(C1R[1][1], tn4.y, yi0.y);
            fma2(C1R[1][2], tn4.x, yr1.x); fma2(C1R[1][2], tn4.y, yi1.x);
            fma2(C1R[1][3], tn4.x, yr1.y); fma2(C1R[1][3], tn4.y, yi1.y);
            fma2(C1I[1][0], tp4.x, yi0.x); fma2(C1I[1][0], tp4.y, yr0.x);
            fma2(C1I[1][1], tp4.x, yi0.y); fma2(C1I[1][1], tp4.y, yr0.y);
            fma2(C1I[1][2], tp4.x, yi1.x); fma2(C1I[1][2], tp4.y, yr1.x);
            fma2(C1I[1][3], tp4.x, yi1.y); fma2(C1I[1][3], tp4.y, yr1.y);
            pa = (pa + stpa) & 255; pb = (pb + stpb) & 255;
        }
        // c = 2
        {
            const int ky = 4*kb + 2;
            ulonglong2 yr0 = *reinterpret_cast<const ulonglong2*>(&YsR[ky*OUTD + o0]);
            ulonglong2 yr1 = *reinterpret_cast<const ulonglong2*>(&YsR[ky*OUTD + o0 + 4]);
            ulonglong2 yi0 = *reinterpret_cast<const ulonglong2*>(&YsI[ky*OUTD + o0]);
            ulonglong2 yi1 = *reinterpret_cast<const ulonglong2*>(&YsI[ky*OUTD + o0 + 4]);
            ulonglong2 tn4 = *reinterpret_cast<const ulonglong2*>(&twn[pa]);
            fma2(C2R[0][0], tn4.x, yr0.x); fma2(C2R[0][0], tn4.y, yi0.x);
            fma2(C2R[0][1], tn4.x, yr0.y); fma2(C2R[0][1], tn4.y, yi0.y);
            fma2(C2R[0][2], tn4.x, yr1.x); fma2(C2R[0][2], tn4.y, yi1.x);
            fma2(C2R[0][3], tn4.x, yr1.y); fma2(C2R[0][3], tn4.y, yi1.y);
            tn4 = *reinterpret_cast<const ulonglong2*>(&twn[pb]);
            fma2(C2R[1][0], tn4.x, yr0.x); fma2(C2R[1][0], tn4.y, yi0.x);
            fma2(C2R[1][1], tn4.x, yr0.y); fma2(C2R[1][1], tn4.y, yi0.y);
            fma2(C2R[1][2], tn4.x, yr1.x); fma2(C2R[1][2], tn4.y, yi1.x);
            fma2(C2R[1][3], tn4.x, yr1.y); fma2(C2R[1][3], tn4.y, yi1.y);
            pa = (pa + stpa) & 255; pb = (pb + stpb) & 255;
        }
        // c = 3
        {
            const int ky = 4*kb + 3;
            ulonglong2 yr0 = *reinterpret_cast<const ulonglong2*>(&YsR[ky*OUTD + o0]);
            ulonglong2 yr1 = *reinterpret_cast<const ulonglong2*>(&YsR[ky*OUTD + o0 + 4]);
            ulonglong2 yi0 = *reinterpret_cast<const ulonglong2*>(&YsI[ky*OUTD + o0]);
            ulonglong2 yi1 = *reinterpret_cast<const ulonglong2*>(&YsI[ky*OUTD + o0 + 4]);
            ulonglong2 tn4 = *reinterpret_cast<const ulonglong2*>(&twn[pa]);
            ulonglong2 tp4 = *reinterpret_cast<const ulonglong2*>(&twp[pa]);
            fma2(C3R[0][0], tn4.x, yr0.x); fma2(C3R[0][0], tn4.y, yi0.x);
            fma2(C3R[0][1], tn4.x, yr0.y); fma2(C3R[0][1], tn4.y, yi0.y);
            fma2(C3R[0][2], tn4.x, yr1.x); fma2(C3R[0][2], tn4.y, yi1.x);
            fma2(C3R[0][3], tn4.x, yr1.y); fma2(C3R[0][3], tn4.y, yi1.y);
            fma2(C3I[0][0], tp4.x, yi0.x); fma2(C3I[0][0], tp4.y, yr0.x);
            fma2(C3I[0][1], tp4.x, yi0.y); fma2(C3I[0][1], tp4.y, yr0.y);
            fma2(C3I[0][2], tp4.x, yi1.x); fma2(C3I[0][2], tp4.y, yr1.x);
            fma2(C3I[0][3], tp4.x, yi1.y); fma2(C3I[0][3], tp4.y, yr1.y);
            tn4 = *reinterpret_cast<const ulonglong2*>(&twn[pb]);
            tp4 = *reinterpret_cast<const ulonglong2*>(&twp[pb]);
            fma2(C3R[1][0], tn4.x, yr0.x); fma2(C3R[1][0], tn4.y, yi0.x);
            fma2(C3R[1][1], tn4.x, yr0.y); fma2(C3R[1][1], tn4.y, yi0.y);
            fma2(C3R[1][2], tn4.x, yr1.x); fma2(C3R[1][2], tn4.y, yi1.x);
            fma2(C3R[1][3], tn4.x, yr1.y); fma2(C3R[1][3], tn4.y, yi1.y);
            fma2(C3I[1][0], tp4.x, yi0.x); fma2(C3I[1][0], tp4.y, yr0.x);
            fma2(C3I[1][1], tp4.x, yi0.y); fma2(C3I[1][1], tp4.y, yr0.y);
            fma2(C3I[1][2], tp4.x, yi1.x); fma2(C3I[1][2], tp4.y, yr1.x);
            fma2(C3I[1][3], tp4.x, yi1.y); fma2(C3I[1][3], tp4.y, yr1.y);
            pa = (pa + stpa) & 255; pb = (pb + stpb) & 255;
        }
    }
    // ---- combine classes into 4 output rows + bias, both w0 ----
    ull ys[2][4][4];
    {
        ulonglong2 b01 = *reinterpret_cast<const ulonglong2*>(&rbs[o0]);
        ulonglong2 b23 = *reinterpret_cast<const ulonglong2*>(&rbs[o0 + 4]);
        ull bias[4] = {b01.x, b01.y, b23.x, b23.y};
#pragma unroll
        for (int s = 0; s < 2; s++)
#pragma unroll
            for (int j = 0; j < 4; j++) {
                ull e  = add2(C0R[s][j], C2R[s][j]);
                ull f  = sub2(C0R[s][j], C2R[s][j], NEG1);
                ull g  = add2(C1R[s][j], C3R[s][j]);
                ull hh = sub2(C3I[s][j], C1I[s][j], NEG1);
                ys[s][0][j] = add2(add2(e, g),  bias[j]);
                ys[s][2][j] = add2(sub2(e, g,  NEG1), bias[j]);
                ys[s][1][j] = add2(add2(f, hh), bias[j]);
                ys[s][3][j] = add2(sub2(f, hh, NEG1), bias[j]);
            }
    }
    // ---- residual GEMM into ys (2 i per step, vector x loads) ----
    for (int i = 0; i < IND; i += 2) {
        ulonglong2 rA01 = *reinterpret_cast<const ulonglong2*>(&rws[i*OUTD + o0]);
        ulonglong2 rA23 = *reinterpret_cast<const ulonglong2*>(&rws[i*OUTD + o0 + 4]);
        ulonglong2 rB01 = *reinterpret_cast<const ulonglong2*>(&rws[(i+1)*OUTD + o0]);
        ulonglong2 rB23 = *reinterpret_cast<const ulonglong2*>(&rws[(i+1)*OUTD + o0 + 4]);
#pragma unroll
        for (int s = 0; s < 2; s++) {
            const int wbase = pr + 32*s;
#pragma unroll
            for (int q = 0; q < 4; q++) {
                float2 xv = *reinterpret_cast<const float2*>(&xs[(wbase + 64*q)*XPAD + i]);
                ull sxA = splat2(xv.x), sxB = splat2(xv.y);
                fma2(ys[s][q][0], sxA, rA01.x); fma2(ys[s][q][1], sxA, rA01.y);
                fma2(ys[s][q][2], sxA, rA23.x); fma2(ys[s][q][3], sxA, rA23.y);
                fma2(ys[s][q][0], sxB, rB01.x); fma2(ys[s][q][1], sxB, rB01.y);
                fma2(ys[s][q][2], sxB, rB23.x); fma2(ys[s][q][3], sxB, rB23.y);
            }
        }
    }
    // ---- SiLU + streaming store ----
#pragma unroll
    for (int s = 0; s < 2; s++) {
        const int wbase = pr + 32*s;
#pragma unroll
        for (int q = 0; q < 4; q++) {
            float4 v4[2];
#pragma unroll
            for (int c = 0; c < 4; c++) {
                float2 v = unpk(ys[s][q][c]);
                v.x = v.x / (1.f + __expf(-v.x));
                v.y = v.y / (1.f + __expf(-v.y));
                reinterpret_cast<float2*>(v4)[c] = v;
            }
            size_t o = (size_t)((n*RR + h)*RR + (wbase + 64*q))*OUTD + o0;
            __stcs(reinterpret_cast<float4*>(&out[o]),     v4[0]);
            __stcs(reinterpret_cast<float4*>(&out[o + 4]), v4[1]);
        }
    }
}

// ---------------- launch ----------------------------------------------------
extern "C" void kernel_launch(void* const* d_in, const int* in_sizes, int n_in,
                              void* d_out, int out_size) {
    const float* x   = (const float*)d_in[0];
    const float* w0  = (const float*)d_in[1];
    const float* w1  = (const float*)d_in[2];
    const float* rsw = (const float*)d_in[3];
    const float* rsb = (const float*)d_in[4];
    float* out = (float*)d_out;

    cudaFuncSetAttribute(k1_fwd_w, cudaFuncAttributeMaxDynamicSharedMemorySize, 65536);
    cudaFuncSetAttribute(k5_inv_w, cudaFuncAttributeMaxDynamicSharedMemorySize, RR*XPAD*4);

    k1_fwd_w<<<NB*RR, 256, 65536>>>(x);
    k2_fwd_h<<<NB*MD*2, 256>>>();
    k3_mix<<<KXN*MD, 256>>>(w0, w1);
    k4_inv_h<<<NB*MD*2, 256>>>();
    k5_inv_w<<<NB*RR, 256, RR*XPAD*4>>>(x, rsw, rsb, out);
}